// round 6
// baseline (speedup 1.0000x reference)
#include <cuda_runtime.h>
#include <cuda_bf16.h>
#include <math.h>
#include <stdint.h>

#define BB 32
#define NN 520
#define DEPOTN 20
#define CUSTN 500
#define EE 128
#define HH 8
#define DKK 16
#define FFHH 512
#define NLL 6
#define MM 520
#define LL 40
#define NP 524
#define KRT 288

typedef __nv_bfloat16 bf16;
typedef unsigned long long ull;

// ---------------- fp32 scratch ----------------
__device__ __align__(16) float g_x   [BB*NN*EE];
__device__ __align__(16) float g_qkv [BB*NN*384];
__device__ __align__(16) float g_y   [BB*NN*EE];
__device__ __align__(16) float g_x1  [BB*NN*EE];
__device__ __align__(16) float g_part[BB*8*EE*2];
__device__ __align__(16) float g_stats[BB*EE*2];
__device__ __align__(16) float g_kvd [BB*NN*256];
__device__ __align__(16) float g_encmean[BB*EE];
__device__ __align__(16) float g_qloc [BB*MM*EE];
__device__ __align__(16) float g_qrout[BB*MM*EE];
__device__ __align__(16) float g_fq   [BB*MM*EE];
__device__ __align__(16) float g_flag [BB*MM];
__device__ __align__(16) float g_sn   [BB*MM*NN];

// ---------------- bf16 hi/lo scratch ----------------
__device__ __align__(16) bf16 g_xh[BB*NN*EE],      g_xl[BB*NN*EE];
__device__ __align__(16) bf16 g_x1h[BB*NN*EE],     g_x1l[BB*NN*EE];
__device__ __align__(16) bf16 g_mhh[BB*NN*EE],     g_mhl[BB*NN*EE];
__device__ __align__(16) bf16 g_ffhh[BB*NN*FFHH],  g_ffhl[BB*NN*FFHH];
__device__ __align__(16) bf16 g_attnh[BB*MM*EE],   g_attnl[BB*MM*EE];
__device__ __align__(16) bf16 g_scoreh[BB*MM*EE],  g_scorel[BB*MM*EE];
__device__ __align__(16) bf16 g_catlh[BB*MM*256],  g_catll[BB*MM*256];
__device__ __align__(16) bf16 g_catrh[BB*MM*KRT],  g_catrl[BB*MM*KRT];
__device__ __align__(16) bf16 g_wqkvh[NLL*384*EE], g_wqkvl[NLL*384*EE];
__device__ __align__(16) bf16 g_wch[NLL*EE*EE],    g_wcl[NLL*EE*EE];
__device__ __align__(16) bf16 g_f1h[NLL*FFHH*EE],  g_f1l[NLL*FFHH*EE];
__device__ __align__(16) bf16 g_f2h[NLL*EE*FFHH],  g_f2l[NLL*EE*FFHH];
__device__ __align__(16) bf16 g_wkvh[256*EE],      g_wkvl[256*EE];
__device__ __align__(16) bf16 g_wqlh[EE*256],      g_wqll[EE*256];
__device__ __align__(16) bf16 g_wpah[EE*KRT],      g_wpal[EE*KRT];
__device__ __align__(16) bf16 g_wdch[EE*EE],       g_wdcl[EE*EE];

__device__ __forceinline__ void split1(float x, bf16* h, bf16* l)
{
    bf16 hv = __float2bfloat16(x);
    *h = hv;
    *l = __float2bfloat16(x - __bfloat162float(hv));
}

// ---------------- f32x2 packed helpers ----------------
__device__ __forceinline__ ull pk2(float x, float y)
{ ull r; asm("mov.b64 %0,{%1,%2};" : "=l"(r) : "f"(x), "f"(y)); return r; }
__device__ __forceinline__ ull pkdup(float x) { return pk2(x, x); }
__device__ __forceinline__ float2 upk(ull v)
{ float2 f; asm("mov.b64 {%0,%1},%2;" : "=f"(f.x), "=f"(f.y) : "l"(v)); return f; }
#define FMA2(a,x,y) asm("fma.rn.f32x2 %0,%1,%2,%0;" : "+l"(a) : "l"(x), "l"(y))
#define MUL2(a,x)   asm("mul.rn.f32x2 %0,%0,%1;"    : "+l"(a) : "l"(x))
#define ADD2(a,x)   asm("add.rn.f32x2 %0,%0,%1;"    : "+l"(a) : "l"(x))

// ---------------- generic fp32 -> hi/lo ----------------
__global__ void cvt_split(const float* __restrict__ s, bf16* __restrict__ h,
                          bf16* __restrict__ l, int n)
{
    int i = blockIdx.x * blockDim.x + threadIdx.x;
    if (i < n) split1(s[i], h + i, l + i);
}

// ---------------- embedding ----------------
__global__ void embed_kernel(const float* __restrict__ dep, const float* __restrict__ cus,
                             const float* __restrict__ Wd, const float* __restrict__ bd,
                             const float* __restrict__ Wc, const float* __restrict__ bc)
{
    int idx = blockIdx.x * blockDim.x + threadIdx.x;
    if (idx >= BB*NN*EE) return;
    int e = idx % EE;
    int n = (idx / EE) % NN;
    int b = idx / (EE*NN);
    float acc;
    if (n < DEPOTN) {
        const float* f = dep + ((long)b*DEPOTN + n) * 4;
        acc = bd[e];
        #pragma unroll
        for (int j = 0; j < 4; j++) acc += f[j] * Wd[e*4 + j];
    } else {
        const float* f = cus + ((long)b*CUSTN + (n - DEPOTN)) * 3;
        acc = bc[e];
        #pragma unroll
        for (int j = 0; j < 3; j++) acc += f[j] * Wc[e*3 + j];
    }
    g_x[idx] = acc;
    split1(acc, g_xh + idx, g_xl + idx);
}

// ---------------- weight packing ----------------
__global__ void pack_w(const float* __restrict__ Wq, const float* __restrict__ Wk,
                       const float* __restrict__ Wv, const float* __restrict__ dWk,
                       const float* __restrict__ dWv)
{
    int idx = blockIdx.x * blockDim.x + threadIdx.x;
    const int tot1 = NLL*384*EE;
    if (idx < tot1) {
        int col = idx % EE;
        int row = (idx / EE) % 384;
        int l   = idx / (EE*384);
        float v;
        if (row < 128)      v = Wq[((long)l*EE + row)*EE + col];
        else if (row < 256) v = Wk[((long)l*EE + row-128)*EE + col];
        else                v = Wv[((long)l*EE + row-256)*EE + col];
        split1(v, g_wqkvh + idx, g_wqkvl + idx);
    } else {
        int j = idx - tot1;
        if (j < 256*EE) {
            int col = j % EE;
            int row = j / EE;
            float v = (row < 128) ? dWk[row*EE + col] : dWv[(row-128)*EE + col];
            split1(v, g_wkvh + j, g_wkvl + j);
        }
    }
}

__global__ void padw_kernel(const float* __restrict__ Wr)
{
    int idx = blockIdx.x * blockDim.x + threadIdx.x;
    if (idx >= EE*KRT) return;
    int rr = idx / KRT, cc = idx % KRT;
    float v = (cc < 257) ? Wr[rr*257 + cc] : 0.f;
    split1(v, g_wpah + idx, g_wpal + idx);
}

// ---------------- TC GEMM v2 (unchanged from R5) ----------------
#define SP 40
#define MAT 10240
#define STAGE 40960

#define LDM4(r0,r1,r2,r3,addr) \
    asm volatile("ldmatrix.sync.aligned.m8n8.x4.shared.b16 {%0,%1,%2,%3},[%4];" \
                 : "=r"(r0),"=r"(r1),"=r"(r2),"=r"(r3) : "r"(addr))
#define LDM2(r0,r1,addr) \
    asm volatile("ldmatrix.sync.aligned.m8n8.x2.shared.b16 {%0,%1},[%2];" \
                 : "=r"(r0),"=r"(r1) : "r"(addr))
#define MMA16816(c,a,b) \
    asm volatile("mma.sync.aligned.m16n8k16.row.col.f32.bf16.bf16.f32 " \
                 "{%0,%1,%2,%3},{%4,%5,%6,%7},{%8,%9},{%0,%1,%2,%3};" \
                 : "+f"((c)[0]),"+f"((c)[1]),"+f"((c)[2]),"+f"((c)[3]) \
                 : "r"((a)[0]),"r"((a)[1]),"r"((a)[2]),"r"((a)[3]), "r"((b)[0]),"r"((b)[1]))

__global__ __launch_bounds__(256, 2)
void gemm_tc2(const bf16* __restrict__ Ahi, const bf16* __restrict__ Alo,
              const bf16* __restrict__ Bhi, const bf16* __restrict__ Blo,
              const float* __restrict__ bias, const float* __restrict__ resid,
              float* __restrict__ C, bf16* __restrict__ Chi, bf16* __restrict__ Clo,
              int R, int K, int Cout, long sA, long sB, long sC, int relu)
{
    int bz = blockIdx.z;
    Ahi += (long)bz*sA; Alo += (long)bz*sA;
    Bhi += (long)bz*sB; Blo += (long)bz*sB;
    if (C)     C   += (long)bz*sC;
    if (Chi) { Chi += (long)bz*sC; Clo += (long)bz*sC; }
    if (resid) resid += (long)bz*sC;

    extern __shared__ bf16 smb[];
    uint32_t sb = (uint32_t)__cvta_generic_to_shared(smb);

    int tid = threadIdx.x, lane = tid & 31, warp = tid >> 5;
    int wm = warp >> 2, wn = warp & 3;
    int rowBase = blockIdx.x * 128, colBase = blockIdx.y * 128;

    float c[4][4][4];
    #pragma unroll
    for (int i = 0; i < 4; i++)
        #pragma unroll
        for (int j = 0; j < 4; j++)
            { c[i][j][0]=0.f; c[i][j][1]=0.f; c[i][j][2]=0.f; c[i][j][3]=0.f; }

    const bf16* bases[4] = { Ahi, Alo, Bhi, Blo };
    int nk = K >> 5;

    #define FILL(st, kt) do { \
        int k0 = (kt) << 5; \
        _Pragma("unroll") \
        for (int t = 0; t < 8; t++) { \
            int o = tid + t*256; \
            int m = o >> 9, r = (o >> 2) & 127, seg = o & 3; \
            int gr = ((m < 2) ? rowBase : colBase) + r; \
            int lim = (m < 2) ? R : Cout; \
            long grc = (gr < lim) ? gr : 0; \
            const bf16* src = bases[m] + grc*K + k0 + seg*8; \
            uint32_t dst = sb + (st)*STAGE + m*MAT + r*80 + seg*16; \
            int nbytes = (gr < lim) ? 16 : 0; \
            asm volatile("cp.async.ca.shared.global [%0],[%1],16,%2;" \
                         :: "r"(dst), "l"(src), "r"(nbytes)); \
        } \
        asm volatile("cp.async.commit_group;"); \
    } while (0)

    FILL(0, 0);

    int ar = lane & 15, ak = (lane >> 4);
    int br = lane & 7,  bk = (lane >> 3) & 1;

    for (int kt = 0; kt < nk; kt++) {
        int st = kt & 1;
        if (kt + 1 < nk) {
            FILL(st ^ 1, kt + 1);
            asm volatile("cp.async.wait_group 1;");
        } else {
            asm volatile("cp.async.wait_group 0;");
        }
        __syncthreads();

        uint32_t aOff = sb + st*STAGE;
        uint32_t bOff = aOff + 2*MAT;
        #pragma unroll
        for (int ks = 0; ks < 2; ks++) {
            uint32_t Ah[4][4], Al[4][4];
            #pragma unroll
            for (int i = 0; i < 4; i++) {
                uint32_t ad = aOff + (uint32_t)((wm*64 + i*16 + ar)*80 + ak*16 + ks*32);
                LDM4(Ah[i][0], Ah[i][1], Ah[i][2], Ah[i][3], ad);
                LDM4(Al[i][0], Al[i][1], Al[i][2], Al[i][3], ad + MAT);
            }
            #pragma unroll
            for (int j = 0; j < 4; j++) {
                uint32_t bd = bOff + (uint32_t)((wn*32 + j*8 + br)*80 + bk*16 + ks*32);
                uint32_t Bh[2], Bl[2];
                LDM2(Bh[0], Bh[1], bd);
                LDM2(Bl[0], Bl[1], bd + MAT);
                #pragma unroll
                for (int i = 0; i < 4; i++) {
                    MMA16816(c[i][j], Ah[i], Bh);
                    MMA16816(c[i][j], Ah[i], Bl);
                    MMA16816(c[i][j], Al[i], Bh);
                }
            }
        }
        __syncthreads();
    }

    int gid = lane >> 2, tig = lane & 3;
    #pragma unroll
    for (int i = 0; i < 4; i++) {
        int rbase = rowBase + wm*64 + i*16 + gid;
        #pragma unroll
        for (int j = 0; j < 4; j++) {
            int c0 = colBase + wn*32 + j*8 + tig*2;
            if (c0 >= Cout) continue;
            #pragma unroll
            for (int hh = 0; hh < 2; hh++) {
                int row = rbase + hh*8;
                if (row >= R) continue;
                float v0 = c[i][j][2*hh], v1 = c[i][j][2*hh+1];
                if (bias)  { v0 += bias[c0]; v1 += bias[c0+1]; }
                if (resid) {
                    float2 rv = *(const float2*)(resid + (long)row*Cout + c0);
                    v0 += rv.x; v1 += rv.y;
                }
                if (relu) { v0 = fmaxf(v0, 0.f); v1 = fmaxf(v1, 0.f); }
                if (C) *(float2*)(C + (long)row*Cout + c0) = make_float2(v0, v1);
                if (Chi) {
                    bf16 h0 = __float2bfloat16(v0);
                    bf16 h1 = __float2bfloat16(v1);
                    bf16 l0 = __float2bfloat16(v0 - __bfloat162float(h0));
                    bf16 l1 = __float2bfloat16(v1 - __bfloat162float(h1));
                    uint32_t hp = ((uint32_t)__bfloat16_as_ushort(h1) << 16) | __bfloat16_as_ushort(h0);
                    uint32_t lp = ((uint32_t)__bfloat16_as_ushort(l1) << 16) | __bfloat16_as_ushort(l0);
                    *(uint32_t*)(Chi + (long)row*Cout + c0) = hp;
                    *(uint32_t*)(Clo + (long)row*Cout + c0) = lp;
                }
            }
        }
    }
}

// ---------------- attention v5: f32x2 packed FMA, j-pairs ----------------
__device__ __forceinline__ void wsplit8(const float* o, bf16* dh, bf16* dl)
{
    uint32_t hp[4], lp[4];
    #pragma unroll
    for (int j = 0; j < 4; j++) {
        bf16 h0 = __float2bfloat16(o[2*j]);
        bf16 h1 = __float2bfloat16(o[2*j+1]);
        bf16 l0 = __float2bfloat16(o[2*j]   - __bfloat162float(h0));
        bf16 l1 = __float2bfloat16(o[2*j+1] - __bfloat162float(h1));
        hp[j] = ((uint32_t)__bfloat16_as_ushort(h1) << 16) | __bfloat16_as_ushort(h0);
        lp[j] = ((uint32_t)__bfloat16_as_ushort(l1) << 16) | __bfloat16_as_ushort(l0);
    }
    *(uint4*)dh = make_uint4(hp[0], hp[1], hp[2], hp[3]);
    *(uint4*)dl = make_uint4(lp[0], lp[1], lp[2], lp[3]);
}

__global__ __launch_bounds__(256)
void attn5_kernel(const float* __restrict__ Q, int ldq,
                  const float* __restrict__ Kt, int ldk,
                  const float* __restrict__ Vt, int ldv,
                  const float* __restrict__ mask,
                  bf16* __restrict__ Oh, bf16* __restrict__ Ol)
{
    int h = blockIdx.x, b = blockIdx.y;
    extern __shared__ float sm[];
    float* Ks = sm;              // [16][NP]
    float* Vs = sm + DKK*NP;

    int tid = threadIdx.x;
    const float* Kb = Kt + (long)b*NN*ldk + h*DKK;
    const float* Vb = Vt + (long)b*NN*ldv + h*DKK;

    for (int idx = tid; idx < NN*4; idx += 256) {
        int n = idx >> 2;
        int c4 = (idx & 3) * 4;
        float4 kv = *(const float4*)(Kb + (long)n*ldk + c4);
        Ks[(c4+0)*NP+n]=kv.x; Ks[(c4+1)*NP+n]=kv.y; Ks[(c4+2)*NP+n]=kv.z; Ks[(c4+3)*NP+n]=kv.w;
        float4 vv = *(const float4*)(Vb + (long)n*ldv + c4);
        Vs[(c4+0)*NP+n]=vv.x; Vs[(c4+1)*NP+n]=vv.y; Vs[(c4+2)*NP+n]=vv.z; Vs[(c4+3)*NP+n]=vv.w;
    }
    if (tid < 64) sm[2*DKK*NP + tid] = 0.f;   // pad after Vs: OOB bleed lands on finite zeros
    __syncthreads();

    int warp = tid >> 5, lane = tid & 31;
    int jb0 = 2*lane;
    const unsigned FULL = 0xffffffffu;
    const ull QTR = pk2(0.25f, 0.25f);
    const ull NEG = pk2(-1e30f, -1e30f);

    for (int p = warp; p < NN/4; p += 8) {
        int q0 = 4*p;
        const float* Qb = Q + ((long)b*NN + q0)*ldq + h*DKK;
        float tq0 = (lane < DKK) ? Qb[lane]        : 0.f;
        float tq1 = (lane < DKK) ? Qb[ldq + lane]  : 0.f;
        float tq2 = (lane < DKK) ? Qb[2*ldq + lane]: 0.f;
        float tq3 = (lane < DKK) ? Qb[3*ldq + lane]: 0.f;

        ull s0[9], s1[9], s2[9], s3[9];
        #pragma unroll
        for (int i = 0; i < 9; i++) { s0[i]=0; s1[i]=0; s2[i]=0; s3[i]=0; }

        // ---- QK^T (packed j-pairs) ----
        #pragma unroll
        for (int t = 0; t < DKK; t++) {
            ull qp0 = pkdup(__shfl_sync(FULL, tq0, t));
            ull qp1 = pkdup(__shfl_sync(FULL, tq1, t));
            ull qp2 = pkdup(__shfl_sync(FULL, tq2, t));
            ull qp3 = pkdup(__shfl_sync(FULL, tq3, t));
            const float* kr = Ks + t*NP + jb0;
            #pragma unroll
            for (int i = 0; i < 9; i++) {
                ull kv = *(const ull*)(kr + 64*i);   // may bleed into next row; discarded below
                FMA2(s0[i], qp0, kv);
                FMA2(s1[i], qp1, kv);
                FMA2(s2[i], qp2, kv);
                FMA2(s3[i], qp3, kv);
            }
        }

        // ---- scale + mask + validity + max ----
        const float* mr = mask ? (mask + ((long)(b*MM + q0))*NN) : (const float*)0;
        float m0=-1e30f, m1=-1e30f, m2=-1e30f, m3=-1e30f;
        #pragma unroll
        for (int i = 0; i < 9; i++) {
            int jb = jb0 + 64*i;
            if (jb <= NN-2) {
                MUL2(s0[i], QTR); MUL2(s1[i], QTR); MUL2(s2[i], QTR); MUL2(s3[i], QTR);
                if (mr) {
                    ADD2(s0[i], *(const ull*)(mr + jb));
                    ADD2(s1[i], *(const ull*)(mr + NN + jb));
                    ADD2(s2[i], *(const ull*)(mr + 2*NN + jb));
                    ADD2(s3[i], *(const ull*)(mr + 3*NN + jb));
                }
                float2 f;
                f = upk(s0[i]); m0 = fmaxf(m0, fmaxf(f.x, f.y));
                f = upk(s1[i]); m1 = fmaxf(m1, fmaxf(f.x, f.y));
                f = upk(s2[i]); m2 = fmaxf(m2, fmaxf(f.x, f.y));
                f = upk(s3[i]); m3 = fmaxf(m3, fmaxf(f.x, f.y));
            } else {
                s0[i] = NEG; s1[i] = NEG; s2[i] = NEG; s3[i] = NEG;
            }
        }
        #pragma unroll
        for (int off = 16; off > 0; off >>= 1) {
            m0 = fmaxf(m0, __shfl_xor_sync(FULL, m0, off));
            m1 = fmaxf(m1, __shfl_xor_sync(FULL, m1, off));
            m2 = fmaxf(m2, __shfl_xor_sync(FULL, m2, off));
            m3 = fmaxf(m3, __shfl_xor_sync(FULL, m3, off));
        }

        // ---- exp + sum ----
        float u0=0.f, u1=0.f, u2=0.f, u3=0.f;
        #pragma unroll
        for (int i = 0; i < 9; i++) {
            float2 f;
            f = upk(s0[i]); f.x = __expf(f.x - m0); f.y = __expf(f.y - m0);
            u0 += f.x + f.y; s0[i] = pk2(f.x, f.y);
            f = upk(s1[i]); f.x = __expf(f.x - m1); f.y = __expf(f.y - m1);
            u1 += f.x + f.y; s1[i] = pk2(f.x, f.y);
            f = upk(s2[i]); f.x = __expf(f.x - m2); f.y = __expf(f.y - m2);
            u2 += f.x + f.y; s2[i] = pk2(f.x, f.y);
            f = upk(s3[i]); f.x = __expf(f.x - m3); f.y = __expf(f.y - m3);
            u3 += f.x + f.y; s3[i] = pk2(f.x, f.y);
        }
        #pragma unroll
        for (int off = 16; off > 0; off >>= 1) {
            u0 += __shfl_xor_sync(FULL, u0, off);
            u1 += __shfl_xor_sync(FULL, u1, off);
            u2 += __shfl_xor_sync(FULL, u2, off);
            u3 += __shfl_xor_sync(FULL, u3, off);
        }
        {
            ull iv0 = pkdup(1.f/u0), iv1 = pkdup(1.f/u1);
            ull iv2 = pkdup(1.f/u2), iv3 = pkdup(1.f/u3);
            #pragma unroll
            for (int i = 0; i < 9; i++) {
                MUL2(s0[i], iv0); MUL2(s1[i], iv1);
                MUL2(s2[i], iv2); MUL2(s3[i], iv3);
            }
        }

        // ---- P @ V (packed), t in halves to bound accumulator registers ----
        #pragma unroll
        for (int th = 0; th < 2; th++) {
            ull a0[8], a1[8], a2[8], a3[8];
            #pragma unroll
            for (int t = 0; t < 8; t++) { a0[t]=0; a1[t]=0; a2[t]=0; a3[t]=0; }
            #pragma unroll
            for (int t = 0; t < 8; t++) {
                const float* vr = Vs + (th*8 + t)*NP + jb0;
                #pragma unroll
                for (int i = 0; i < 9; i++) {
                    ull vv = *(const ull*)(vr + 64*i);   // bleed -> finite; weight = 0
                    FMA2(a0[t], s0[i], vv);
                    FMA2(a1[t], s1[i], vv);
                    FMA2(a2[t], s2[i], vv);
                    FMA2(a3[t], s3[i], vv);
                }
            }
            float o0[8], o1[8], o2[8], o3[8];
            #pragma unroll
            for (int t = 0; t < 8; t++) {
                float2 f;
                f = upk(a0[t]); o0[t] = f.x + f.y;
                f = upk(a1[t]); o1[t] = f.x + f.y;
                f = upk(a2[t]); o2[t] = f.x + f.y;
                f = upk(a3[t]); o3[t] = f.x + f.y;
                #pragma unroll
                for (int off = 16; off > 0; off >>= 1) {
                    o0[t] += __shfl_xor_sync(FULL, o0[t], off);
                    o1[t] += __shfl_xor_sync(FULL, o1[t], off);
                    o2[t] += __shfl_xor_sync(FULL, o2[t], off);
                    o3[t] += __shfl_xor_sync(FULL, o3[t], off);
                }
            }
            if (lane == 0) {
                long base = ((long)(b*NN + q0))*EE + h*DKK + th*8;
                wsplit8(o0, Oh + base,        Ol + base);
                wsplit8(o1, Oh + base + EE,   Ol + base + EE);
                wsplit8(o2, Oh + base + 2*EE, Ol + base + 2*EE);
                wsplit8(o3, Oh + base + 3*EE, Ol + base + 3*EE);
            }
        }
    }
}

// ---------------- instance norm ----------------
__global__ void inorm_stats(const float* __restrict__ Y)
{
    int b = blockIdx.x, ch = blockIdx.y, e = threadIdx.x;
    float s1 = 0.f, s2 = 0.f;
    for (int n = ch; n < NN; n += 8) {
        float v = Y[((long)(b*NN + n))*EE + e];
        s1 += v; s2 += v*v;
    }
    int idx = (b*8 + ch)*EE + e;
    g_part[idx*2]   = s1;
    g_part[idx*2+1] = s2;
}
__global__ void inorm_fin()
{
    int b = blockIdx.x, e = threadIdx.x;
    float s1 = 0.f, s2 = 0.f;
    for (int c = 0; c < 8; c++) {
        int idx = (b*8 + c)*EE + e;
        s1 += g_part[idx*2]; s2 += g_part[idx*2+1];
    }
    float mean = s1 / (float)NN;
    float var  = s2 / (float)NN - mean*mean;
    g_stats[(b*EE+e)*2]   = mean;
    g_stats[(b*EE+e)*2+1] = rsqrtf(var + 1e-5f);
}
__global__ void inorm_apply(const float* __restrict__ Y, const float* __restrict__ gg,
                            const float* __restrict__ bt, float* __restrict__ Xo,
                            bf16* __restrict__ Xh, bf16* __restrict__ Xl)
{
    int idx = blockIdx.x * blockDim.x + threadIdx.x;
    if (idx >= BB*NN*EE) return;
    int e = idx % EE;
    int b = idx / (NN*EE);
    float mean = g_stats[(b*EE+e)*2];
    float istd = g_stats[(b*EE+e)*2+1];
    float v = (Y[idx] - mean) * istd * gg[e] + bt[e];
    Xo[idx] = v;
    split1(v, Xh + idx, Xl + idx);
}

// ---------------- decoder helpers ----------------
__global__ void encmean_kernel()
{
    int b = blockIdx.x, e = threadIdx.x;
    float s = 0.f;
    for (int n = 0; n < NN; n++) s += g_x[((long)(b*NN + n))*EE + e];
    g_encmean[b*EE + e] = s / (float)NN;
}

__global__ void build_cat(const float* __restrict__ loadv, const int* __restrict__ cur,
                          const int* __restrict__ subn, const int* __restrict__ subl,
                          const int* __restrict__ sel)
{
    int r = blockIdx.x;
    int b = r / MM;
    int e = threadIdx.x;
    int c = cur[r];
    float le = g_x[((long)(b*NN + c))*EE + e];

    int len = subl[r];
    const int* nodes = subn + (long)r*LL;
    float ssum = 0.f; int cnt = 0;
    for (int l = 0; l < LL; l++) {
        int nd = nodes[l];
        if (l < len && nd >= DEPOTN) {
            ssum += g_x[((long)(b*NN + nd))*EE + e];
            cnt++;
        }
    }
    float cntf = (cnt > 0) ? (float)cnt : 1.f;
    float smean = ssum / cntf;

    long bl = (long)r*256, br = (long)r*KRT;
    split1(le,    g_catlh + bl + e,       g_catll + bl + e);
    split1(smean, g_catlh + bl + 128 + e, g_catll + bl + 128 + e);
    split1(le,    g_catrh + br + e,       g_catrl + br + e);
    split1(g_encmean[b*EE + e], g_catrh + br + 128 + e, g_catrl + br + 128 + e);
    if (e == 0) split1(loadv[r], g_catrh + br + 256, g_catrl + br + 256);
    if (e >= 1 && e < 32) { g_catrh[br + 256 + e] = __float2bfloat16(0.f);
                            g_catrl[br + 256 + e] = __float2bfloat16(0.f); }
    if (e == 0) {
        int s2 = sel[(long)r*4 + 2];
        g_flag[r] = (s2 >= DEPOTN && c < DEPOTN) ? 1.f : 0.f;
    }
}

__global__ void blend_kernel()
{
    int idx = blockIdx.x * blockDim.x + threadIdx.x;
    if (idx >= BB*MM*EE) return;
    int r = idx / EE;
    float f = g_flag[r];
    g_fq[idx] = f * g_qloc[idx] + (1.f - f) * g_qrout[idx];
}

// ---------------- final tanh-clip + mask + softmax ----------------
__global__ void final_kernel(const float* __restrict__ mask, float* __restrict__ out)
{
    int r = blockIdx.x;
    int tid = threadIdx.x;
    __shared__ float buf[NN];
    __shared__ float red[256];
    const float* sn = g_sn + (long)r*NN;
    const float* mk = mask + (long)r*NN;
    const float invs = 0.08838834764831845f;

    float lm = -1e30f;
    for (int j = tid; j < NN; j += 256) {
        float v = 10.f * tanhf(sn[j] * invs) + mk[j];
        buf[j] = v;
        lm = fmaxf(lm, v);
    }
    red[tid] = lm; __syncthreads();
    for (int off = 128; off > 0; off >>= 1) {
        if (tid < off) red[tid] = fmaxf(red[tid], red[tid+off]);
        __syncthreads();
    }
    float mx = red[0]; __syncthreads();

    float ls = 0.f;
    for (int j = tid; j < NN; j += 256) {
        float e0 = __expf(buf[j] - mx);
        buf[j] = e0; ls += e0;
    }
    red[tid] = ls; __syncthreads();
    for (int off = 128; off > 0; off >>= 1) {
        if (tid < off) red[tid] += red[tid+off];
        __syncthreads();
    }
    float inv = 1.f / red[0];
    for (int j = tid; j < NN; j += 256)
        out[(long)r*NN + j] = buf[j] * inv;
}

// ---------------- host ----------------
#define GEMM_SMEM 81920
#define ATTN_SMEM (2*DKK*NP*4 + 256)

static void launch_tc(const bf16* Ah, const bf16* Al, const bf16* Bh, const bf16* Bl,
                      const float* bias, const float* resid,
                      float* C, bf16* Ch, bf16* Cl,
                      int R, int K, int Cout, int batch,
                      long sA, long sB, long sC, int relu)
{
    dim3 grid((R + 127) / 128, (Cout + 127) / 128, batch);
    gemm_tc2<<<grid, 256, GEMM_SMEM>>>(Ah, Al, Bh, Bl, bias, resid, C, Ch, Cl,
                                       R, K, Cout, sA, sB, sC, relu);
}

#define SYM(p, s) cudaGetSymbolAddress((void**)&p, s)

extern "C" void kernel_launch(void* const* d_in, const int* in_sizes, int n_in,
                              void* d_out, int out_size)
{
    const float* depot  = (const float*)d_in[0];
    const float* cust   = (const float*)d_in[1];
    const float* mask   = (const float*)d_in[2];
    const float* loadv  = (const float*)d_in[3];
    const int*   cur    = (const int*)d_in[4];
    const int*   subn   = (const int*)d_in[5];
    const int*   subl   = (const int*)d_in[6];
    const int*   sel    = (const int*)d_in[7];
    const float* edW    = (const float*)d_in[8];
    const float* edb    = (const float*)d_in[9];
    const float* ecW    = (const float*)d_in[10];
    const float* ecb    = (const float*)d_in[11];
    const float* Wq     = (const float*)d_in[12];
    const float* Wk     = (const float*)d_in[13];
    const float* Wv     = (const float*)d_in[14];
    const float* Wc     = (const float*)d_in[15];
    const float* Wcb    = (const float*)d_in[16];
    const float* n1g    = (const float*)d_in[17];
    const float* n1b    = (const float*)d_in[18];
    const float* fW1    = (const float*)d_in[19];
    const float* fb1    = (const float*)d_in[20];
    const float* fW2    = (const float*)d_in[21];
    const float* fb2    = (const float*)d_in[22];
    const float* n2g    = (const float*)d_in[23];
    const float* n2b    = (const float*)d_in[24];
    const float* dWqloc = (const float*)d_in[25];
    const float* dWqrt  = (const float*)d_in[26];
    const float* dWk    = (const float*)d_in[27];
    const float* dWv    = (const float*)d_in[28];
    const float* dWc    = (const float*)d_in[29];
    const float* dWcb   = (const float*)d_in[30];
    float* out = (float*)d_out;

    float *px, *pqkv, *py, *px1, *pkvd, *pqloc, *pqrout, *pfq, *psn;
    SYM(px, g_x); SYM(pqkv, g_qkv); SYM(py, g_y); SYM(px1, g_x1);
    SYM(pkvd, g_kvd); SYM(pqloc, g_qloc); SYM(pqrout, g_qrout);
    SYM(pfq, g_fq); SYM(psn, g_sn);

    bf16 *pxh,*pxl, *px1h,*px1l, *pmhh,*pmhl, *pffhh,*pffhl, *pattnh,*pattnl;
    bf16 *pscoreh,*pscorel, *pcatlh,*pcatll, *pcatrh,*pcatrl;
    bf16 *pwqkvh,*pwqkvl, *pwch,*pwcl, *pf1h,*pf1l, *pf2h,*pf2l;
    bf16 *pwkvh,*pwkvl, *pwqlh,*pwqll, *pwpah,*pwpal, *pwdch,*pwdcl;
    SYM(pxh, g_xh); SYM(pxl, g_xl); SYM(px1h, g_x1h); SYM(px1l, g_x1l);
    SYM(pmhh, g_mhh); SYM(pmhl, g_mhl); SYM(pffhh, g_ffhh); SYM(pffhl, g_ffhl);
    SYM(pattnh, g_attnh); SYM(pattnl, g_attnl);
    SYM(pscoreh, g_scoreh); SYM(pscorel, g_scorel);
    SYM(pcatlh, g_catlh); SYM(pcatll, g_catll); SYM(pcatrh, g_catrh); SYM(pcatrl, g_catrl);
    SYM(pwqkvh, g_wqkvh); SYM(pwqkvl, g_wqkvl); SYM(pwch, g_wch); SYM(pwcl, g_wcl);
    SYM(pf1h, g_f1h); SYM(pf1l, g_f1l); SYM(pf2h, g_f2h); SYM(pf2l, g_f2l);
    SYM(pwkvh, g_wkvh); SYM(pwkvl, g_wkvl); SYM(pwqlh, g_wqlh); SYM(pwqll, g_wqll);
    SYM(pwpah, g_wpah); SYM(pwpal, g_wpal); SYM(pwdch, g_wdch); SYM(pwdcl, g_wdcl);

    const int R = BB * NN;
    const int TOT = BB * NN * EE;
    static int smem_set = 0;
    if (!smem_set) {
        cudaFuncSetAttribute(attn5_kernel, cudaFuncAttributeMaxDynamicSharedMemorySize, ATTN_SMEM);
        cudaFuncSetAttribute(gemm_tc2, cudaFuncAttributeMaxDynamicSharedMemorySize, GEMM_SMEM);
        smem_set = 1;
    }

    // ---- one-time converts ----
    embed_kernel<<<(TOT + 255)/256, 256>>>(depot, cust, edW, edb, ecW, ecb);
    pack_w<<<(NLL*384*EE + 256*EE + 255)/256, 256>>>(Wq, Wk, Wv, dWk, dWv);
    padw_kernel<<<(EE*KRT + 255)/256, 256>>>(dWqrt);
    cvt_split<<<(NLL*EE*EE + 255)/256, 256>>>(Wc,  pwch, pwcl, NLL*EE*EE);
    cvt_split<<<(NLL*FFHH*EE + 255)/256, 256>>>(fW1, pf1h, pf1l, NLL*FFHH*EE);
    cvt_split<<<(NLL*EE*FFHH + 255)/256, 256>>>(fW2, pf2h, pf2l, NLL*EE*FFHH);
    cvt_split<<<(EE*256 + 255)/256, 256>>>(dWqloc, pwqlh, pwqll, EE*256);
    cvt_split<<<(EE*EE + 255)/256, 256>>>(dWc, pwdch, pwdcl, EE*EE);

    // ---- encoder ----
    for (int i = 0; i < NLL; i++) {
        launch_tc(pxh, pxl, pwqkvh + (long)i*384*EE, pwqkvl + (long)i*384*EE,
                  0, 0, pqkv, 0, 0, R, EE, 384, 1, 0, 0, 0, 0);
        attn5_kernel<<<dim3(HH, BB), 256, ATTN_SMEM>>>(pqkv, 384, pqkv + 128, 384,
                                                       pqkv + 256, 384, (const float*)0,
                                                       pmhh, pmhl);
        launch_tc(pmhh, pmhl, pwch + (long)i*EE*EE, pwcl + (long)i*EE*EE,
                  Wcb + (long)i*EE, px, py, 0, 0, R, EE, EE, 1, 0, 0, 0, 0);
        inorm_stats<<<dim3(BB, 8), EE>>>(py);
        inorm_fin<<<BB, EE>>>();
        inorm_apply<<<(TOT + 255)/256, 256>>>(py, n1g + (long)i*EE, n1b + (long)i*EE,
                                              px1, px1h, px1l);
        launch_tc(px1h, px1l, pf1h + (long)i*FFHH*EE, pf1l + (long)i*FFHH*EE,
                  fb1 + (long)i*FFHH, 0, 0, pffhh, pffhl, R, EE, FFHH, 1, 0, 0, 0, 1);
        launch_tc(pffhh, pffhl, pf2h + (long)i*EE*FFHH, pf2l + (long)i*EE*FFHH,
                  fb2 + (long)i*EE, px1, py, 0, 0, R, FFHH, EE, 1, 0, 0, 0, 0);
        inorm_stats<<<dim3(BB, 8), EE>>>(py);
        inorm_fin<<<BB, EE>>>();
        inorm_apply<<<(TOT + 255)/256, 256>>>(py, n2g + (long)i*EE, n2b + (long)i*EE,
                                              px, pxh, pxl);
    }

    // ---- decoder ----
    launch_tc(pxh, pxl, pwkvh, pwkvl, 0, 0, pkvd, 0, 0, R, EE, 256, 1, 0, 0, 0, 0);
    encmean_kernel<<<BB, EE>>>();
    build_cat<<<BB*MM, EE>>>(loadv, cur, subn, subl, sel);
    launch_tc(pcatlh, pcatll, pwqlh, pwqll, 0, 0, pqloc, 0, 0, R, 256, EE, 1, 0, 0, 0, 0);
    launch_tc(pcatrh, pcatrl, pwpah, pwpal, 0, 0, pqrout, 0, 0, R, KRT, EE, 1, 0, 0, 0, 0);
    blend_kernel<<<(BB*MM*EE + 255)/256, 256>>>();
    attn5_kernel<<<dim3(HH, BB), 256, ATTN_SMEM>>>(pfq, 128, pkvd, 256, pkvd + 128, 256,
                                                   mask, pattnh, pattnl);
    launch_tc(pattnh, pattnl, pwdch, pwdcl, dWcb, 0, 0, pscoreh, pscorel,
              R, EE, EE, 1, 0, 0, 0, 0);
    launch_tc(pscoreh, pscorel, pxh, pxl, 0, 0, psn, 0, 0, MM, EE, NN, BB,
              (long)MM*EE, (long)NN*EE, (long)MM*NN, 0);
    final_kernel<<<BB*MM, 256>>>(mask, out);
}

// round 7
// speedup vs baseline: 1.3653x; 1.3653x over previous
#include <cuda_runtime.h>
#include <cuda_bf16.h>
#include <math.h>
#include <stdint.h>

#define BB 32
#define NN 520
#define DEPOTN 20
#define CUSTN 500
#define EE 128
#define HH 8
#define DKK 16
#define FFHH 512
#define NLL 6
#define MM 520
#define LL 40
#define KRT 288

typedef __nv_bfloat16 bf16;

// ---------------- fp32 scratch ----------------
__device__ __align__(16) float g_x   [BB*NN*EE];
__device__ __align__(16) float g_qkv [BB*NN*384];
__device__ __align__(16) float g_y   [BB*NN*EE];
__device__ __align__(16) float g_x1  [BB*NN*EE];
__device__ __align__(16) float g_part[BB*8*EE*2];
__device__ __align__(16) float g_stats[BB*EE*2];
__device__ __align__(16) float g_kvd [BB*NN*256];
__device__ __align__(16) float g_encmean[BB*EE];
__device__ __align__(16) float g_qloc [BB*MM*EE];
__device__ __align__(16) float g_qrout[BB*MM*EE];
__device__ __align__(16) float g_fq   [BB*MM*EE];
__device__ __align__(16) float g_flag [BB*MM];
__device__ __align__(16) float g_sn   [BB*MM*NN];

// ---------------- bf16 hi/lo scratch ----------------
__device__ __align__(16) bf16 g_xh[BB*NN*EE],      g_xl[BB*NN*EE];
__device__ __align__(16) bf16 g_x1h[BB*NN*EE],     g_x1l[BB*NN*EE];
__device__ __align__(16) bf16 g_mhh[BB*NN*EE],     g_mhl[BB*NN*EE];
__device__ __align__(16) bf16 g_ffhh[BB*NN*FFHH],  g_ffhl[BB*NN*FFHH];
__device__ __align__(16) bf16 g_attnh[BB*MM*EE],   g_attnl[BB*MM*EE];
__device__ __align__(16) bf16 g_scoreh[BB*MM*EE],  g_scorel[BB*MM*EE];
__device__ __align__(16) bf16 g_catlh[BB*MM*256],  g_catll[BB*MM*256];
__device__ __align__(16) bf16 g_catrh[BB*MM*KRT],  g_catrl[BB*MM*KRT];
__device__ __align__(16) bf16 g_wqkvh[NLL*384*EE], g_wqkvl[NLL*384*EE];
__device__ __align__(16) bf16 g_wch[NLL*EE*EE],    g_wcl[NLL*EE*EE];
__device__ __align__(16) bf16 g_f1h[NLL*FFHH*EE],  g_f1l[NLL*FFHH*EE];
__device__ __align__(16) bf16 g_f2h[NLL*EE*FFHH],  g_f2l[NLL*EE*FFHH];
__device__ __align__(16) bf16 g_wkvh[256*EE],      g_wkvl[256*EE];
__device__ __align__(16) bf16 g_wqlh[EE*256],      g_wqll[EE*256];
__device__ __align__(16) bf16 g_wpah[EE*KRT],      g_wpal[EE*KRT];
__device__ __align__(16) bf16 g_wdch[EE*EE],       g_wdcl[EE*EE];

__device__ __forceinline__ void split1(float x, bf16* h, bf16* l)
{
    bf16 hv = __float2bfloat16(x);
    *h = hv;
    *l = __float2bfloat16(x - __bfloat162float(hv));
}

__device__ __forceinline__ void cvtpk(float x0, float x1, uint32_t& h, uint32_t& l)
{
    bf16 h0 = __float2bfloat16(x0), h1 = __float2bfloat16(x1);
    float l0 = x0 - __bfloat162float(h0), l1 = x1 - __bfloat162float(h1);
    h = ((uint32_t)__bfloat16_as_ushort(h1) << 16) | __bfloat16_as_ushort(h0);
    bf16 g0 = __float2bfloat16(l0), g1 = __float2bfloat16(l1);
    l = ((uint32_t)__bfloat16_as_ushort(g1) << 16) | __bfloat16_as_ushort(g0);
}

// ---------------- generic fp32 -> hi/lo ----------------
__global__ void cvt_split(const float* __restrict__ s, bf16* __restrict__ h,
                          bf16* __restrict__ l, int n)
{
    int i = blockIdx.x * blockDim.x + threadIdx.x;
    if (i < n) split1(s[i], h + i, l + i);
}

// ---------------- embedding ----------------
__global__ void embed_kernel(const float* __restrict__ dep, const float* __restrict__ cus,
                             const float* __restrict__ Wd, const float* __restrict__ bd,
                             const float* __restrict__ Wc, const float* __restrict__ bc)
{
    int idx = blockIdx.x * blockDim.x + threadIdx.x;
    if (idx >= BB*NN*EE) return;
    int e = idx % EE;
    int n = (idx / EE) % NN;
    int b = idx / (EE*NN);
    float acc;
    if (n < DEPOTN) {
        const float* f = dep + ((long)b*DEPOTN + n) * 4;
        acc = bd[e];
        #pragma unroll
        for (int j = 0; j < 4; j++) acc += f[j] * Wd[e*4 + j];
    } else {
        const float* f = cus + ((long)b*CUSTN + (n - DEPOTN)) * 3;
        acc = bc[e];
        #pragma unroll
        for (int j = 0; j < 3; j++) acc += f[j] * Wc[e*3 + j];
    }
    g_x[idx] = acc;
    split1(acc, g_xh + idx, g_xl + idx);
}

// ---------------- weight packing ----------------
__global__ void pack_w(const float* __restrict__ Wq, const float* __restrict__ Wk,
                       const float* __restrict__ Wv, const float* __restrict__ dWk,
                       const float* __restrict__ dWv)
{
    int idx = blockIdx.x * blockDim.x + threadIdx.x;
    const int tot1 = NLL*384*EE;
    if (idx < tot1) {
        int col = idx % EE;
        int row = (idx / EE) % 384;
        int l   = idx / (EE*384);
        float v;
        if (row < 128)      v = Wq[((long)l*EE + row)*EE + col];
        else if (row < 256) v = Wk[((long)l*EE + row-128)*EE + col];
        else                v = Wv[((long)l*EE + row-256)*EE + col];
        split1(v, g_wqkvh + idx, g_wqkvl + idx);
    } else {
        int j = idx - tot1;
        if (j < 256*EE) {
            int col = j % EE;
            int row = j / EE;
            float v = (row < 128) ? dWk[row*EE + col] : dWv[(row-128)*EE + col];
            split1(v, g_wkvh + j, g_wkvl + j);
        }
    }
}

__global__ void padw_kernel(const float* __restrict__ Wr)
{
    int idx = blockIdx.x * blockDim.x + threadIdx.x;
    if (idx >= EE*KRT) return;
    int rr = idx / KRT, cc = idx % KRT;
    float v = (cc < 257) ? Wr[rr*257 + cc] : 0.f;
    split1(v, g_wpah + idx, g_wpal + idx);
}

// ---------------- MMA primitives ----------------
#define LDM4(r0,r1,r2,r3,addr) \
    asm volatile("ldmatrix.sync.aligned.m8n8.x4.shared.b16 {%0,%1,%2,%3},[%4];" \
                 : "=r"(r0),"=r"(r1),"=r"(r2),"=r"(r3) : "r"(addr))
#define LDM2(r0,r1,addr) \
    asm volatile("ldmatrix.sync.aligned.m8n8.x2.shared.b16 {%0,%1},[%2];" \
                 : "=r"(r0),"=r"(r1) : "r"(addr))
#define MMA16816(c,a,b) \
    asm volatile("mma.sync.aligned.m16n8k16.row.col.f32.bf16.bf16.f32 " \
                 "{%0,%1,%2,%3},{%4,%5,%6,%7},{%8,%9},{%0,%1,%2,%3};" \
                 : "+f"((c)[0]),"+f"((c)[1]),"+f"((c)[2]),"+f"((c)[3]) \
                 : "r"((a)[0]),"r"((a)[1]),"r"((a)[2]),"r"((a)[3]), "r"((b)[0]),"r"((b)[1]))

// ---------------- TC GEMM v2 (unchanged, proven) ----------------
#define MAT 10240
#define STAGE 40960

__global__ __launch_bounds__(256, 2)
void gemm_tc2(const bf16* __restrict__ Ahi, const bf16* __restrict__ Alo,
              const bf16* __restrict__ Bhi, const bf16* __restrict__ Blo,
              const float* __restrict__ bias, const float* __restrict__ resid,
              float* __restrict__ C, bf16* __restrict__ Chi, bf16* __restrict__ Clo,
              int R, int K, int Cout, long sA, long sB, long sC, int relu)
{
    int bz = blockIdx.z;
    Ahi += (long)bz*sA; Alo += (long)bz*sA;
    Bhi += (long)bz*sB; Blo += (long)bz*sB;
    if (C)     C   += (long)bz*sC;
    if (Chi) { Chi += (long)bz*sC; Clo += (long)bz*sC; }
    if (resid) resid += (long)bz*sC;

    extern __shared__ bf16 smb[];
    uint32_t sb = (uint32_t)__cvta_generic_to_shared(smb);

    int tid = threadIdx.x, lane = tid & 31, warp = tid >> 5;
    int wm = warp >> 2, wn = warp & 3;
    int rowBase = blockIdx.x * 128, colBase = blockIdx.y * 128;

    float c[4][4][4];
    #pragma unroll
    for (int i = 0; i < 4; i++)
        #pragma unroll
        for (int j = 0; j < 4; j++)
            { c[i][j][0]=0.f; c[i][j][1]=0.f; c[i][j][2]=0.f; c[i][j][3]=0.f; }

    const bf16* bases[4] = { Ahi, Alo, Bhi, Blo };
    int nk = K >> 5;

    #define FILL(st, kt) do { \
        int k0 = (kt) << 5; \
        _Pragma("unroll") \
        for (int t = 0; t < 8; t++) { \
            int o = tid + t*256; \
            int m = o >> 9, r = (o >> 2) & 127, seg = o & 3; \
            int gr = ((m < 2) ? rowBase : colBase) + r; \
            int lim = (m < 2) ? R : Cout; \
            long grc = (gr < lim) ? gr : 0; \
            const bf16* src = bases[m] + grc*K + k0 + seg*8; \
            uint32_t dst = sb + (st)*STAGE + m*MAT + r*80 + seg*16; \
            int nbytes = (gr < lim) ? 16 : 0; \
            asm volatile("cp.async.ca.shared.global [%0],[%1],16,%2;" \
                         :: "r"(dst), "l"(src), "r"(nbytes)); \
        } \
        asm volatile("cp.async.commit_group;"); \
    } while (0)

    FILL(0, 0);

    int ar = lane & 15, ak = (lane >> 4);
    int br = lane & 7,  bk = (lane >> 3) & 1;

    for (int kt = 0; kt < nk; kt++) {
        int st = kt & 1;
        if (kt + 1 < nk) {
            FILL(st ^ 1, kt + 1);
            asm volatile("cp.async.wait_group 1;");
        } else {
            asm volatile("cp.async.wait_group 0;");
        }
        __syncthreads();

        uint32_t aOff = sb + st*STAGE;
        uint32_t bOff = aOff + 2*MAT;
        #pragma unroll
        for (int ks = 0; ks < 2; ks++) {
            uint32_t Ah[4][4], Al[4][4];
            #pragma unroll
            for (int i = 0; i < 4; i++) {
                uint32_t ad = aOff + (uint32_t)((wm*64 + i*16 + ar)*80 + ak*16 + ks*32);
                LDM4(Ah[i][0], Ah[i][1], Ah[i][2], Ah[i][3], ad);
                LDM4(Al[i][0], Al[i][1], Al[i][2], Al[i][3], ad + MAT);
            }
            #pragma unroll
            for (int j = 0; j < 4; j++) {
                uint32_t bd = bOff + (uint32_t)((wn*32 + j*8 + br)*80 + bk*16 + ks*32);
                uint32_t Bh[2], Bl[2];
                LDM2(Bh[0], Bh[1], bd);
                LDM2(Bl[0], Bl[1], bd + MAT);
                #pragma unroll
                for (int i = 0; i < 4; i++) {
                    MMA16816(c[i][j], Ah[i], Bh);
                    MMA16816(c[i][j], Ah[i], Bl);
                    MMA16816(c[i][j], Al[i], Bh);
                }
            }
        }
        __syncthreads();
    }

    int gid = lane >> 2, tig = lane & 3;
    #pragma unroll
    for (int i = 0; i < 4; i++) {
        int rbase = rowBase + wm*64 + i*16 + gid;
        #pragma unroll
        for (int j = 0; j < 4; j++) {
            int c0 = colBase + wn*32 + j*8 + tig*2;
            if (c0 >= Cout) continue;
            #pragma unroll
            for (int hh = 0; hh < 2; hh++) {
                int row = rbase + hh*8;
                if (row >= R) continue;
                float v0 = c[i][j][2*hh], v1 = c[i][j][2*hh+1];
                if (bias)  { v0 += bias[c0]; v1 += bias[c0+1]; }
                if (resid) {
                    float2 rv = *(const float2*)(resid + (long)row*Cout + c0);
                    v0 += rv.x; v1 += rv.y;
                }
                if (relu) { v0 = fmaxf(v0, 0.f); v1 = fmaxf(v1, 0.f); }
                if (C) *(float2*)(C + (long)row*Cout + c0) = make_float2(v0, v1);
                if (Chi) {
                    uint32_t hp, lp;
                    cvtpk(v0, v1, hp, lp);
                    *(uint32_t*)(Chi + (long)row*Cout + c0) = hp;
                    *(uint32_t*)(Clo + (long)row*Cout + c0) = lp;
                }
            }
        }
    }
}

// ---------------- attention via MMA (FA2-style, hi/lo bf16) ----------------
// block = (q-tile of 128, head, batch); 8 warps, warp = m16 queries.
#define KPAD 576
#define KROW 24                  // bf16 per K/Q smem row (48 B pitch)
#define VROW 584                 // bf16 per VT smem row (1168 B pitch)
#define KLO_B  27648             // byte offsets inside dynamic smem
#define VHI_B  55296
#define VLO_B  18688             // relative to VHI
#define QHI_B  92672
#define QLO_B  6144              // relative to QHI
#define ATTN2_SMEM 104960

__global__ __launch_bounds__(256)
void attn_mma(const float* __restrict__ Q, int ldq,
              const float* __restrict__ Kt, int ldk,
              const float* __restrict__ Vt, int ldv,
              const float* __restrict__ mask,
              bf16* __restrict__ Oh, bf16* __restrict__ Ol)
{
    int qb = blockIdx.x * 128;
    int h = blockIdx.y, b = blockIdx.z;
    extern __shared__ bf16 sm2[];
    uint32_t sb = (uint32_t)__cvta_generic_to_shared(sm2);
    int tid = threadIdx.x;

    // element-index bases within sm2
    const int KHI_E = 0, KLO_E = 13824, VHI_E = 27648, VLO_E = 36992;
    const int QHI_E = 46336, QLO_E = 49408;

    // stage K (keys x 16, 48B pitch) and VT (16 x keys, 1168B pitch), hi/lo
    const float* Kg = Kt + (long)b*NN*ldk + h*DKK;
    const float* Vg = Vt + (long)b*NN*ldv + h*DKK;
    for (int i = tid; i < KPAD*DKK; i += 256) {
        int key = i >> 4, d = i & 15;
        float kv = (key < NN) ? Kg[(long)key*ldk + d] : 0.f;
        float vv = (key < NN) ? Vg[(long)key*ldv + d] : 0.f;
        bf16 kh = __float2bfloat16(kv);
        bf16 kl = __float2bfloat16(kv - __bfloat162float(kh));
        bf16 vh = __float2bfloat16(vv);
        bf16 vl = __float2bfloat16(vv - __bfloat162float(vh));
        sm2[KHI_E + key*KROW + d] = kh;
        sm2[KLO_E + key*KROW + d] = kl;
        sm2[VHI_E + d*VROW + key] = vh;
        sm2[VLO_E + d*VROW + key] = vl;
    }
    const float* Qg = Q + (long)b*NN*ldq + h*DKK;
    for (int i = tid; i < 128*DKK; i += 256) {
        int row = i >> 4, d = i & 15;
        int q = qb + row;
        float qv = (q < NN) ? Qg[(long)q*ldq + d] : 0.f;
        bf16 qh = __float2bfloat16(qv);
        sm2[QHI_E + row*KROW + d] = qh;
        sm2[QLO_E + row*KROW + d] = __float2bfloat16(qv - __bfloat162float(qh));
    }
    __syncthreads();

    int warp = tid >> 5, lane = tid & 31;
    int g = lane >> 2;
    int ar = lane & 15, ak = lane >> 4;
    int br = lane & 7,  bk = (lane >> 3) & 1;
    const unsigned FULL = 0xffffffffu;

    // A fragments: Q hi/lo (fixed for whole kernel)
    uint32_t Qh[4], Ql[4];
    {
        uint32_t qa = sb + QHI_B + (uint32_t)((warp*16 + ar)*48 + ak*16);
        LDM4(Qh[0], Qh[1], Qh[2], Qh[3], qa);
        LDM4(Ql[0], Ql[1], Ql[2], Ql[3], qa + QLO_B);
    }

    float o[2][4];
    #pragma unroll
    for (int n = 0; n < 2; n++) { o[n][0]=0.f; o[n][1]=0.f; o[n][2]=0.f; o[n][3]=0.f; }
    float mrow[2] = { -1e30f, -1e30f };
    float lrow[2] = { 0.f, 0.f };

    int qr0 = qb + warp*16 + g;
    int qm0 = (qr0 < NN) ? qr0 : NN-1;
    int qm1 = (qr0+8 < NN) ? qr0+8 : NN-1;
    const float* mk0 = mask ? (mask + ((long)(b*MM + qm0))*NN) : (const float*)0;
    const float* mk1 = mask ? (mask + ((long)(b*MM + qm1))*NN) : (const float*)0;

    #pragma unroll 1
    for (int c = 0; c < 9; c++) {
        float s[8][4];
        // ---- S = Q K^T (3-pass hi/lo) ----
        #pragma unroll
        for (int t = 0; t < 8; t++) {
            uint32_t ka = sb + (uint32_t)((c*64 + t*8 + br)*48 + bk*16);
            uint32_t bh[2], bl[2];
            LDM2(bh[0], bh[1], ka);
            LDM2(bl[0], bl[1], ka + KLO_B);
            s[t][0]=0.f; s[t][1]=0.f; s[t][2]=0.f; s[t][3]=0.f;
            MMA16816(s[t], Qh, bh);
            MMA16816(s[t], Qh, bl);
            MMA16816(s[t], Ql, bh);
        }
        // ---- scale + mask + validity + row max ----
        float mx0 = -1e30f, mx1 = -1e30f;
        #pragma unroll
        for (int t = 0; t < 8; t++) {
            if (c < 8 || t == 0) {
                s[t][0]*=0.25f; s[t][1]*=0.25f; s[t][2]*=0.25f; s[t][3]*=0.25f;
                if (mask) {
                    int j = c*64 + t*8 + (lane&3)*2;
                    float2 m0 = *(const float2*)(mk0 + j);
                    float2 m1 = *(const float2*)(mk1 + j);
                    s[t][0]+=m0.x; s[t][1]+=m0.y; s[t][2]+=m1.x; s[t][3]+=m1.y;
                }
            } else {
                s[t][0]=-1e30f; s[t][1]=-1e30f; s[t][2]=-1e30f; s[t][3]=-1e30f;
            }
            mx0 = fmaxf(mx0, fmaxf(s[t][0], s[t][1]));
            mx1 = fmaxf(mx1, fmaxf(s[t][2], s[t][3]));
        }
        mx0 = fmaxf(mx0, __shfl_xor_sync(FULL, mx0, 1));
        mx0 = fmaxf(mx0, __shfl_xor_sync(FULL, mx0, 2));
        mx1 = fmaxf(mx1, __shfl_xor_sync(FULL, mx1, 1));
        mx1 = fmaxf(mx1, __shfl_xor_sync(FULL, mx1, 2));
        float mn0 = fmaxf(mrow[0], mx0), mn1 = fmaxf(mrow[1], mx1);
        float f0 = __expf(mrow[0] - mn0), f1 = __expf(mrow[1] - mn1);
        mrow[0] = mn0; mrow[1] = mn1;
        // ---- exp + row sums ----
        float rs0 = 0.f, rs1 = 0.f;
        #pragma unroll
        for (int t = 0; t < 8; t++) {
            s[t][0] = __expf(s[t][0] - mn0);
            s[t][1] = __expf(s[t][1] - mn0);
            s[t][2] = __expf(s[t][2] - mn1);
            s[t][3] = __expf(s[t][3] - mn1);
            rs0 += s[t][0] + s[t][1];
            rs1 += s[t][2] + s[t][3];
        }
        rs0 += __shfl_xor_sync(FULL, rs0, 1); rs0 += __shfl_xor_sync(FULL, rs0, 2);
        rs1 += __shfl_xor_sync(FULL, rs1, 1); rs1 += __shfl_xor_sync(FULL, rs1, 2);
        lrow[0] = lrow[0]*f0 + rs0;
        lrow[1] = lrow[1]*f1 + rs1;
        #pragma unroll
        for (int n = 0; n < 2; n++) {
            o[n][0]*=f0; o[n][1]*=f0; o[n][2]*=f1; o[n][3]*=f1;
        }
        // ---- P @ V (3-pass hi/lo); C-frags repack as A-frags ----
        #pragma unroll
        for (int ss = 0; ss < 4; ss++) {
            uint32_t pah[4], pal[4];
            cvtpk(s[2*ss][0],   s[2*ss][1],   pah[0], pal[0]);
            cvtpk(s[2*ss][2],   s[2*ss][3],   pah[1], pal[1]);
            cvtpk(s[2*ss+1][0], s[2*ss+1][1], pah[2], pal[2]);
            cvtpk(s[2*ss+1][2], s[2*ss+1][3], pah[3], pal[3]);
            #pragma unroll
            for (int n = 0; n < 2; n++) {
                uint32_t va = sb + VHI_B +
                    (uint32_t)((n*8 + br)*1168 + (c*64 + ss*16)*2 + bk*16);
                uint32_t vh[2], vl[2];
                LDM2(vh[0], vh[1], va);
                LDM2(vl[0], vl[1], va + VLO_B);
                MMA16816(o[n], pah, vh);
                MMA16816(o[n], pah, vl);
                MMA16816(o[n], pal, vh);
            }
        }
    }

    // ---- finalize + store bf16 hi/lo ----
    float i0 = 1.f / lrow[0], i1 = 1.f / lrow[1];
    #pragma unroll
    for (int n = 0; n < 2; n++) {
        int d = h*DKK + n*8 + (lane&3)*2;
        if (qr0 < NN) {
            uint32_t hp, lp;
            cvtpk(o[n][0]*i0, o[n][1]*i0, hp, lp);
            long off = ((long)(b*NN + qr0))*EE + d;
            *(uint32_t*)(Oh + off) = hp;
            *(uint32_t*)(Ol + off) = lp;
        }
        if (qr0 + 8 < NN) {
            uint32_t hp, lp;
            cvtpk(o[n][2]*i1, o[n][3]*i1, hp, lp);
            long off = ((long)(b*NN + qr0 + 8))*EE + d;
            *(uint32_t*)(Oh + off) = hp;
            *(uint32_t*)(Ol + off) = lp;
        }
    }
}

// ---------------- instance norm ----------------
__global__ void inorm_stats(const float* __restrict__ Y)
{
    int b = blockIdx.x, ch = blockIdx.y, e = threadIdx.x;
    float s1 = 0.f, s2 = 0.f;
    for (int n = ch; n < NN; n += 8) {
        float v = Y[((long)(b*NN + n))*EE + e];
        s1 += v; s2 += v*v;
    }
    int idx = (b*8 + ch)*EE + e;
    g_part[idx*2]   = s1;
    g_part[idx*2+1] = s2;
}
__global__ void inorm_fin()
{
    int b = blockIdx.x, e = threadIdx.x;
    float s1 = 0.f, s2 = 0.f;
    for (int c = 0; c < 8; c++) {
        int idx = (b*8 + c)*EE + e;
        s1 += g_part[idx*2]; s2 += g_part[idx*2+1];
    }
    float mean = s1 / (float)NN;
    float var  = s2 / (float)NN - mean*mean;
    g_stats[(b*EE+e)*2]   = mean;
    g_stats[(b*EE+e)*2+1] = rsqrtf(var + 1e-5f);
}
__global__ void inorm_apply(const float* __restrict__ Y, const float* __restrict__ gg,
                            const float* __restrict__ bt, float* __restrict__ Xo,
                            bf16* __restrict__ Xh, bf16* __restrict__ Xl)
{
    int idx = blockIdx.x * blockDim.x + threadIdx.x;
    if (idx >= BB*NN*EE) return;
    int e = idx % EE;
    int b = idx / (NN*EE);
    float mean = g_stats[(b*EE+e)*2];
    float istd = g_stats[(b*EE+e)*2+1];
    float v = (Y[idx] - mean) * istd * gg[e] + bt[e];
    Xo[idx] = v;
    split1(v, Xh + idx, Xl + idx);
}

// ---------------- decoder helpers ----------------
__global__ void encmean_kernel()
{
    int b = blockIdx.x, e = threadIdx.x;
    float s = 0.f;
    for (int n = 0; n < NN; n++) s += g_x[((long)(b*NN + n))*EE + e];
    g_encmean[b*EE + e] = s / (float)NN;
}

__global__ void build_cat(const float* __restrict__ loadv, const int* __restrict__ cur,
                          const int* __restrict__ subn, const int* __restrict__ subl,
                          const int* __restrict__ sel)
{
    int r = blockIdx.x;
    int b = r / MM;
    int e = threadIdx.x;
    int c = cur[r];
    float le = g_x[((long)(b*NN + c))*EE + e];

    int len = subl[r];
    const int* nodes = subn + (long)r*LL;
    float ssum = 0.f; int cnt = 0;
    for (int l = 0; l < LL; l++) {
        int nd = nodes[l];
        if (l < len && nd >= DEPOTN) {
            ssum += g_x[((long)(b*NN + nd))*EE + e];
            cnt++;
        }
    }
    float cntf = (cnt > 0) ? (float)cnt : 1.f;
    float smean = ssum / cntf;

    long bl = (long)r*256, br = (long)r*KRT;
    split1(le,    g_catlh + bl + e,       g_catll + bl + e);
    split1(smean, g_catlh + bl + 128 + e, g_catll + bl + 128 + e);
    split1(le,    g_catrh + br + e,       g_catrl + br + e);
    split1(g_encmean[b*EE + e], g_catrh + br + 128 + e, g_catrl + br + 128 + e);
    if (e == 0) split1(loadv[r], g_catrh + br + 256, g_catrl + br + 256);
    if (e >= 1 && e < 32) { g_catrh[br + 256 + e] = __float2bfloat16(0.f);
                            g_catrl[br + 256 + e] = __float2bfloat16(0.f); }
    if (e == 0) {
        int s2 = sel[(long)r*4 + 2];
        g_flag[r] = (s2 >= DEPOTN && c < DEPOTN) ? 1.f : 0.f;
    }
}

__global__ void blend_kernel()
{
    int idx = blockIdx.x * blockDim.x + threadIdx.x;
    if (idx >= BB*MM*EE) return;
    int r = idx / EE;
    float f = g_flag[r];
    g_fq[idx] = f * g_qloc[idx] + (1.f - f) * g_qrout[idx];
}

// ---------------- final tanh-clip + mask + softmax ----------------
__global__ void final_kernel(const float* __restrict__ mask, float* __restrict__ out)
{
    int r = blockIdx.x;
    int tid = threadIdx.x;
    __shared__ float buf[NN];
    __shared__ float red[256];
    const float* sn = g_sn + (long)r*NN;
    const float* mk = mask + (long)r*NN;
    const float invs = 0.08838834764831845f;

    float lm = -1e30f;
    for (int j = tid; j < NN; j += 256) {
        float v = 10.f * tanhf(sn[j] * invs) + mk[j];
        buf[j] = v;
        lm = fmaxf(lm, v);
    }
    red[tid] = lm; __syncthreads();
    for (int off = 128; off > 0; off >>= 1) {
        if (tid < off) red[tid] = fmaxf(red[tid], red[tid+off]);
        __syncthreads();
    }
    float mx = red[0]; __syncthreads();

    float ls = 0.f;
    for (int j = tid; j < NN; j += 256) {
        float e0 = __expf(buf[j] - mx);
        buf[j] = e0; ls += e0;
    }
    red[tid] = ls; __syncthreads();
    for (int off = 128; off > 0; off >>= 1) {
        if (tid < off) red[tid] += red[tid+off];
        __syncthreads();
    }
    float inv = 1.f / red[0];
    for (int j = tid; j < NN; j += 256)
        out[(long)r*NN + j] = buf[j] * inv;
}

// ---------------- host ----------------
#define GEMM_SMEM 81920

static void launch_tc(const bf16* Ah, const bf16* Al, const bf16* Bh, const bf16* Bl,
                      const float* bias, const float* resid,
                      float* C, bf16* Ch, bf16* Cl,
                      int R, int K, int Cout, int batch,
                      long sA, long sB, long sC, int relu)
{
    dim3 grid((R + 127) / 128, (Cout + 127) / 128, batch);
    gemm_tc2<<<grid, 256, GEMM_SMEM>>>(Ah, Al, Bh, Bl, bias, resid, C, Ch, Cl,
                                       R, K, Cout, sA, sB, sC, relu);
}

#define SYM(p, s) cudaGetSymbolAddress((void**)&p, s)

extern "C" void kernel_launch(void* const* d_in, const int* in_sizes, int n_in,
                              void* d_out, int out_size)
{
    const float* depot  = (const float*)d_in[0];
    const float* cust   = (const float*)d_in[1];
    const float* mask   = (const float*)d_in[2];
    const float* loadv  = (const float*)d_in[3];
    const int*   cur    = (const int*)d_in[4];
    const int*   subn   = (const int*)d_in[5];
    const int*   subl   = (const int*)d_in[6];
    const int*   sel    = (const int*)d_in[7];
    const float* edW    = (const float*)d_in[8];
    const float* edb    = (const float*)d_in[9];
    const float* ecW    = (const float*)d_in[10];
    const float* ecb    = (const float*)d_in[11];
    const float* Wq     = (const float*)d_in[12];
    const float* Wk     = (const float*)d_in[13];
    const float* Wv     = (const float*)d_in[14];
    const float* Wc     = (const float*)d_in[15];
    const float* Wcb    = (const float*)d_in[16];
    const float* n1g    = (const float*)d_in[17];
    const float* n1b    = (const float*)d_in[18];
    const float* fW1    = (const float*)d_in[19];
    const float* fb1    = (const float*)d_in[20];
    const float* fW2    = (const float*)d_in[21];
    const float* fb2    = (const float*)d_in[22];
    const float* n2g    = (const float*)d_in[23];
    const float* n2b    = (const float*)d_in[24];
    const float* dWqloc = (const float*)d_in[25];
    const float* dWqrt  = (const float*)d_in[26];
    const float* dWk    = (const float*)d_in[27];
    const float* dWv    = (const float*)d_in[28];
    const float* dWc    = (const float*)d_in[29];
    const float* dWcb   = (const float*)d_in[30];
    float* out = (float*)d_out;

    float *px, *pqkv, *py, *px1, *pkvd, *pqloc, *pqrout, *pfq, *psn;
    SYM(px, g_x); SYM(pqkv, g_qkv); SYM(py, g_y); SYM(px1, g_x1);
    SYM(pkvd, g_kvd); SYM(pqloc, g_qloc); SYM(pqrout, g_qrout);
    SYM(pfq, g_fq); SYM(psn, g_sn);

    bf16 *pxh,*pxl, *px1h,*px1l, *pmhh,*pmhl, *pffhh,*pffhl, *pattnh,*pattnl;
    bf16 *pscoreh,*pscorel, *pcatlh,*pcatll, *pcatrh,*pcatrl;
    bf16 *pwqkvh,*pwqkvl, *pwch,*pwcl, *pf1h,*pf1l, *pf2h,*pf2l;
    bf16 *pwkvh,*pwkvl, *pwqlh,*pwqll, *pwpah,*pwpal, *pwdch,*pwdcl;
    SYM(pxh, g_xh); SYM(pxl, g_xl); SYM(px1h, g_x1h); SYM(px1l, g_x1l);
    SYM(pmhh, g_mhh); SYM(pmhl, g_mhl); SYM(pffhh, g_ffhh); SYM(pffhl, g_ffhl);
    SYM(pattnh, g_attnh); SYM(pattnl, g_attnl);
    SYM(pscoreh, g_scoreh); SYM(pscorel, g_scorel);
    SYM(pcatlh, g_catlh); SYM(pcatll, g_catll); SYM(pcatrh, g_catrh); SYM(pcatrl, g_catrl);
    SYM(pwqkvh, g_wqkvh); SYM(pwqkvl, g_wqkvl); SYM(pwch, g_wch); SYM(pwcl, g_wcl);
    SYM(pf1h, g_f1h); SYM(pf1l, g_f1l); SYM(pf2h, g_f2h); SYM(pf2l, g_f2l);
    SYM(pwkvh, g_wkvh); SYM(pwkvl, g_wkvl); SYM(pwqlh, g_wqlh); SYM(pwqll, g_wqll);
    SYM(pwpah, g_wpah); SYM(pwpal, g_wpal); SYM(pwdch, g_wdch); SYM(pwdcl, g_wdcl);

    const int R = BB * NN;
    const int TOT = BB * NN * EE;
    const int NQT = (NN + 127) / 128;
    static int smem_set = 0;
    if (!smem_set) {
        cudaFuncSetAttribute(attn_mma, cudaFuncAttributeMaxDynamicSharedMemorySize, ATTN2_SMEM);
        cudaFuncSetAttribute(gemm_tc2, cudaFuncAttributeMaxDynamicSharedMemorySize, GEMM_SMEM);
        smem_set = 1;
    }

    // ---- one-time converts ----
    embed_kernel<<<(TOT + 255)/256, 256>>>(depot, cust, edW, edb, ecW, ecb);
    pack_w<<<(NLL*384*EE + 256*EE + 255)/256, 256>>>(Wq, Wk, Wv, dWk, dWv);
    padw_kernel<<<(EE*KRT + 255)/256, 256>>>(dWqrt);
    cvt_split<<<(NLL*EE*EE + 255)/256, 256>>>(Wc,  pwch, pwcl, NLL*EE*EE);
    cvt_split<<<(NLL*FFHH*EE + 255)/256, 256>>>(fW1, pf1h, pf1l, NLL*FFHH*EE);
    cvt_split<<<(NLL*EE*FFHH + 255)/256, 256>>>(fW2, pf2h, pf2l, NLL*EE*FFHH);
    cvt_split<<<(EE*256 + 255)/256, 256>>>(dWqloc, pwqlh, pwqll, EE*256);
    cvt_split<<<(EE*EE + 255)/256, 256>>>(dWc, pwdch, pwdcl, EE*EE);

    // ---- encoder ----
    for (int i = 0; i < NLL; i++) {
        launch_tc(pxh, pxl, pwqkvh + (long)i*384*EE, pwqkvl + (long)i*384*EE,
                  0, 0, pqkv, 0, 0, R, EE, 384, 1, 0, 0, 0, 0);
        attn_mma<<<dim3(NQT, HH, BB), 256, ATTN2_SMEM>>>(pqkv, 384, pqkv + 128, 384,
                                                         pqkv + 256, 384, (const float*)0,
                                                         pmhh, pmhl);
        launch_tc(pmhh, pmhl, pwch + (long)i*EE*EE, pwcl + (long)i*EE*EE,
                  Wcb + (long)i*EE, px, py, 0, 0, R, EE, EE, 1, 0, 0, 0, 0);
        inorm_stats<<<dim3(BB, 8), EE>>>(py);
        inorm_fin<<<BB, EE>>>();
        inorm_apply<<<(TOT + 255)/256, 256>>>(py, n1g + (long)i*EE, n1b + (long)i*EE,
                                              px1, px1h, px1l);
        launch_tc(px1h, px1l, pf1h + (long)i*FFHH*EE, pf1l + (long)i*FFHH*EE,
                  fb1 + (long)i*FFHH, 0, 0, pffhh, pffhl, R, EE, FFHH, 1, 0, 0, 0, 1);
        launch_tc(pffhh, pffhl, pf2h + (long)i*EE*FFHH, pf2l + (long)i*EE*FFHH,
                  fb2 + (long)i*EE, px1, py, 0, 0, R, FFHH, EE, 1, 0, 0, 0, 0);
        inorm_stats<<<dim3(BB, 8), EE>>>(py);
        inorm_fin<<<BB, EE>>>();
        inorm_apply<<<(TOT + 255)/256, 256>>>(py, n2g + (long)i*EE, n2b + (long)i*EE,
                                              px, pxh, pxl);
    }

    // ---- decoder ----
    launch_tc(pxh, pxl, pwkvh, pwkvl, 0, 0, pkvd, 0, 0, R, EE, 256, 1, 0, 0, 0, 0);
    encmean_kernel<<<BB, EE>>>();
    build_cat<<<BB*MM, EE>>>(loadv, cur, subn, subl, sel);
    launch_tc(pcatlh, pcatll, pwqlh, pwqll, 0, 0, pqloc, 0, 0, R, 256, EE, 1, 0, 0, 0, 0);
    launch_tc(pcatrh, pcatrl, pwpah, pwpal, 0, 0, pqrout, 0, 0, R, KRT, EE, 1, 0, 0, 0, 0);
    blend_kernel<<<(BB*MM*EE + 255)/256, 256>>>();
    attn_mma<<<dim3(NQT, HH, BB), 256, ATTN2_SMEM>>>(pfq, 128, pkvd, 256, pkvd + 128, 256,
                                                     mask, pattnh, pattnl);
    launch_tc(pattnh, pattnl, pwdch, pwdcl, dWcb, 0, 0, pscoreh, pscorel,
              R, EE, EE, 1, 0, 0, 0, 0);
    launch_tc(pscoreh, pscorel, pxh, pxl, 0, 0, psn, 0, 0, MM, EE, NN, BB,
              (long)MM*EE, (long)NN*EE, (long)MM*NN, 0);
    final_kernel<<<BB*MM, 256>>>(mask, out);
}

// round 8
// speedup vs baseline: 1.3769x; 1.0085x over previous
#include <cuda_runtime.h>
#include <cuda_bf16.h>
#include <math.h>
#include <stdint.h>

#define BB 32
#define NN 520
#define DEPOTN 20
#define CUSTN 500
#define EE 128
#define HH 8
#define DKK 16
#define FFHH 512
#define NLL 6
#define MM 520
#define LL 40
#define KRT 288

typedef __nv_bfloat16 bf16;

// ---------------- fp32 scratch ----------------
__device__ __align__(16) float g_x   [BB*NN*EE];
__device__ __align__(16) float g_qkv [BB*NN*384];
__device__ __align__(16) float g_y   [BB*NN*EE];
__device__ __align__(16) float g_x1  [BB*NN*EE];
__device__ __align__(16) float g_stats[BB*EE*2];
__device__ __align__(16) float g_kvd [BB*NN*256];
__device__ __align__(16) float g_encmean[BB*EE];
__device__ __align__(16) float g_qloc [BB*MM*EE];
__device__ __align__(16) float g_qrout[BB*MM*EE];
__device__ __align__(16) float g_flag [BB*MM];
__device__ __align__(16) float g_sn   [BB*MM*NN];

// ---------------- bf16 hi/lo scratch ----------------
__device__ __align__(16) bf16 g_xh[BB*NN*EE],      g_xl[BB*NN*EE];
__device__ __align__(16) bf16 g_x1h[BB*NN*EE],     g_x1l[BB*NN*EE];
__device__ __align__(16) bf16 g_mhh[BB*NN*EE],     g_mhl[BB*NN*EE];
__device__ __align__(16) bf16 g_ffhh[BB*NN*FFHH],  g_ffhl[BB*NN*FFHH];
__device__ __align__(16) bf16 g_attnh[BB*MM*EE],   g_attnl[BB*MM*EE];
__device__ __align__(16) bf16 g_scoreh[BB*MM*EE],  g_scorel[BB*MM*EE];
__device__ __align__(16) bf16 g_catlh[BB*MM*256],  g_catll[BB*MM*256];
__device__ __align__(16) bf16 g_catrh[BB*MM*KRT],  g_catrl[BB*MM*KRT];
__device__ __align__(16) bf16 g_wqkvh[NLL*384*EE], g_wqkvl[NLL*384*EE];
__device__ __align__(16) bf16 g_wch[NLL*EE*EE],    g_wcl[NLL*EE*EE];
__device__ __align__(16) bf16 g_f1h[NLL*FFHH*EE],  g_f1l[NLL*FFHH*EE];
__device__ __align__(16) bf16 g_f2h[NLL*EE*FFHH],  g_f2l[NLL*EE*FFHH];
__device__ __align__(16) bf16 g_wkvh[256*EE],      g_wkvl[256*EE];
__device__ __align__(16) bf16 g_wqlh[EE*256],      g_wqll[EE*256];
__device__ __align__(16) bf16 g_wpah[EE*KRT],      g_wpal[EE*KRT];
__device__ __align__(16) bf16 g_wdch[EE*EE],       g_wdcl[EE*EE];

__device__ __forceinline__ void split1(float x, bf16* h, bf16* l)
{
    bf16 hv = __float2bfloat16(x);
    *h = hv;
    *l = __float2bfloat16(x - __bfloat162float(hv));
}

__device__ __forceinline__ void cvtpk(float x0, float x1, uint32_t& h, uint32_t& l)
{
    bf16 h0 = __float2bfloat16(x0), h1 = __float2bfloat16(x1);
    float l0 = x0 - __bfloat162float(h0), l1 = x1 - __bfloat162float(h1);
    h = ((uint32_t)__bfloat16_as_ushort(h1) << 16) | __bfloat16_as_ushort(h0);
    bf16 g0 = __float2bfloat16(l0), g1 = __float2bfloat16(l1);
    l = ((uint32_t)__bfloat16_as_ushort(g1) << 16) | __bfloat16_as_ushort(g0);
}

// ---------------- generic fp32 -> hi/lo ----------------
__global__ void cvt_split(const float* __restrict__ s, bf16* __restrict__ h,
                          bf16* __restrict__ l, int n)
{
    int i = blockIdx.x * blockDim.x + threadIdx.x;
    if (i < n) split1(s[i], h + i, l + i);
}

// ---------------- embedding ----------------
__global__ void embed_kernel(const float* __restrict__ dep, const float* __restrict__ cus,
                             const float* __restrict__ Wd, const float* __restrict__ bd,
                             const float* __restrict__ Wc, const float* __restrict__ bc)
{
    int idx = blockIdx.x * blockDim.x + threadIdx.x;
    if (idx >= BB*NN*EE) return;
    int e = idx % EE;
    int n = (idx / EE) % NN;
    int b = idx / (EE*NN);
    float acc;
    if (n < DEPOTN) {
        const float* f = dep + ((long)b*DEPOTN + n) * 4;
        acc = bd[e];
        #pragma unroll
        for (int j = 0; j < 4; j++) acc += f[j] * Wd[e*4 + j];
    } else {
        const float* f = cus + ((long)b*CUSTN + (n - DEPOTN)) * 3;
        acc = bc[e];
        #pragma unroll
        for (int j = 0; j < 3; j++) acc += f[j] * Wc[e*3 + j];
    }
    g_x[idx] = acc;
    split1(acc, g_xh + idx, g_xl + idx);
}

// ---------------- weight packing ----------------
__global__ void pack_w(const float* __restrict__ Wq, const float* __restrict__ Wk,
                       const float* __restrict__ Wv, const float* __restrict__ dWk,
                       const float* __restrict__ dWv)
{
    int idx = blockIdx.x * blockDim.x + threadIdx.x;
    const int tot1 = NLL*384*EE;
    if (idx < tot1) {
        int col = idx % EE;
        int row = (idx / EE) % 384;
        int l   = idx / (EE*384);
        float v;
        if (row < 128)      v = Wq[((long)l*EE + row)*EE + col];
        else if (row < 256) v = Wk[((long)l*EE + row-128)*EE + col];
        else                v = Wv[((long)l*EE + row-256)*EE + col];
        split1(v, g_wqkvh + idx, g_wqkvl + idx);
    } else {
        int j = idx - tot1;
        if (j < 256*EE) {
            int col = j % EE;
            int row = j / EE;
            float v = (row < 128) ? dWk[row*EE + col] : dWv[(row-128)*EE + col];
            split1(v, g_wkvh + j, g_wkvl + j);
        }
    }
}

__global__ void padw_kernel(const float* __restrict__ Wr)
{
    int idx = blockIdx.x * blockDim.x + threadIdx.x;
    if (idx >= EE*KRT) return;
    int rr = idx / KRT, cc = idx % KRT;
    float v = (cc < 257) ? Wr[rr*257 + cc] : 0.f;
    split1(v, g_wpah + idx, g_wpal + idx);
}

// ---------------- MMA primitives ----------------
#define LDM4(r0,r1,r2,r3,addr) \
    asm volatile("ldmatrix.sync.aligned.m8n8.x4.shared.b16 {%0,%1,%2,%3},[%4];" \
                 : "=r"(r0),"=r"(r1),"=r"(r2),"=r"(r3) : "r"(addr))
#define LDM2(r0,r1,addr) \
    asm volatile("ldmatrix.sync.aligned.m8n8.x2.shared.b16 {%0,%1},[%2];" \
                 : "=r"(r0),"=r"(r1) : "r"(addr))
#define MMA16816(c,a,b) \
    asm volatile("mma.sync.aligned.m16n8k16.row.col.f32.bf16.bf16.f32 " \
                 "{%0,%1,%2,%3},{%4,%5,%6,%7},{%8,%9},{%0,%1,%2,%3};" \
                 : "+f"((c)[0]),"+f"((c)[1]),"+f"((c)[2]),"+f"((c)[3]) \
                 : "r"((a)[0]),"r"((a)[1]),"r"((a)[2]),"r"((a)[3]), "r"((b)[0]),"r"((b)[1]))

// ---------------- TC GEMM v2 (proven) ----------------
#define MAT 10240
#define STAGE 40960

__global__ __launch_bounds__(256, 2)
void gemm_tc2(const bf16* __restrict__ Ahi, const bf16* __restrict__ Alo,
              const bf16* __restrict__ Bhi, const bf16* __restrict__ Blo,
              const float* __restrict__ bias, const float* __restrict__ resid,
              float* __restrict__ C, bf16* __restrict__ Chi, bf16* __restrict__ Clo,
              int R, int K, int Cout, long sA, long sB, long sC, int relu)
{
    int bz = blockIdx.z;
    Ahi += (long)bz*sA; Alo += (long)bz*sA;
    Bhi += (long)bz*sB; Blo += (long)bz*sB;
    if (C)     C   += (long)bz*sC;
    if (Chi) { Chi += (long)bz*sC; Clo += (long)bz*sC; }
    if (resid) resid += (long)bz*sC;

    extern __shared__ bf16 smb[];
    uint32_t sb = (uint32_t)__cvta_generic_to_shared(smb);

    int tid = threadIdx.x, lane = tid & 31, warp = tid >> 5;
    int wm = warp >> 2, wn = warp & 3;
    int rowBase = blockIdx.x * 128, colBase = blockIdx.y * 128;

    float c[4][4][4];
    #pragma unroll
    for (int i = 0; i < 4; i++)
        #pragma unroll
        for (int j = 0; j < 4; j++)
            { c[i][j][0]=0.f; c[i][j][1]=0.f; c[i][j][2]=0.f; c[i][j][3]=0.f; }

    const bf16* bases[4] = { Ahi, Alo, Bhi, Blo };
    int nk = K >> 5;

    #define FILL(st, kt) do { \
        int k0 = (kt) << 5; \
        _Pragma("unroll") \
        for (int t = 0; t < 8; t++) { \
            int o = tid + t*256; \
            int m = o >> 9, r = (o >> 2) & 127, seg = o & 3; \
            int gr = ((m < 2) ? rowBase : colBase) + r; \
            int lim = (m < 2) ? R : Cout; \
            long grc = (gr < lim) ? gr : 0; \
            const bf16* src = bases[m] + grc*K + k0 + seg*8; \
            uint32_t dst = sb + (st)*STAGE + m*MAT + r*80 + seg*16; \
            int nbytes = (gr < lim) ? 16 : 0; \
            asm volatile("cp.async.ca.shared.global [%0],[%1],16,%2;" \
                         :: "r"(dst), "l"(src), "r"(nbytes)); \
        } \
        asm volatile("cp.async.commit_group;"); \
    } while (0)

    FILL(0, 0);

    int ar = lane & 15, ak = (lane >> 4);
    int br = lane & 7,  bk = (lane >> 3) & 1;

    for (int kt = 0; kt < nk; kt++) {
        int st = kt & 1;
        if (kt + 1 < nk) {
            FILL(st ^ 1, kt + 1);
            asm volatile("cp.async.wait_group 1;");
        } else {
            asm volatile("cp.async.wait_group 0;");
        }
        __syncthreads();

        uint32_t aOff = sb + st*STAGE;
        uint32_t bOff = aOff + 2*MAT;
        #pragma unroll
        for (int ks = 0; ks < 2; ks++) {
            uint32_t Ah[4][4], Al[4][4];
            #pragma unroll
            for (int i = 0; i < 4; i++) {
                uint32_t ad = aOff + (uint32_t)((wm*64 + i*16 + ar)*80 + ak*16 + ks*32);
                LDM4(Ah[i][0], Ah[i][1], Ah[i][2], Ah[i][3], ad);
                LDM4(Al[i][0], Al[i][1], Al[i][2], Al[i][3], ad + MAT);
            }
            #pragma unroll
            for (int j = 0; j < 4; j++) {
                uint32_t bd = bOff + (uint32_t)((wn*32 + j*8 + br)*80 + bk*16 + ks*32);
                uint32_t Bh[2], Bl[2];
                LDM2(Bh[0], Bh[1], bd);
                LDM2(Bl[0], Bl[1], bd + MAT);
                #pragma unroll
                for (int i = 0; i < 4; i++) {
                    MMA16816(c[i][j], Ah[i], Bh);
                    MMA16816(c[i][j], Ah[i], Bl);
                    MMA16816(c[i][j], Al[i], Bh);
                }
            }
        }
        __syncthreads();
    }

    int gid = lane >> 2, tig = lane & 3;
    #pragma unroll
    for (int i = 0; i < 4; i++) {
        int rbase = rowBase + wm*64 + i*16 + gid;
        #pragma unroll
        for (int j = 0; j < 4; j++) {
            int c0 = colBase + wn*32 + j*8 + tig*2;
            if (c0 >= Cout) continue;
            #pragma unroll
            for (int hh = 0; hh < 2; hh++) {
                int row = rbase + hh*8;
                if (row >= R) continue;
                float v0 = c[i][j][2*hh], v1 = c[i][j][2*hh+1];
                if (bias)  { v0 += bias[c0]; v1 += bias[c0+1]; }
                if (resid) {
                    float2 rv = *(const float2*)(resid + (long)row*Cout + c0);
                    v0 += rv.x; v1 += rv.y;
                }
                if (relu) { v0 = fmaxf(v0, 0.f); v1 = fmaxf(v1, 0.f); }
                if (C) *(float2*)(C + (long)row*Cout + c0) = make_float2(v0, v1);
                if (Chi) {
                    uint32_t hp, lp;
                    cvtpk(v0, v1, hp, lp);
                    *(uint32_t*)(Chi + (long)row*Cout + c0) = hp;
                    *(uint32_t*)(Clo + (long)row*Cout + c0) = lp;
                }
            }
        }
    }
}

// ---------------- attention via MMA (FA2-style, hi/lo bf16) ----------------
// block = (q-tile of 128, head, batch); 8 warps, warp = m16 queries.
// Optional Q2/flagv: staged Q = flag*Q + (1-flag)*Q2 (decoder blend fused).
#define KPAD 576
#define KLO_B  27648
#define VHI_B  55296
#define VLO_B  18688
#define QHI_B  92672
#define QLO_B  6144
#define ATTN2_SMEM 104960

__global__ __launch_bounds__(256)
void attn_mma(const float* __restrict__ Q, const float* __restrict__ Q2,
              const float* __restrict__ flagv, int ldq,
              const float* __restrict__ Kt, int ldk,
              const float* __restrict__ Vt, int ldv,
              const float* __restrict__ mask,
              bf16* __restrict__ Oh, bf16* __restrict__ Ol)
{
    int qb = blockIdx.x * 128;
    int h = blockIdx.y, b = blockIdx.z;
    extern __shared__ bf16 sm2[];
    uint32_t sb = (uint32_t)__cvta_generic_to_shared(sm2);
    int tid = threadIdx.x;

    const int KHI_E = 0, KLO_E = 13824, VHI_E = 27648, VLO_E = 36992;
    const int QHI_E = 46336, QLO_E = 49408;

    const float* Kg = Kt + (long)b*NN*ldk + h*DKK;
    const float* Vg = Vt + (long)b*NN*ldv + h*DKK;
    for (int i = tid; i < KPAD*DKK; i += 256) {
        int key = i >> 4, d = i & 15;
        float kv = (key < NN) ? Kg[(long)key*ldk + d] : 0.f;
        float vv = (key < NN) ? Vg[(long)key*ldv + d] : 0.f;
        bf16 kh = __float2bfloat16(kv);
        bf16 kl = __float2bfloat16(kv - __bfloat162float(kh));
        bf16 vh = __float2bfloat16(vv);
        bf16 vl = __float2bfloat16(vv - __bfloat162float(vh));
        sm2[KHI_E + key*24 + d] = kh;
        sm2[KLO_E + key*24 + d] = kl;
        sm2[VHI_E + d*584 + key] = vh;
        sm2[VLO_E + d*584 + key] = vl;
    }
    const float* Qg = Q + (long)b*NN*ldq + h*DKK;
    const float* Qg2 = Q2 ? (Q2 + (long)b*NN*ldq + h*DKK) : (const float*)0;
    for (int i = tid; i < 128*DKK; i += 256) {
        int row = i >> 4, d = i & 15;
        int q = qb + row;
        float qv = 0.f;
        if (q < NN) {
            qv = Qg[(long)q*ldq + d];
            if (Qg2) {
                float f = flagv[(long)b*MM + q];
                qv = f*qv + (1.f - f)*Qg2[(long)q*ldq + d];
            }
        }
        bf16 qh = __float2bfloat16(qv);
        sm2[QHI_E + row*24 + d] = qh;
        sm2[QLO_E + row*24 + d] = __float2bfloat16(qv - __bfloat162float(qh));
    }
    __syncthreads();

    int warp = tid >> 5, lane = tid & 31;
    int g = lane >> 2;
    int ar = lane & 15, ak = lane >> 4;
    int br = lane & 7,  bk = (lane >> 3) & 1;
    const unsigned FULL = 0xffffffffu;

    uint32_t Qh[4], Ql[4];
    {
        uint32_t qa = sb + QHI_B + (uint32_t)((warp*16 + ar)*48 + ak*16);
        LDM4(Qh[0], Qh[1], Qh[2], Qh[3], qa);
        LDM4(Ql[0], Ql[1], Ql[2], Ql[3], qa + QLO_B);
    }

    float o[2][4];
    #pragma unroll
    for (int n = 0; n < 2; n++) { o[n][0]=0.f; o[n][1]=0.f; o[n][2]=0.f; o[n][3]=0.f; }
    float mrow[2] = { -1e30f, -1e30f };
    float lrow[2] = { 0.f, 0.f };

    int qr0 = qb + warp*16 + g;
    int qm0 = (qr0 < NN) ? qr0 : NN-1;
    int qm1 = (qr0+8 < NN) ? qr0+8 : NN-1;
    const float* mk0 = mask ? (mask + ((long)(b*MM + qm0))*NN) : (const float*)0;
    const float* mk1 = mask ? (mask + ((long)(b*MM + qm1))*NN) : (const float*)0;

    #pragma unroll 1
    for (int c = 0; c < 9; c++) {
        float s[8][4];
        #pragma unroll
        for (int t = 0; t < 8; t++) {
            uint32_t ka = sb + (uint32_t)((c*64 + t*8 + br)*48 + bk*16);
            uint32_t bh[2], bl[2];
            LDM2(bh[0], bh[1], ka);
            LDM2(bl[0], bl[1], ka + KLO_B);
            s[t][0]=0.f; s[t][1]=0.f; s[t][2]=0.f; s[t][3]=0.f;
            MMA16816(s[t], Qh, bh);
            MMA16816(s[t], Qh, bl);
            MMA16816(s[t], Ql, bh);
        }
        float mx0 = -1e30f, mx1 = -1e30f;
        #pragma unroll
        for (int t = 0; t < 8; t++) {
            if (c < 8 || t == 0) {
                s[t][0]*=0.25f; s[t][1]*=0.25f; s[t][2]*=0.25f; s[t][3]*=0.25f;
                if (mask) {
                    int j = c*64 + t*8 + (lane&3)*2;
                    float2 m0 = *(const float2*)(mk0 + j);
                    float2 m1 = *(const float2*)(mk1 + j);
                    s[t][0]+=m0.x; s[t][1]+=m0.y; s[t][2]+=m1.x; s[t][3]+=m1.y;
                }
            } else {
                s[t][0]=-1e30f; s[t][1]=-1e30f; s[t][2]=-1e30f; s[t][3]=-1e30f;
            }
            mx0 = fmaxf(mx0, fmaxf(s[t][0], s[t][1]));
            mx1 = fmaxf(mx1, fmaxf(s[t][2], s[t][3]));
        }
        mx0 = fmaxf(mx0, __shfl_xor_sync(FULL, mx0, 1));
        mx0 = fmaxf(mx0, __shfl_xor_sync(FULL, mx0, 2));
        mx1 = fmaxf(mx1, __shfl_xor_sync(FULL, mx1, 1));
        mx1 = fmaxf(mx1, __shfl_xor_sync(FULL, mx1, 2));
        float mn0 = fmaxf(mrow[0], mx0), mn1 = fmaxf(mrow[1], mx1);
        float f0 = __expf(mrow[0] - mn0), f1 = __expf(mrow[1] - mn1);
        mrow[0] = mn0; mrow[1] = mn1;
        float rs0 = 0.f, rs1 = 0.f;
        #pragma unroll
        for (int t = 0; t < 8; t++) {
            s[t][0] = __expf(s[t][0] - mn0);
            s[t][1] = __expf(s[t][1] - mn0);
            s[t][2] = __expf(s[t][2] - mn1);
            s[t][3] = __expf(s[t][3] - mn1);
            rs0 += s[t][0] + s[t][1];
            rs1 += s[t][2] + s[t][3];
        }
        rs0 += __shfl_xor_sync(FULL, rs0, 1); rs0 += __shfl_xor_sync(FULL, rs0, 2);
        rs1 += __shfl_xor_sync(FULL, rs1, 1); rs1 += __shfl_xor_sync(FULL, rs1, 2);
        lrow[0] = lrow[0]*f0 + rs0;
        lrow[1] = lrow[1]*f1 + rs1;
        #pragma unroll
        for (int n = 0; n < 2; n++) {
            o[n][0]*=f0; o[n][1]*=f0; o[n][2]*=f1; o[n][3]*=f1;
        }
        #pragma unroll
        for (int ss = 0; ss < 4; ss++) {
            uint32_t pah[4], pal[4];
            cvtpk(s[2*ss][0],   s[2*ss][1],   pah[0], pal[0]);
            cvtpk(s[2*ss][2],   s[2*ss][3],   pah[1], pal[1]);
            cvtpk(s[2*ss+1][0], s[2*ss+1][1], pah[2], pal[2]);
            cvtpk(s[2*ss+1][2], s[2*ss+1][3], pah[3], pal[3]);
            #pragma unroll
            for (int n = 0; n < 2; n++) {
                uint32_t va = sb + VHI_B +
                    (uint32_t)((n*8 + br)*1168 + (c*64 + ss*16)*2 + bk*16);
                uint32_t vh[2], vl[2];
                LDM2(vh[0], vh[1], va);
                LDM2(vl[0], vl[1], va + VLO_B);
                MMA16816(o[n], pah, vh);
                MMA16816(o[n], pah, vl);
                MMA16816(o[n], pal, vh);
            }
        }
    }

    float i0 = 1.f / lrow[0], i1 = 1.f / lrow[1];
    #pragma unroll
    for (int n = 0; n < 2; n++) {
        int d = h*DKK + n*8 + (lane&3)*2;
        if (qr0 < NN) {
            uint32_t hp, lp;
            cvtpk(o[n][0]*i0, o[n][1]*i0, hp, lp);
            long off = ((long)(b*NN + qr0))*EE + d;
            *(uint32_t*)(Oh + off) = hp;
            *(uint32_t*)(Ol + off) = lp;
        }
        if (qr0 + 8 < NN) {
            uint32_t hp, lp;
            cvtpk(o[n][2]*i1, o[n][3]*i1, hp, lp);
            long off = ((long)(b*NN + qr0 + 8))*EE + d;
            *(uint32_t*)(Oh + off) = hp;
            *(uint32_t*)(Ol + off) = lp;
        }
    }
}

// ---------------- instance norm: fused stats+finalize ----------------
__global__ __launch_bounds__(512)
void inorm_sf(const float* __restrict__ Y)
{
    int b = blockIdx.x;
    int tid = threadIdx.x;
    int e = tid & 127, ch = tid >> 7;     // 4 node-chunks
    float s1 = 0.f, s2 = 0.f;
    for (int n = ch; n < NN; n += 4) {
        float v = Y[((long)(b*NN + n))*EE + e];
        s1 += v; s2 += v*v;
    }
    __shared__ float sh1[512], sh2[512];
    sh1[tid] = s1; sh2[tid] = s2;
    __syncthreads();
    if (tid < 128) {
        float t1 = sh1[tid] + sh1[tid+128] + sh1[tid+256] + sh1[tid+384];
        float t2 = sh2[tid] + sh2[tid+128] + sh2[tid+256] + sh2[tid+384];
        float mean = t1 / (float)NN;
        float var  = t2 / (float)NN - mean*mean;
        g_stats[(b*EE+tid)*2]   = mean;
        g_stats[(b*EE+tid)*2+1] = rsqrtf(var + 1e-5f);
    }
}

__global__ void inorm_apply(const float* __restrict__ Y, const float* __restrict__ gg,
                            const float* __restrict__ bt, float* __restrict__ Xo,
                            bf16* __restrict__ Xh, bf16* __restrict__ Xl)
{
    int idx = blockIdx.x * blockDim.x + threadIdx.x;
    if (idx >= BB*NN*EE) return;
    int e = idx % EE;
    int b = idx / (NN*EE);
    float mean = g_stats[(b*EE+e)*2];
    float istd = g_stats[(b*EE+e)*2+1];
    float v = (Y[idx] - mean) * istd * gg[e] + bt[e];
    Xo[idx] = v;
    split1(v, Xh + idx, Xl + idx);
}

// ---------------- decoder helpers ----------------
__global__ void encmean_kernel()
{
    int b = blockIdx.x, e = threadIdx.x;
    float s = 0.f;
    for (int n = 0; n < NN; n++) s += g_x[((long)(b*NN + n))*EE + e];
    g_encmean[b*EE + e] = s / (float)NN;
}

__global__ void build_cat(const float* __restrict__ loadv, const int* __restrict__ cur,
                          const int* __restrict__ subn, const int* __restrict__ subl,
                          const int* __restrict__ sel)
{
    int r = blockIdx.x;
    int b = r / MM;
    int e = threadIdx.x;
    int c = cur[r];
    float le = g_x[((long)(b*NN + c))*EE + e];

    int len = subl[r];
    const int* nodes = subn + (long)r*LL;
    float ssum = 0.f; int cnt = 0;
    for (int l = 0; l < LL; l++) {
        int nd = nodes[l];
        if (l < len && nd >= DEPOTN) {
            ssum += g_x[((long)(b*NN + nd))*EE + e];
            cnt++;
        }
    }
    float cntf = (cnt > 0) ? (float)cnt : 1.f;
    float smean = ssum / cntf;

    long bl = (long)r*256, br = (long)r*KRT;
    split1(le,    g_catlh + bl + e,       g_catll + bl + e);
    split1(smean, g_catlh + bl + 128 + e, g_catll + bl + 128 + e);
    split1(le,    g_catrh + br + e,       g_catrl + br + e);
    split1(g_encmean[b*EE + e], g_catrh + br + 128 + e, g_catrl + br + 128 + e);
    if (e == 0) split1(loadv[r], g_catrh + br + 256, g_catrl + br + 256);
    if (e >= 1 && e < 32) { g_catrh[br + 256 + e] = __float2bfloat16(0.f);
                            g_catrl[br + 256 + e] = __float2bfloat16(0.f); }
    if (e == 0) {
        int s2 = sel[(long)r*4 + 2];
        g_flag[r] = (s2 >= DEPOTN && c < DEPOTN) ? 1.f : 0.f;
    }
}

// ---------------- final tanh-clip + mask + softmax ----------------
__global__ void final_kernel(const float* __restrict__ mask, float* __restrict__ out)
{
    int r = blockIdx.x;
    int tid = threadIdx.x;
    __shared__ float buf[NN];
    __shared__ float red[256];
    const float* sn = g_sn + (long)r*NN;
    const float* mk = mask + (long)r*NN;
    const float invs = 0.08838834764831845f;

    float lm = -1e30f;
    for (int j = tid; j < NN; j += 256) {
        float v = 10.f * tanhf(sn[j] * invs) + mk[j];
        buf[j] = v;
        lm = fmaxf(lm, v);
    }
    red[tid] = lm; __syncthreads();
    for (int off = 128; off > 0; off >>= 1) {
        if (tid < off) red[tid] = fmaxf(red[tid], red[tid+off]);
        __syncthreads();
    }
    float mx = red[0]; __syncthreads();

    float ls = 0.f;
    for (int j = tid; j < NN; j += 256) {
        float e0 = __expf(buf[j] - mx);
        buf[j] = e0; ls += e0;
    }
    red[tid] = ls; __syncthreads();
    for (int off = 128; off > 0; off >>= 1) {
        if (tid < off) red[tid] += red[tid+off];
        __syncthreads();
    }
    float inv = 1.f / red[0];
    for (int j = tid; j < NN; j += 256)
        out[(long)r*NN + j] = buf[j] * inv;
}

// ---------------- host ----------------
#define GEMM_SMEM 81920

static void launch_tc(const bf16* Ah, const bf16* Al, const bf16* Bh, const bf16* Bl,
                      const float* bias, const float* resid,
                      float* C, bf16* Ch, bf16* Cl,
                      int R, int K, int Cout, int batch,
                      long sA, long sB, long sC, int relu)
{
    dim3 grid((R + 127) / 128, (Cout + 127) / 128, batch);
    gemm_tc2<<<grid, 256, GEMM_SMEM>>>(Ah, Al, Bh, Bl, bias, resid, C, Ch, Cl,
                                       R, K, Cout, sA, sB, sC, relu);
}

#define SYM(p, s) cudaGetSymbolAddress((void**)&p, s)

extern "C" void kernel_launch(void* const* d_in, const int* in_sizes, int n_in,
                              void* d_out, int out_size)
{
    const float* depot  = (const float*)d_in[0];
    const float* cust   = (const float*)d_in[1];
    const float* mask   = (const float*)d_in[2];
    const float* loadv  = (const float*)d_in[3];
    const int*   cur    = (const int*)d_in[4];
    const int*   subn   = (const int*)d_in[5];
    const int*   subl   = (const int*)d_in[6];
    const int*   sel    = (const int*)d_in[7];
    const float* edW    = (const float*)d_in[8];
    const float* edb    = (const float*)d_in[9];
    const float* ecW    = (const float*)d_in[10];
    const float* ecb    = (const float*)d_in[11];
    const float* Wq     = (const float*)d_in[12];
    const float* Wk     = (const float*)d_in[13];
    const float* Wv     = (const float*)d_in[14];
    const float* Wc     = (const float*)d_in[15];
    const float* Wcb    = (const float*)d_in[16];
    const float* n1g    = (const float*)d_in[17];
    const float* n1b    = (const float*)d_in[18];
    const float* fW1    = (const float*)d_in[19];
    const float* fb1    = (const float*)d_in[20];
    const float* fW2    = (const float*)d_in[21];
    const float* fb2    = (const float*)d_in[22];
    const float* n2g    = (const float*)d_in[23];
    const float* n2b    = (const float*)d_in[24];
    const float* dWqloc = (const float*)d_in[25];
    const float* dWqrt  = (const float*)d_in[26];
    const float* dWk    = (const float*)d_in[27];
    const float* dWv    = (const float*)d_in[28];
    const float* dWc    = (const float*)d_in[29];
    const float* dWcb   = (const float*)d_in[30];
    float* out = (float*)d_out;

    float *px, *pqkv, *py, *px1, *pkvd, *pqloc, *pqrout, *pflag, *psn;
    SYM(px, g_x); SYM(pqkv, g_qkv); SYM(py, g_y); SYM(px1, g_x1);
    SYM(pkvd, g_kvd); SYM(pqloc, g_qloc); SYM(pqrout, g_qrout);
    SYM(pflag, g_flag); SYM(psn, g_sn);

    bf16 *pxh,*pxl, *px1h,*px1l, *pmhh,*pmhl, *pffhh,*pffhl, *pattnh,*pattnl;
    bf16 *pscoreh,*pscorel, *pcatlh,*pcatll, *pcatrh,*pcatrl;
    bf16 *pwqkvh,*pwqkvl, *pwch,*pwcl, *pf1h,*pf1l, *pf2h,*pf2l;
    bf16 *pwkvh,*pwkvl, *pwqlh,*pwqll, *pwpah,*pwpal, *pwdch,*pwdcl;
    SYM(pxh, g_xh); SYM(pxl, g_xl); SYM(px1h, g_x1h); SYM(px1l, g_x1l);
    SYM(pmhh, g_mhh); SYM(pmhl, g_mhl); SYM(pffhh, g_ffhh); SYM(pffhl, g_ffhl);
    SYM(pattnh, g_attnh); SYM(pattnl, g_attnl);
    SYM(pscoreh, g_scoreh); SYM(pscorel, g_scorel);
    SYM(pcatlh, g_catlh); SYM(pcatll, g_catll); SYM(pcatrh, g_catrh); SYM(pcatrl, g_catrl);
    SYM(pwqkvh, g_wqkvh); SYM(pwqkvl, g_wqkvl); SYM(pwch, g_wch); SYM(pwcl, g_wcl);
    SYM(pf1h, g_f1h); SYM(pf1l, g_f1l); SYM(pf2h, g_f2h); SYM(pf2l, g_f2l);
    SYM(pwkvh, g_wkvh); SYM(pwkvl, g_wkvl); SYM(pwqlh, g_wqlh); SYM(pwqll, g_wqll);
    SYM(pwpah, g_wpah); SYM(pwpal, g_wpal); SYM(pwdch, g_wdch); SYM(pwdcl, g_wdcl);

    const int R = BB * NN;
    const int TOT = BB * NN * EE;
    const int NQT = (NN + 127) / 128;
    static int smem_set = 0;
    if (!smem_set) {
        cudaFuncSetAttribute(attn_mma, cudaFuncAttributeMaxDynamicSharedMemorySize, ATTN2_SMEM);
        cudaFuncSetAttribute(gemm_tc2, cudaFuncAttributeMaxDynamicSharedMemorySize, GEMM_SMEM);
        smem_set = 1;
    }

    // ---- launches 0-4: setup (ordered so launch #5 = QKV gemm for ncu -s 5) ----
    embed_kernel<<<(TOT + 255)/256, 256>>>(depot, cust, edW, edb, ecW, ecb);     // 0
    pack_w<<<(NLL*384*EE + 256*EE + 255)/256, 256>>>(Wq, Wk, Wv, dWk, dWv);      // 1
    padw_kernel<<<(EE*KRT + 255)/256, 256>>>(dWqrt);                             // 2
    cvt_split<<<(NLL*EE*EE + 255)/256, 256>>>(Wc,  pwch, pwcl, NLL*EE*EE);       // 3
    cvt_split<<<(NLL*FFHH*EE + 255)/256, 256>>>(fW1, pf1h, pf1l, NLL*FFHH*EE);   // 4

    // ---- launch 5: layer-0 QKV GEMM (profiled) ----
    launch_tc(pxh, pxl, pwqkvh, pwqkvl, 0, 0, pqkv, 0, 0, R, EE, 384, 1, 0, 0, 0, 0);

    // remaining one-time converts
    cvt_split<<<(NLL*EE*FFHH + 255)/256, 256>>>(fW2, pf2h, pf2l, NLL*EE*FFHH);   // 6
    cvt_split<<<(EE*256 + 255)/256, 256>>>(dWqloc, pwqlh, pwqll, EE*256);        // 7
    cvt_split<<<(EE*EE + 255)/256, 256>>>(dWc, pwdch, pwdcl, EE*EE);             // 8

    // ---- encoder ----
    for (int i = 0; i < NLL; i++) {
        if (i > 0)
            launch_tc(pxh, pxl, pwqkvh + (long)i*384*EE, pwqkvl + (long)i*384*EE,
                      0, 0, pqkv, 0, 0, R, EE, 384, 1, 0, 0, 0, 0);
        attn_mma<<<dim3(NQT, HH, BB), 256, ATTN2_SMEM>>>(
            pqkv, (const float*)0, (const float*)0, 384,
            pqkv + 128, 384, pqkv + 256, 384, (const float*)0, pmhh, pmhl);
        launch_tc(pmhh, pmhl, pwch + (long)i*EE*EE, pwcl + (long)i*EE*EE,
                  Wcb + (long)i*EE, px, py, 0, 0, R, EE, EE, 1, 0, 0, 0, 0);
        inorm_sf<<<BB, 512>>>(py);
        inorm_apply<<<(TOT + 255)/256, 256>>>(py, n1g + (long)i*EE, n1b + (long)i*EE,
                                              px1, px1h, px1l);
        launch_tc(px1h, px1l, pf1h + (long)i*FFHH*EE, pf1l + (long)i*FFHH*EE,
                  fb1 + (long)i*FFHH, 0, 0, pffhh, pffhl, R, EE, FFHH, 1, 0, 0, 0, 1);
        launch_tc(pffhh, pffhl, pf2h + (long)i*EE*FFHH, pf2l + (long)i*EE*FFHH,
                  fb2 + (long)i*EE, px1, py, 0, 0, R, FFHH, EE, 1, 0, 0, 0, 0);
        inorm_sf<<<BB, 512>>>(py);
        inorm_apply<<<(TOT + 255)/256, 256>>>(py, n2g + (long)i*EE, n2b + (long)i*EE,
                                              px, pxh, pxl);
    }

    // ---- decoder ----
    launch_tc(pxh, pxl, pwkvh, pwkvl, 0, 0, pkvd, 0, 0, R, EE, 256, 1, 0, 0, 0, 0);
    encmean_kernel<<<BB, EE>>>();
    build_cat<<<BB*MM, EE>>>(loadv, cur, subn, subl, sel);
    launch_tc(pcatlh, pcatll, pwqlh, pwqll, 0, 0, pqloc, 0, 0, R, 256, EE, 1, 0, 0, 0, 0);
    launch_tc(pcatrh, pcatrl, pwpah, pwpal, 0, 0, pqrout, 0, 0, R, KRT, EE, 1, 0, 0, 0, 0);
    attn_mma<<<dim3(NQT, HH, BB), 256, ATTN2_SMEM>>>(
        pqloc, pqrout, pflag, 128, pkvd, 256, pkvd + 128, 256, mask, pattnh, pattnl);
    launch_tc(pattnh, pattnl, pwdch, pwdcl, dWcb, 0, 0, pscoreh, pscorel,
              R, EE, EE, 1, 0, 0, 0, 0);
    launch_tc(pscoreh, pscorel, pxh, pxl, 0, 0, psn, 0, 0, MM, EE, NN, BB,
              (long)MM*EE, (long)NN*EE, (long)MM*NN, 0);
    final_kernel<<<BB*MM, 256>>>(mask, out);
}

// round 9
// speedup vs baseline: 1.4009x; 1.0174x over previous
#include <cuda_runtime.h>
#include <cuda_bf16.h>
#include <math.h>
#include <stdint.h>

#define BB 32
#define NN 520
#define DEPOTN 20
#define CUSTN 500
#define EE 128
#define HH 8
#define DKK 16
#define FFHH 512
#define NLL 6
#define MM 520
#define LL 40
#define KRT 288

typedef __nv_bfloat16 bf16;

// ---------------- fp32 scratch ----------------
__device__ __align__(16) float g_x   [BB*NN*EE];
__device__ __align__(16) float g_qkv [BB*NN*384];
__device__ __align__(16) float g_y   [BB*NN*EE];
__device__ __align__(16) float g_x1  [BB*NN*EE];
__device__ __align__(16) float g_stats[BB*EE*2];
__device__ __align__(16) float g_kvd [BB*NN*256];
__device__ __align__(16) float g_encmean[BB*EE];
__device__ __align__(16) float g_qloc [BB*MM*EE];
__device__ __align__(16) float g_qrout[BB*MM*EE];
__device__ __align__(16) float g_flag [BB*MM];
__device__ __align__(16) float g_sn   [BB*MM*NN];

// ---------------- bf16 hi/lo scratch ----------------
__device__ __align__(16) bf16 g_xh[BB*NN*EE],      g_xl[BB*NN*EE];
__device__ __align__(16) bf16 g_x1h[BB*NN*EE],     g_x1l[BB*NN*EE];
__device__ __align__(16) bf16 g_mhh[BB*NN*EE],     g_mhl[BB*NN*EE];
__device__ __align__(16) bf16 g_ffhh[BB*NN*FFHH],  g_ffhl[BB*NN*FFHH];
__device__ __align__(16) bf16 g_attnh[BB*MM*EE],   g_attnl[BB*MM*EE];
__device__ __align__(16) bf16 g_scoreh[BB*MM*EE],  g_scorel[BB*MM*EE];
__device__ __align__(16) bf16 g_catlh[BB*MM*256],  g_catll[BB*MM*256];
__device__ __align__(16) bf16 g_catrh[BB*MM*KRT],  g_catrl[BB*MM*KRT];
__device__ __align__(16) bf16 g_wqkvh[NLL*384*EE], g_wqkvl[NLL*384*EE];
__device__ __align__(16) bf16 g_wch[NLL*EE*EE],    g_wcl[NLL*EE*EE];
__device__ __align__(16) bf16 g_f1h[NLL*FFHH*EE],  g_f1l[NLL*FFHH*EE];
__device__ __align__(16) bf16 g_f2h[NLL*EE*FFHH],  g_f2l[NLL*EE*FFHH];
__device__ __align__(16) bf16 g_wkvh[256*EE],      g_wkvl[256*EE];
__device__ __align__(16) bf16 g_wqlh[EE*256],      g_wqll[EE*256];
__device__ __align__(16) bf16 g_wpah[EE*KRT],      g_wpal[EE*KRT];
__device__ __align__(16) bf16 g_wdch[EE*EE],       g_wdcl[EE*EE];

__device__ __forceinline__ void split1(float x, bf16* h, bf16* l)
{
    bf16 hv = __float2bfloat16(x);
    *h = hv;
    *l = __float2bfloat16(x - __bfloat162float(hv));
}

__device__ __forceinline__ void cvtpk(float x0, float x1, uint32_t& h, uint32_t& l)
{
    bf16 h0 = __float2bfloat16(x0), h1 = __float2bfloat16(x1);
    float l0 = x0 - __bfloat162float(h0), l1 = x1 - __bfloat162float(h1);
    h = ((uint32_t)__bfloat16_as_ushort(h1) << 16) | __bfloat16_as_ushort(h0);
    bf16 g0 = __float2bfloat16(l0), g1 = __float2bfloat16(l1);
    l = ((uint32_t)__bfloat16_as_ushort(g1) << 16) | __bfloat16_as_ushort(g0);
}

// ---------------- generic fp32 -> hi/lo ----------------
__global__ void cvt_split(const float* __restrict__ s, bf16* __restrict__ h,
                          bf16* __restrict__ l, int n)
{
    int i = blockIdx.x * blockDim.x + threadIdx.x;
    if (i < n) split1(s[i], h + i, l + i);
}

// ---------------- embedding ----------------
__global__ void embed_kernel(const float* __restrict__ dep, const float* __restrict__ cus,
                             const float* __restrict__ Wd, const float* __restrict__ bd,
                             const float* __restrict__ Wc, const float* __restrict__ bc)
{
    int idx = blockIdx.x * blockDim.x + threadIdx.x;
    if (idx >= BB*NN*EE) return;
    int e = idx % EE;
    int n = (idx / EE) % NN;
    int b = idx / (EE*NN);
    float acc;
    if (n < DEPOTN) {
        const float* f = dep + ((long)b*DEPOTN + n) * 4;
        acc = bd[e];
        #pragma unroll
        for (int j = 0; j < 4; j++) acc += f[j] * Wd[e*4 + j];
    } else {
        const float* f = cus + ((long)b*CUSTN + (n - DEPOTN)) * 3;
        acc = bc[e];
        #pragma unroll
        for (int j = 0; j < 3; j++) acc += f[j] * Wc[e*3 + j];
    }
    g_x[idx] = acc;
    split1(acc, g_xh + idx, g_xl + idx);
}

// ---------------- weight packing ----------------
__global__ void pack_w(const float* __restrict__ Wq, const float* __restrict__ Wk,
                       const float* __restrict__ Wv, const float* __restrict__ dWk,
                       const float* __restrict__ dWv)
{
    int idx = blockIdx.x * blockDim.x + threadIdx.x;
    const int tot1 = NLL*384*EE;
    if (idx < tot1) {
        int col = idx % EE;
        int row = (idx / EE) % 384;
        int l   = idx / (EE*384);
        float v;
        if (row < 128)      v = Wq[((long)l*EE + row)*EE + col];
        else if (row < 256) v = Wk[((long)l*EE + row-128)*EE + col];
        else                v = Wv[((long)l*EE + row-256)*EE + col];
        split1(v, g_wqkvh + idx, g_wqkvl + idx);
    } else {
        int j = idx - tot1;
        if (j < 256*EE) {
            int col = j % EE;
            int row = j / EE;
            float v = (row < 128) ? dWk[row*EE + col] : dWv[(row-128)*EE + col];
            split1(v, g_wkvh + j, g_wkvl + j);
        }
    }
}

__global__ void padw_kernel(const float* __restrict__ Wr)
{
    int idx = blockIdx.x * blockDim.x + threadIdx.x;
    if (idx >= EE*KRT) return;
    int rr = idx / KRT, cc = idx % KRT;
    float v = (cc < 257) ? Wr[rr*257 + cc] : 0.f;
    split1(v, g_wpah + idx, g_wpal + idx);
}

// ---------------- MMA primitives ----------------
#define LDM4(r0,r1,r2,r3,addr) \
    asm volatile("ldmatrix.sync.aligned.m8n8.x4.shared.b16 {%0,%1,%2,%3},[%4];" \
                 : "=r"(r0),"=r"(r1),"=r"(r2),"=r"(r3) : "r"(addr))
#define LDM2(r0,r1,addr) \
    asm volatile("ldmatrix.sync.aligned.m8n8.x2.shared.b16 {%0,%1},[%2];" \
                 : "=r"(r0),"=r"(r1) : "r"(addr))
#define MMA16816(c,a,b) \
    asm volatile("mma.sync.aligned.m16n8k16.row.col.f32.bf16.bf16.f32 " \
                 "{%0,%1,%2,%3},{%4,%5,%6,%7},{%8,%9},{%0,%1,%2,%3};" \
                 : "+f"((c)[0]),"+f"((c)[1]),"+f"((c)[2]),"+f"((c)[3]) \
                 : "r"((a)[0]),"r"((a)[1]),"r"((a)[2]),"r"((a)[3]), "r"((b)[0]),"r"((b)[1]))

// ---------------- TC GEMM v2 (proven) ----------------
#define MAT 10240
#define STAGE 40960

__global__ __launch_bounds__(256, 2)
void gemm_tc2(const bf16* __restrict__ Ahi, const bf16* __restrict__ Alo,
              const bf16* __restrict__ Bhi, const bf16* __restrict__ Blo,
              const float* __restrict__ bias, const float* __restrict__ resid,
              float* __restrict__ C, bf16* __restrict__ Chi, bf16* __restrict__ Clo,
              int R, int K, int Cout, long sA, long sB, long sC, int relu)
{
    int bz = blockIdx.z;
    Ahi += (long)bz*sA; Alo += (long)bz*sA;
    Bhi += (long)bz*sB; Blo += (long)bz*sB;
    if (C)     C   += (long)bz*sC;
    if (Chi) { Chi += (long)bz*sC; Clo += (long)bz*sC; }
    if (resid) resid += (long)bz*sC;

    extern __shared__ bf16 smb[];
    uint32_t sb = (uint32_t)__cvta_generic_to_shared(smb);

    int tid = threadIdx.x, lane = tid & 31, warp = tid >> 5;
    int wm = warp >> 2, wn = warp & 3;
    int rowBase = blockIdx.x * 128, colBase = blockIdx.y * 128;

    float c[4][4][4];
    #pragma unroll
    for (int i = 0; i < 4; i++)
        #pragma unroll
        for (int j = 0; j < 4; j++)
            { c[i][j][0]=0.f; c[i][j][1]=0.f; c[i][j][2]=0.f; c[i][j][3]=0.f; }

    const bf16* bases[4] = { Ahi, Alo, Bhi, Blo };
    int nk = K >> 5;

    #define FILL(st, kt) do { \
        int k0 = (kt) << 5; \
        _Pragma("unroll") \
        for (int t = 0; t < 8; t++) { \
            int o = tid + t*256; \
            int m = o >> 9, r = (o >> 2) & 127, seg = o & 3; \
            int gr = ((m < 2) ? rowBase : colBase) + r; \
            int lim = (m < 2) ? R : Cout; \
            long grc = (gr < lim) ? gr : 0; \
            const bf16* src = bases[m] + grc*K + k0 + seg*8; \
            uint32_t dst = sb + (st)*STAGE + m*MAT + r*80 + seg*16; \
            int nbytes = (gr < lim) ? 16 : 0; \
            asm volatile("cp.async.ca.shared.global [%0],[%1],16,%2;" \
                         :: "r"(dst), "l"(src), "r"(nbytes)); \
        } \
        asm volatile("cp.async.commit_group;"); \
    } while (0)

    FILL(0, 0);

    int ar = lane & 15, ak = (lane >> 4);
    int br = lane & 7,  bk = (lane >> 3) & 1;

    for (int kt = 0; kt < nk; kt++) {
        int st = kt & 1;
        if (kt + 1 < nk) {
            FILL(st ^ 1, kt + 1);
            asm volatile("cp.async.wait_group 1;");
        } else {
            asm volatile("cp.async.wait_group 0;");
        }
        __syncthreads();

        uint32_t aOff = sb + st*STAGE;
        uint32_t bOff = aOff + 2*MAT;
        #pragma unroll
        for (int ks = 0; ks < 2; ks++) {
            uint32_t Ah[4][4], Al[4][4];
            #pragma unroll
            for (int i = 0; i < 4; i++) {
                uint32_t ad = aOff + (uint32_t)((wm*64 + i*16 + ar)*80 + ak*16 + ks*32);
                LDM4(Ah[i][0], Ah[i][1], Ah[i][2], Ah[i][3], ad);
                LDM4(Al[i][0], Al[i][1], Al[i][2], Al[i][3], ad + MAT);
            }
            #pragma unroll
            for (int j = 0; j < 4; j++) {
                uint32_t bd = bOff + (uint32_t)((wn*32 + j*8 + br)*80 + bk*16 + ks*32);
                uint32_t Bh[2], Bl[2];
                LDM2(Bh[0], Bh[1], bd);
                LDM2(Bl[0], Bl[1], bd + MAT);
                #pragma unroll
                for (int i = 0; i < 4; i++) {
                    MMA16816(c[i][j], Ah[i], Bh);
                    MMA16816(c[i][j], Ah[i], Bl);
                    MMA16816(c[i][j], Al[i], Bh);
                }
            }
        }
        __syncthreads();
    }

    int gid = lane >> 2, tig = lane & 3;
    #pragma unroll
    for (int i = 0; i < 4; i++) {
        int rbase = rowBase + wm*64 + i*16 + gid;
        #pragma unroll
        for (int j = 0; j < 4; j++) {
            int c0 = colBase + wn*32 + j*8 + tig*2;
            if (c0 >= Cout) continue;
            #pragma unroll
            for (int hh = 0; hh < 2; hh++) {
                int row = rbase + hh*8;
                if (row >= R) continue;
                float v0 = c[i][j][2*hh], v1 = c[i][j][2*hh+1];
                if (bias)  { v0 += bias[c0]; v1 += bias[c0+1]; }
                if (resid) {
                    float2 rv = *(const float2*)(resid + (long)row*Cout + c0);
                    v0 += rv.x; v1 += rv.y;
                }
                if (relu) { v0 = fmaxf(v0, 0.f); v1 = fmaxf(v1, 0.f); }
                if (C) *(float2*)(C + (long)row*Cout + c0) = make_float2(v0, v1);
                if (Chi) {
                    uint32_t hp, lp;
                    cvtpk(v0, v1, hp, lp);
                    *(uint32_t*)(Chi + (long)row*Cout + c0) = hp;
                    *(uint32_t*)(Clo + (long)row*Cout + c0) = lp;
                }
            }
        }
    }
}

// ---------------- attention via MMA (FA2-style, hi/lo bf16) ----------------
#define KPAD 576
#define KLO_B  27648
#define VHI_B  55296
#define VLO_B  18688
#define QHI_B  92672
#define QLO_B  6144
#define ATTN2_SMEM 104960

__global__ __launch_bounds__(256)
void attn_mma(const float* __restrict__ Q, const float* __restrict__ Q2,
              const float* __restrict__ flagv, int ldq,
              const float* __restrict__ Kt, int ldk,
              const float* __restrict__ Vt, int ldv,
              const float* __restrict__ mask,
              bf16* __restrict__ Oh, bf16* __restrict__ Ol)
{
    int qb = blockIdx.x * 128;
    int h = blockIdx.y, b = blockIdx.z;
    extern __shared__ bf16 sm2[];
    uint32_t sb = (uint32_t)__cvta_generic_to_shared(sm2);
    int tid = threadIdx.x;

    const int KHI_E = 0, KLO_E = 13824, VHI_E = 27648, VLO_E = 36992;
    const int QHI_E = 46336, QLO_E = 49408;

    const float* Kg = Kt + (long)b*NN*ldk + h*DKK;
    const float* Vg = Vt + (long)b*NN*ldv + h*DKK;
    for (int i = tid; i < KPAD*DKK; i += 256) {
        int key = i >> 4, d = i & 15;
        float kv = (key < NN) ? Kg[(long)key*ldk + d] : 0.f;
        float vv = (key < NN) ? Vg[(long)key*ldv + d] : 0.f;
        bf16 kh = __float2bfloat16(kv);
        bf16 kl = __float2bfloat16(kv - __bfloat162float(kh));
        bf16 vh = __float2bfloat16(vv);
        bf16 vl = __float2bfloat16(vv - __bfloat162float(vh));
        sm2[KHI_E + key*24 + d] = kh;
        sm2[KLO_E + key*24 + d] = kl;
        sm2[VHI_E + d*584 + key] = vh;
        sm2[VLO_E + d*584 + key] = vl;
    }
    const float* Qg = Q + (long)b*NN*ldq + h*DKK;
    const float* Qg2 = Q2 ? (Q2 + (long)b*NN*ldq + h*DKK) : (const float*)0;
    for (int i = tid; i < 128*DKK; i += 256) {
        int row = i >> 4, d = i & 15;
        int q = qb + row;
        float qv = 0.f;
        if (q < NN) {
            qv = Qg[(long)q*ldq + d];
            if (Qg2) {
                float f = flagv[(long)b*MM + q];
                qv = f*qv + (1.f - f)*Qg2[(long)q*ldq + d];
            }
        }
        bf16 qh = __float2bfloat16(qv);
        sm2[QHI_E + row*24 + d] = qh;
        sm2[QLO_E + row*24 + d] = __float2bfloat16(qv - __bfloat162float(qh));
    }
    __syncthreads();

    int warp = tid >> 5, lane = tid & 31;

    // tail-wave skip: warps whose entire 16-row slice is padding exit now.
    // No block-level syncs below (only intra-warp shuffles), so this is legal.
    if (qb + warp*16 >= NN) return;

    int g = lane >> 2;
    int ar = lane & 15, ak = lane >> 4;
    int br = lane & 7,  bk = (lane >> 3) & 1;
    const unsigned FULL = 0xffffffffu;

    uint32_t Qh[4], Ql[4];
    {
        uint32_t qa = sb + QHI_B + (uint32_t)((warp*16 + ar)*48 + ak*16);
        LDM4(Qh[0], Qh[1], Qh[2], Qh[3], qa);
        LDM4(Ql[0], Ql[1], Ql[2], Ql[3], qa + QLO_B);
    }

    float o[2][4];
    #pragma unroll
    for (int n = 0; n < 2; n++) { o[n][0]=0.f; o[n][1]=0.f; o[n][2]=0.f; o[n][3]=0.f; }
    float mrow[2] = { -1e30f, -1e30f };
    float lrow[2] = { 0.f, 0.f };

    int qr0 = qb + warp*16 + g;
    int qm0 = (qr0 < NN) ? qr0 : NN-1;
    int qm1 = (qr0+8 < NN) ? qr0+8 : NN-1;
    const float* mk0 = mask ? (mask + ((long)(b*MM + qm0))*NN) : (const float*)0;
    const float* mk1 = mask ? (mask + ((long)(b*MM + qm1))*NN) : (const float*)0;

    #pragma unroll 1
    for (int c = 0; c < 9; c++) {
        float s[8][4];
        #pragma unroll
        for (int t = 0; t < 8; t++) {
            uint32_t ka = sb + (uint32_t)((c*64 + t*8 + br)*48 + bk*16);
            uint32_t bh[2], bl[2];
            LDM2(bh[0], bh[1], ka);
            LDM2(bl[0], bl[1], ka + KLO_B);
            s[t][0]=0.f; s[t][1]=0.f; s[t][2]=0.f; s[t][3]=0.f;
            MMA16816(s[t], Qh, bh);
            MMA16816(s[t], Qh, bl);
            MMA16816(s[t], Ql, bh);
        }
        float mx0 = -1e30f, mx1 = -1e30f;
        #pragma unroll
        for (int t = 0; t < 8; t++) {
            if (c < 8 || t == 0) {
                s[t][0]*=0.25f; s[t][1]*=0.25f; s[t][2]*=0.25f; s[t][3]*=0.25f;
                if (mask) {
                    int j = c*64 + t*8 + (lane&3)*2;
                    float2 m0 = *(const float2*)(mk0 + j);
                    float2 m1 = *(const float2*)(mk1 + j);
                    s[t][0]+=m0.x; s[t][1]+=m0.y; s[t][2]+=m1.x; s[t][3]+=m1.y;
                }
            } else {
                s[t][0]=-1e30f; s[t][1]=-1e30f; s[t][2]=-1e30f; s[t][3]=-1e30f;
            }
            mx0 = fmaxf(mx0, fmaxf(s[t][0], s[t][1]));
            mx1 = fmaxf(mx1, fmaxf(s[t][2], s[t][3]));
        }
        mx0 = fmaxf(mx0, __shfl_xor_sync(FULL, mx0, 1));
        mx0 = fmaxf(mx0, __shfl_xor_sync(FULL, mx0, 2));
        mx1 = fmaxf(mx1, __shfl_xor_sync(FULL, mx1, 1));
        mx1 = fmaxf(mx1, __shfl_xor_sync(FULL, mx1, 2));
        float mn0 = fmaxf(mrow[0], mx0), mn1 = fmaxf(mrow[1], mx1);
        float f0 = __expf(mrow[0] - mn0), f1 = __expf(mrow[1] - mn1);
        mrow[0] = mn0; mrow[1] = mn1;
        float rs0 = 0.f, rs1 = 0.f;
        #pragma unroll
        for (int t = 0; t < 8; t++) {
            s[t][0] = __expf(s[t][0] - mn0);
            s[t][1] = __expf(s[t][1] - mn0);
            s[t][2] = __expf(s[t][2] - mn1);
            s[t][3] = __expf(s[t][3] - mn1);
            rs0 += s[t][0] + s[t][1];
            rs1 += s[t][2] + s[t][3];
        }
        rs0 += __shfl_xor_sync(FULL, rs0, 1); rs0 += __shfl_xor_sync(FULL, rs0, 2);
        rs1 += __shfl_xor_sync(FULL, rs1, 1); rs1 += __shfl_xor_sync(FULL, rs1, 2);
        lrow[0] = lrow[0]*f0 + rs0;
        lrow[1] = lrow[1]*f1 + rs1;
        #pragma unroll
        for (int n = 0; n < 2; n++) {
            o[n][0]*=f0; o[n][1]*=f0; o[n][2]*=f1; o[n][3]*=f1;
        }
        #pragma unroll
        for (int ss = 0; ss < 4; ss++) {
            uint32_t pah[4], pal[4];
            cvtpk(s[2*ss][0],   s[2*ss][1],   pah[0], pal[0]);
            cvtpk(s[2*ss][2],   s[2*ss][3],   pah[1], pal[1]);
            cvtpk(s[2*ss+1][0], s[2*ss+1][1], pah[2], pal[2]);
            cvtpk(s[2*ss+1][2], s[2*ss+1][3], pah[3], pal[3]);
            #pragma unroll
            for (int n = 0; n < 2; n++) {
                uint32_t va = sb + VHI_B +
                    (uint32_t)((n*8 + br)*1168 + (c*64 + ss*16)*2 + bk*16);
                uint32_t vh[2], vl[2];
                LDM2(vh[0], vh[1], va);
                LDM2(vl[0], vl[1], va + VLO_B);
                MMA16816(o[n], pah, vh);
                MMA16816(o[n], pah, vl);
                MMA16816(o[n], pal, vh);
            }
        }
    }

    float i0 = 1.f / lrow[0], i1 = 1.f / lrow[1];
    #pragma unroll
    for (int n = 0; n < 2; n++) {
        int d = h*DKK + n*8 + (lane&3)*2;
        if (qr0 < NN) {
            uint32_t hp, lp;
            cvtpk(o[n][0]*i0, o[n][1]*i0, hp, lp);
            long off = ((long)(b*NN + qr0))*EE + d;
            *(uint32_t*)(Oh + off) = hp;
            *(uint32_t*)(Ol + off) = lp;
        }
        if (qr0 + 8 < NN) {
            uint32_t hp, lp;
            cvtpk(o[n][2]*i1, o[n][3]*i1, hp, lp);
            long off = ((long)(b*NN + qr0 + 8))*EE + d;
            *(uint32_t*)(Oh + off) = hp;
            *(uint32_t*)(Ol + off) = lp;
        }
    }
}

// ---------------- instance norm: fused stats+finalize ----------------
__global__ __launch_bounds__(512)
void inorm_sf(const float* __restrict__ Y)
{
    int b = blockIdx.x;
    int tid = threadIdx.x;
    int e = tid & 127, ch = tid >> 7;
    float s1 = 0.f, s2 = 0.f;
    for (int n = ch; n < NN; n += 4) {
        float v = Y[((long)(b*NN + n))*EE + e];
        s1 += v; s2 += v*v;
    }
    __shared__ float sh1[512], sh2[512];
    sh1[tid] = s1; sh2[tid] = s2;
    __syncthreads();
    if (tid < 128) {
        float t1 = sh1[tid] + sh1[tid+128] + sh1[tid+256] + sh1[tid+384];
        float t2 = sh2[tid] + sh2[tid+128] + sh2[tid+256] + sh2[tid+384];
        float mean = t1 / (float)NN;
        float var  = t2 / (float)NN - mean*mean;
        g_stats[(b*EE+tid)*2]   = mean;
        g_stats[(b*EE+tid)*2+1] = rsqrtf(var + 1e-5f);
    }
}

__global__ void inorm_apply(const float* __restrict__ Y, const float* __restrict__ gg,
                            const float* __restrict__ bt, float* __restrict__ Xo,
                            bf16* __restrict__ Xh, bf16* __restrict__ Xl)
{
    int idx = blockIdx.x * blockDim.x + threadIdx.x;
    if (idx >= BB*NN*EE) return;
    int e = idx % EE;
    int b = idx / (NN*EE);
    float mean = g_stats[(b*EE+e)*2];
    float istd = g_stats[(b*EE+e)*2+1];
    float v = (Y[idx] - mean) * istd * gg[e] + bt[e];
    Xo[idx] = v;
    split1(v, Xh + idx, Xl + idx);
}

// ---------------- decoder helpers ----------------
__global__ void encmean_kernel()
{
    int b = blockIdx.x, e = threadIdx.x;
    float s = 0.f;
    for (int n = 0; n < NN; n++) s += g_x[((long)(b*NN + n))*EE + e];
    g_encmean[b*EE + e] = s / (float)NN;
}

__global__ void build_cat(const float* __restrict__ loadv, const int* __restrict__ cur,
                          const int* __restrict__ subn, const int* __restrict__ subl,
                          const int* __restrict__ sel)
{
    int r = blockIdx.x;
    int b = r / MM;
    int e = threadIdx.x;
    int c = cur[r];
    float le = g_x[((long)(b*NN + c))*EE + e];

    int len = subl[r];
    const int* nodes = subn + (long)r*LL;
    float ssum = 0.f; int cnt = 0;
    for (int l = 0; l < LL; l++) {
        int nd = nodes[l];
        if (l < len && nd >= DEPOTN) {
            ssum += g_x[((long)(b*NN + nd))*EE + e];
            cnt++;
        }
    }
    float cntf = (cnt > 0) ? (float)cnt : 1.f;
    float smean = ssum / cntf;

    long bl = (long)r*256, br = (long)r*KRT;
    split1(le,    g_catlh + bl + e,       g_catll + bl + e);
    split1(smean, g_catlh + bl + 128 + e, g_catll + bl + 128 + e);
    split1(le,    g_catrh + br + e,       g_catrl + br + e);
    split1(g_encmean[b*EE + e], g_catrh + br + 128 + e, g_catrl + br + 128 + e);
    if (e == 0) split1(loadv[r], g_catrh + br + 256, g_catrl + br + 256);
    if (e >= 1 && e < 32) { g_catrh[br + 256 + e] = __float2bfloat16(0.f);
                            g_catrl[br + 256 + e] = __float2bfloat16(0.f); }
    if (e == 0) {
        int s2 = sel[(long)r*4 + 2];
        g_flag[r] = (s2 >= DEPOTN && c < DEPOTN) ? 1.f : 0.f;
    }
}

// ---------------- final tanh-clip + mask + softmax ----------------
__global__ void final_kernel(const float* __restrict__ mask, float* __restrict__ out)
{
    int r = blockIdx.x;
    int tid = threadIdx.x;
    __shared__ float buf[NN];
    __shared__ float red[256];
    const float* sn = g_sn + (long)r*NN;
    const float* mk = mask + (long)r*NN;
    const float invs = 0.08838834764831845f;

    float lm = -1e30f;
    for (int j = tid; j < NN; j += 256) {
        float v = 10.f * tanhf(sn[j] * invs) + mk[j];
        buf[j] = v;
        lm = fmaxf(lm, v);
    }
    red[tid] = lm; __syncthreads();
    for (int off = 128; off > 0; off >>= 1) {
        if (tid < off) red[tid] = fmaxf(red[tid], red[tid+off]);
        __syncthreads();
    }
    float mx = red[0]; __syncthreads();

    float ls = 0.f;
    for (int j = tid; j < NN; j += 256) {
        float e0 = __expf(buf[j] - mx);
        buf[j] = e0; ls += e0;
    }
    red[tid] = ls; __syncthreads();
    for (int off = 128; off > 0; off >>= 1) {
        if (tid < off) red[tid] += red[tid+off];
        __syncthreads();
    }
    float inv = 1.f / red[0];
    for (int j = tid; j < NN; j += 256)
        out[(long)r*NN + j] = buf[j] * inv;
}

// ---------------- host ----------------
#define GEMM_SMEM 81920

static void launch_tc(const bf16* Ah, const bf16* Al, const bf16* Bh, const bf16* Bl,
                      const float* bias, const float* resid,
                      float* C, bf16* Ch, bf16* Cl,
                      int R, int K, int Cout, int batch,
                      long sA, long sB, long sC, int relu)
{
    dim3 grid((R + 127) / 128, (Cout + 127) / 128, batch);
    gemm_tc2<<<grid, 256, GEMM_SMEM>>>(Ah, Al, Bh, Bl, bias, resid, C, Ch, Cl,
                                       R, K, Cout, sA, sB, sC, relu);
}

#define SYM(p, s) cudaGetSymbolAddress((void**)&p, s)

extern "C" void kernel_launch(void* const* d_in, const int* in_sizes, int n_in,
                              void* d_out, int out_size)
{
    const float* depot  = (const float*)d_in[0];
    const float* cust   = (const float*)d_in[1];
    const float* mask   = (const float*)d_in[2];
    const float* loadv  = (const float*)d_in[3];
    const int*   cur    = (const int*)d_in[4];
    const int*   subn   = (const int*)d_in[5];
    const int*   subl   = (const int*)d_in[6];
    const int*   sel    = (const int*)d_in[7];
    const float* edW    = (const float*)d_in[8];
    const float* edb    = (const float*)d_in[9];
    const float* ecW    = (const float*)d_in[10];
    const float* ecb    = (const float*)d_in[11];
    const float* Wq     = (const float*)d_in[12];
    const float* Wk     = (const float*)d_in[13];
    const float* Wv     = (const float*)d_in[14];
    const float* Wc     = (const float*)d_in[15];
    const float* Wcb    = (const float*)d_in[16];
    const float* n1g    = (const float*)d_in[17];
    const float* n1b    = (const float*)d_in[18];
    const float* fW1    = (const float*)d_in[19];
    const float* fb1    = (const float*)d_in[20];
    const float* fW2    = (const float*)d_in[21];
    const float* fb2    = (const float*)d_in[22];
    const float* n2g    = (const float*)d_in[23];
    const float* n2b    = (const float*)d_in[24];
    const float* dWqloc = (const float*)d_in[25];
    const float* dWqrt  = (const float*)d_in[26];
    const float* dWk    = (const float*)d_in[27];
    const float* dWv    = (const float*)d_in[28];
    const float* dWc    = (const float*)d_in[29];
    const float* dWcb   = (const float*)d_in[30];
    float* out = (float*)d_out;

    float *px, *pqkv, *py, *px1, *pkvd, *pqloc, *pqrout, *pflag, *psn;
    SYM(px, g_x); SYM(pqkv, g_qkv); SYM(py, g_y); SYM(px1, g_x1);
    SYM(pkvd, g_kvd); SYM(pqloc, g_qloc); SYM(pqrout, g_qrout);
    SYM(pflag, g_flag); SYM(psn, g_sn);

    bf16 *pxh,*pxl, *px1h,*px1l, *pmhh,*pmhl, *pffhh,*pffhl, *pattnh,*pattnl;
    bf16 *pscoreh,*pscorel, *pcatlh,*pcatll, *pcatrh,*pcatrl;
    bf16 *pwqkvh,*pwqkvl, *pwch,*pwcl, *pf1h,*pf1l, *pf2h,*pf2l;
    bf16 *pwkvh,*pwkvl, *pwqlh,*pwqll, *pwpah,*pwpal, *pwdch,*pwdcl;
    SYM(pxh, g_xh); SYM(pxl, g_xl); SYM(px1h, g_x1h); SYM(px1l, g_x1l);
    SYM(pmhh, g_mhh); SYM(pmhl, g_mhl); SYM(pffhh, g_ffhh); SYM(pffhl, g_ffhl);
    SYM(pattnh, g_attnh); SYM(pattnl, g_attnl);
    SYM(pscoreh, g_scoreh); SYM(pscorel, g_scorel);
    SYM(pcatlh, g_catlh); SYM(pcatll, g_catll); SYM(pcatrh, g_catrh); SYM(pcatrl, g_catrl);
    SYM(pwqkvh, g_wqkvh); SYM(pwqkvl, g_wqkvl); SYM(pwch, g_wch); SYM(pwcl, g_wcl);
    SYM(pf1h, g_f1h); SYM(pf1l, g_f1l); SYM(pf2h, g_f2h); SYM(pf2l, g_f2l);
    SYM(pwkvh, g_wkvh); SYM(pwkvl, g_wkvl); SYM(pwqlh, g_wqlh); SYM(pwqll, g_wqll);
    SYM(pwpah, g_wpah); SYM(pwpal, g_wpal); SYM(pwdch, g_wdch); SYM(pwdcl, g_wdcl);

    const int R = BB * NN;
    const int TOT = BB * NN * EE;
    const int NQT = (NN + 127) / 128;
    static int smem_set = 0;
    if (!smem_set) {
        cudaFuncSetAttribute(attn_mma, cudaFuncAttributeMaxDynamicSharedMemorySize, ATTN2_SMEM);
        cudaFuncSetAttribute(gemm_tc2, cudaFuncAttributeMaxDynamicSharedMemorySize, GEMM_SMEM);
        smem_set = 1;
    }

    // ---- my launches 0,1: producers for the QKV GEMM ----
    embed_kernel<<<(TOT + 255)/256, 256>>>(depot, cust, edW, edb, ecW, ecb);     // 0
    pack_w<<<(NLL*384*EE + 256*EE + 255)/256, 256>>>(Wq, Wk, Wv, dWk, dWv);      // 1

    // ---- my launch 2: layer-0 QKV GEMM — target for ncu (-s 5 with ~3 hidden launches) ----
    launch_tc(pxh, pxl, pwqkvh, pwqkvl, 0, 0, pqkv, 0, 0, R, EE, 384, 1, 0, 0, 0, 0);

    // ---- remaining one-time converts ----
    padw_kernel<<<(EE*KRT + 255)/256, 256>>>(dWqrt);
    cvt_split<<<(NLL*EE*EE + 255)/256, 256>>>(Wc,  pwch, pwcl, NLL*EE*EE);
    cvt_split<<<(NLL*FFHH*EE + 255)/256, 256>>>(fW1, pf1h, pf1l, NLL*FFHH*EE);
    cvt_split<<<(NLL*EE*FFHH + 255)/256, 256>>>(fW2, pf2h, pf2l, NLL*EE*FFHH);
    cvt_split<<<(EE*256 + 255)/256, 256>>>(dWqloc, pwqlh, pwqll, EE*256);
    cvt_split<<<(EE*EE + 255)/256, 256>>>(dWc, pwdch, pwdcl, EE*EE);

    // ---- encoder ----
    for (int i = 0; i < NLL; i++) {
        if (i > 0)
            launch_tc(pxh, pxl, pwqkvh + (long)i*384*EE, pwqkvl + (long)i*384*EE,
                      0, 0, pqkv, 0, 0, R, EE, 384, 1, 0, 0, 0, 0);
        attn_mma<<<dim3(NQT, HH, BB), 256, ATTN2_SMEM>>>(
            pqkv, (const float*)0, (const float*)0, 384,
            pqkv + 128, 384, pqkv + 256, 384, (const float*)0, pmhh, pmhl);
        launch_tc(pmhh, pmhl, pwch + (long)i*EE*EE, pwcl + (long)i*EE*EE,
                  Wcb + (long)i*EE, px, py, 0, 0, R, EE, EE, 1, 0, 0, 0, 0);
        inorm_sf<<<BB, 512>>>(py);
        inorm_apply<<<(TOT + 255)/256, 256>>>(py, n1g + (long)i*EE, n1b + (long)i*EE,
                                              px1, px1h, px1l);
        launch_tc(px1h, px1l, pf1h + (long)i*FFHH*EE, pf1l + (long)i*FFHH*EE,
                  fb1 + (long)i*FFHH, 0, 0, pffhh, pffhl, R, EE, FFHH, 1, 0, 0, 0, 1);
        launch_tc(pffhh, pffhl, pf2h + (long)i*EE*FFHH, pf2l + (long)i*EE*FFHH,
                  fb2 + (long)i*EE, px1, py, 0, 0, R, FFHH, EE, 1, 0, 0, 0, 0);
        inorm_sf<<<BB, 512>>>(py);
        inorm_apply<<<(TOT + 255)/256, 256>>>(py, n2g + (long)i*EE, n2b + (long)i*EE,
                                              px, pxh, pxl);
    }

    // ---- decoder ----
    launch_tc(pxh, pxl, pwkvh, pwkvl, 0, 0, pkvd, 0, 0, R, EE, 256, 1, 0, 0, 0, 0);
    encmean_kernel<<<BB, EE>>>();
    build_cat<<<BB*MM, EE>>>(loadv, cur, subn, subl, sel);
    launch_tc(pcatlh, pcatll, pwqlh, pwqll, 0, 0, pqloc, 0, 0, R, 256, EE, 1, 0, 0, 0, 0);
    launch_tc(pcatrh, pcatrl, pwpah, pwpal, 0, 0, pqrout, 0, 0, R, KRT, EE, 1, 0, 0, 0, 0);
    attn_mma<<<dim3(NQT, HH, BB), 256, ATTN2_SMEM>>>(
        pqloc, pqrout, pflag, 128, pkvd, 256, pkvd + 128, 256, mask, pattnh, pattnl);
    launch_tc(pattnh, pattnl, pwdch, pwdcl, dWcb, 0, 0, pscoreh, pscorel,
              R, EE, EE, 1, 0, 0, 0, 0);
    launch_tc(pscoreh, pscorel, pxh, pxl, 0, 0, psn, 0, 0, MM, EE, NN, BB,
              (long)MM*EE, (long)NN*EE, (long)MM*NN, 0);
    final_kernel<<<BB*MM, 256>>>(mask, out);
}

// round 10
// speedup vs baseline: 1.4407x; 1.0284x over previous
#include <cuda_runtime.h>
#include <cuda_bf16.h>
#include <math.h>
#include <stdint.h>

#define BB 32
#define NN 520
#define DEPOTN 20
#define CUSTN 500
#define EE 128
#define HH 8
#define DKK 16
#define FFHH 512
#define NLL 6
#define MM 520
#define LL 40
#define KRT 288

typedef __nv_bfloat16 bf16;

// ---------------- fp32 scratch ----------------
__device__ __align__(16) float g_x   [BB*NN*EE];
__device__ __align__(16) float g_qkv [BB*NN*384];
__device__ __align__(16) float g_y   [BB*NN*EE];
__device__ __align__(16) float g_x1  [BB*NN*EE];
__device__ __align__(16) float g_stats[BB*EE*2];
__device__ __align__(16) float g_kvd [BB*NN*256];
__device__ __align__(16) float g_qloc [BB*MM*EE];
__device__ __align__(16) float g_qrout[BB*MM*EE];
__device__ __align__(16) float g_flag [BB*MM];
__device__ __align__(16) float g_sn   [BB*MM*NN];

// ---------------- bf16 hi/lo scratch ----------------
__device__ __align__(16) bf16 g_xh[BB*NN*EE],      g_xl[BB*NN*EE];
__device__ __align__(16) bf16 g_x1h[BB*NN*EE],     g_x1l[BB*NN*EE];
__device__ __align__(16) bf16 g_mhh[BB*NN*EE],     g_mhl[BB*NN*EE];
__device__ __align__(16) bf16 g_ffhh[BB*NN*FFHH],  g_ffhl[BB*NN*FFHH];
__device__ __align__(16) bf16 g_attnh[BB*MM*EE],   g_attnl[BB*MM*EE];
__device__ __align__(16) bf16 g_scoreh[BB*MM*EE],  g_scorel[BB*MM*EE];
__device__ __align__(16) bf16 g_catlh[BB*MM*256],  g_catll[BB*MM*256];
__device__ __align__(16) bf16 g_catrh[BB*MM*KRT],  g_catrl[BB*MM*KRT];
__device__ __align__(16) bf16 g_wqkvh[NLL*384*EE], g_wqkvl[NLL*384*EE];
__device__ __align__(16) bf16 g_wch[NLL*EE*EE],    g_wcl[NLL*EE*EE];
__device__ __align__(16) bf16 g_f1h[NLL*FFHH*EE],  g_f1l[NLL*FFHH*EE];
__device__ __align__(16) bf16 g_f2h[NLL*EE*FFHH],  g_f2l[NLL*EE*FFHH];
__device__ __align__(16) bf16 g_wkvh[256*EE],      g_wkvl[256*EE];
__device__ __align__(16) bf16 g_wqlh[EE*256],      g_wqll[EE*256];
__device__ __align__(16) bf16 g_wpah[EE*KRT],      g_wpal[EE*KRT];
__device__ __align__(16) bf16 g_wdch[EE*EE],       g_wdcl[EE*EE];

__device__ __forceinline__ void split1(float x, bf16* h, bf16* l)
{
    bf16 hv = __float2bfloat16(x);
    *h = hv;
    *l = __float2bfloat16(x - __bfloat162float(hv));
}

__device__ __forceinline__ void cvtpk(float x0, float x1, uint32_t& h, uint32_t& l)
{
    bf16 h0 = __float2bfloat16(x0), h1 = __float2bfloat16(x1);
    float l0 = x0 - __bfloat162float(h0), l1 = x1 - __bfloat162float(h1);
    h = ((uint32_t)__bfloat16_as_ushort(h1) << 16) | __bfloat16_as_ushort(h0);
    bf16 g0 = __float2bfloat16(l0), g1 = __float2bfloat16(l1);
    l = ((uint32_t)__bfloat16_as_ushort(g1) << 16) | __bfloat16_as_ushort(g0);
}

// ---------------- generic fp32 -> hi/lo ----------------
__global__ void cvt_split(const float* __restrict__ s, bf16* __restrict__ h,
                          bf16* __restrict__ l, int n)
{
    int i = blockIdx.x * blockDim.x + threadIdx.x;
    if (i < n) split1(s[i], h + i, l + i);
}

// ---------------- embedding ----------------
__global__ void embed_kernel(const float* __restrict__ dep, const float* __restrict__ cus,
                             const float* __restrict__ Wd, const float* __restrict__ bd,
                             const float* __restrict__ Wc, const float* __restrict__ bc)
{
    int idx = blockIdx.x * blockDim.x + threadIdx.x;
    if (idx >= BB*NN*EE) return;
    int e = idx % EE;
    int n = (idx / EE) % NN;
    int b = idx / (EE*NN);
    float acc;
    if (n < DEPOTN) {
        const float* f = dep + ((long)b*DEPOTN + n) * 4;
        acc = bd[e];
        #pragma unroll
        for (int j = 0; j < 4; j++) acc += f[j] * Wd[e*4 + j];
    } else {
        const float* f = cus + ((long)b*CUSTN + (n - DEPOTN)) * 3;
        acc = bc[e];
        #pragma unroll
        for (int j = 0; j < 3; j++) acc += f[j] * Wc[e*3 + j];
    }
    g_x[idx] = acc;
    split1(acc, g_xh + idx, g_xl + idx);
}

// ---------------- weight packing ----------------
__global__ void pack_w(const float* __restrict__ Wq, const float* __restrict__ Wk,
                       const float* __restrict__ Wv, const float* __restrict__ dWk,
                       const float* __restrict__ dWv)
{
    int idx = blockIdx.x * blockDim.x + threadIdx.x;
    const int tot1 = NLL*384*EE;
    if (idx < tot1) {
        int col = idx % EE;
        int row = (idx / EE) % 384;
        int l   = idx / (EE*384);
        float v;
        if (row < 128)      v = Wq[((long)l*EE + row)*EE + col];
        else if (row < 256) v = Wk[((long)l*EE + row-128)*EE + col];
        else                v = Wv[((long)l*EE + row-256)*EE + col];
        split1(v, g_wqkvh + idx, g_wqkvl + idx);
    } else {
        int j = idx - tot1;
        if (j < 256*EE) {
            int col = j % EE;
            int row = j / EE;
            float v = (row < 128) ? dWk[row*EE + col] : dWv[(row-128)*EE + col];
            split1(v, g_wkvh + j, g_wkvl + j);
        }
    }
}

__global__ void padw_kernel(const float* __restrict__ Wr)
{
    int idx = blockIdx.x * blockDim.x + threadIdx.x;
    if (idx >= EE*KRT) return;
    int rr = idx / KRT, cc = idx % KRT;
    float v = (cc < 257) ? Wr[rr*257 + cc] : 0.f;
    split1(v, g_wpah + idx, g_wpal + idx);
}

// ---------------- MMA primitives ----------------
#define LDM4(r0,r1,r2,r3,addr) \
    asm volatile("ldmatrix.sync.aligned.m8n8.x4.shared.b16 {%0,%1,%2,%3},[%4];" \
                 : "=r"(r0),"=r"(r1),"=r"(r2),"=r"(r3) : "r"(addr))
#define LDM2(r0,r1,addr) \
    asm volatile("ldmatrix.sync.aligned.m8n8.x2.shared.b16 {%0,%1},[%2];" \
                 : "=r"(r0),"=r"(r1) : "r"(addr))
#define MMA16816(c,a,b) \
    asm volatile("mma.sync.aligned.m16n8k16.row.col.f32.bf16.bf16.f32 " \
                 "{%0,%1,%2,%3},{%4,%5,%6,%7},{%8,%9},{%0,%1,%2,%3};" \
                 : "+f"((c)[0]),"+f"((c)[1]),"+f"((c)[2]),"+f"((c)[3]) \
                 : "r"((a)[0]),"r"((a)[1]),"r"((a)[2]),"r"((a)[3]), "r"((b)[0]),"r"((b)[1]))

// ---------------- TC GEMM v2 (proven) ----------------
#define MAT 10240
#define STAGE 40960

__global__ __launch_bounds__(256, 2)
void gemm_tc2(const bf16* __restrict__ Ahi, const bf16* __restrict__ Alo,
              const bf16* __restrict__ Bhi, const bf16* __restrict__ Blo,
              const float* __restrict__ bias, const float* __restrict__ resid,
              float* __restrict__ C, bf16* __restrict__ Chi, bf16* __restrict__ Clo,
              int R, int K, int Cout, long sA, long sB, long sC, int relu)
{
    int bz = blockIdx.z;
    Ahi += (long)bz*sA; Alo += (long)bz*sA;
    Bhi += (long)bz*sB; Blo += (long)bz*sB;
    if (C)     C   += (long)bz*sC;
    if (Chi) { Chi += (long)bz*sC; Clo += (long)bz*sC; }
    if (resid) resid += (long)bz*sC;

    extern __shared__ bf16 smb[];
    uint32_t sb = (uint32_t)__cvta_generic_to_shared(smb);

    int tid = threadIdx.x, lane = tid & 31, warp = tid >> 5;
    int wm = warp >> 2, wn = warp & 3;
    int rowBase = blockIdx.x * 128, colBase = blockIdx.y * 128;

    float c[4][4][4];
    #pragma unroll
    for (int i = 0; i < 4; i++)
        #pragma unroll
        for (int j = 0; j < 4; j++)
            { c[i][j][0]=0.f; c[i][j][1]=0.f; c[i][j][2]=0.f; c[i][j][3]=0.f; }

    const bf16* bases[4] = { Ahi, Alo, Bhi, Blo };
    int nk = K >> 5;

    #define FILL(st, kt) do { \
        int k0 = (kt) << 5; \
        _Pragma("unroll") \
        for (int t = 0; t < 8; t++) { \
            int o = tid + t*256; \
            int m = o >> 9, r = (o >> 2) & 127, seg = o & 3; \
            int gr = ((m < 2) ? rowBase : colBase) + r; \
            int lim = (m < 2) ? R : Cout; \
            long grc = (gr < lim) ? gr : 0; \
            const bf16* src = bases[m] + grc*K + k0 + seg*8; \
            uint32_t dst = sb + (st)*STAGE + m*MAT + r*80 + seg*16; \
            int nbytes = (gr < lim) ? 16 : 0; \
            asm volatile("cp.async.ca.shared.global [%0],[%1],16,%2;" \
                         :: "r"(dst), "l"(src), "r"(nbytes)); \
        } \
        asm volatile("cp.async.commit_group;"); \
    } while (0)

    FILL(0, 0);

    int ar = lane & 15, ak = (lane >> 4);
    int br = lane & 7,  bk = (lane >> 3) & 1;

    for (int kt = 0; kt < nk; kt++) {
        int st = kt & 1;
        if (kt + 1 < nk) {
            FILL(st ^ 1, kt + 1);
            asm volatile("cp.async.wait_group 1;");
        } else {
            asm volatile("cp.async.wait_group 0;");
        }
        __syncthreads();

        uint32_t aOff = sb + st*STAGE;
        uint32_t bOff = aOff + 2*MAT;
        #pragma unroll
        for (int ks = 0; ks < 2; ks++) {
            uint32_t Ah[4][4], Al[4][4];
            #pragma unroll
            for (int i = 0; i < 4; i++) {
                uint32_t ad = aOff + (uint32_t)((wm*64 + i*16 + ar)*80 + ak*16 + ks*32);
                LDM4(Ah[i][0], Ah[i][1], Ah[i][2], Ah[i][3], ad);
                LDM4(Al[i][0], Al[i][1], Al[i][2], Al[i][3], ad + MAT);
            }
            #pragma unroll
            for (int j = 0; j < 4; j++) {
                uint32_t bd = bOff + (uint32_t)((wn*32 + j*8 + br)*80 + bk*16 + ks*32);
                uint32_t Bh[2], Bl[2];
                LDM2(Bh[0], Bh[1], bd);
                LDM2(Bl[0], Bl[1], bd + MAT);
                #pragma unroll
                for (int i = 0; i < 4; i++) {
                    MMA16816(c[i][j], Ah[i], Bh);
                    MMA16816(c[i][j], Ah[i], Bl);
                    MMA16816(c[i][j], Al[i], Bh);
                }
            }
        }
        __syncthreads();
    }

    int gid = lane >> 2, tig = lane & 3;
    #pragma unroll
    for (int i = 0; i < 4; i++) {
        int rbase = rowBase + wm*64 + i*16 + gid;
        #pragma unroll
        for (int j = 0; j < 4; j++) {
            int c0 = colBase + wn*32 + j*8 + tig*2;
            if (c0 >= Cout) continue;
            #pragma unroll
            for (int hh = 0; hh < 2; hh++) {
                int row = rbase + hh*8;
                if (row >= R) continue;
                float v0 = c[i][j][2*hh], v1 = c[i][j][2*hh+1];
                if (bias)  { v0 += bias[c0]; v1 += bias[c0+1]; }
                if (resid) {
                    float2 rv = *(const float2*)(resid + (long)row*Cout + c0);
                    v0 += rv.x; v1 += rv.y;
                }
                if (relu) { v0 = fmaxf(v0, 0.f); v1 = fmaxf(v1, 0.f); }
                if (C) *(float2*)(C + (long)row*Cout + c0) = make_float2(v0, v1);
                if (Chi) {
                    uint32_t hp, lp;
                    cvtpk(v0, v1, hp, lp);
                    *(uint32_t*)(Chi + (long)row*Cout + c0) = hp;
                    *(uint32_t*)(Clo + (long)row*Cout + c0) = lp;
                }
            }
        }
    }
}

// ---------------- attention via MMA (FA2-style, hi/lo bf16) ----------------
#define KPAD 576
#define KLO_B  27648
#define VHI_B  55296
#define VLO_B  18688
#define QHI_B  92672
#define QLO_B  6144
#define ATTN2_SMEM 104960

__global__ __launch_bounds__(256)
void attn_mma(const float* __restrict__ Q, const float* __restrict__ Q2,
              const float* __restrict__ flagv, int ldq,
              const float* __restrict__ Kt, int ldk,
              const float* __restrict__ Vt, int ldv,
              const float* __restrict__ mask,
              bf16* __restrict__ Oh, bf16* __restrict__ Ol)
{
    int qb = blockIdx.x * 128;
    int h = blockIdx.y, b = blockIdx.z;
    extern __shared__ bf16 sm2[];
    uint32_t sb = (uint32_t)__cvta_generic_to_shared(sm2);
    int tid = threadIdx.x;

    const int KHI_E = 0, KLO_E = 13824, VHI_E = 27648, VLO_E = 36992;
    const int QHI_E = 46336, QLO_E = 49408;

    const float* Kg = Kt + (long)b*NN*ldk + h*DKK;
    const float* Vg = Vt + (long)b*NN*ldv + h*DKK;
    for (int i = tid; i < KPAD*DKK; i += 256) {
        int key = i >> 4, d = i & 15;
        float kv = (key < NN) ? Kg[(long)key*ldk + d] : 0.f;
        float vv = (key < NN) ? Vg[(long)key*ldv + d] : 0.f;
        bf16 kh = __float2bfloat16(kv);
        bf16 kl = __float2bfloat16(kv - __bfloat162float(kh));
        bf16 vh = __float2bfloat16(vv);
        bf16 vl = __float2bfloat16(vv - __bfloat162float(vh));
        sm2[KHI_E + key*24 + d] = kh;
        sm2[KLO_E + key*24 + d] = kl;
        sm2[VHI_E + d*584 + key] = vh;
        sm2[VLO_E + d*584 + key] = vl;
    }
    const float* Qg = Q + (long)b*NN*ldq + h*DKK;
    const float* Qg2 = Q2 ? (Q2 + (long)b*NN*ldq + h*DKK) : (const float*)0;
    for (int i = tid; i < 128*DKK; i += 256) {
        int row = i >> 4, d = i & 15;
        int q = qb + row;
        float qv = 0.f;
        if (q < NN) {
            qv = Qg[(long)q*ldq + d];
            if (Qg2) {
                float f = flagv[(long)b*MM + q];
                qv = f*qv + (1.f - f)*Qg2[(long)q*ldq + d];
            }
        }
        bf16 qh = __float2bfloat16(qv);
        sm2[QHI_E + row*24 + d] = qh;
        sm2[QLO_E + row*24 + d] = __float2bfloat16(qv - __bfloat162float(qh));
    }
    __syncthreads();

    int warp = tid >> 5, lane = tid & 31;
    if (qb + warp*16 >= NN) return;   // tail-wave skip (no block syncs below)

    int g = lane >> 2;
    int ar = lane & 15, ak = lane >> 4;
    int br = lane & 7,  bk = (lane >> 3) & 1;
    const unsigned FULL = 0xffffffffu;

    uint32_t Qh[4], Ql[4];
    {
        uint32_t qa = sb + QHI_B + (uint32_t)((warp*16 + ar)*48 + ak*16);
        LDM4(Qh[0], Qh[1], Qh[2], Qh[3], qa);
        LDM4(Ql[0], Ql[1], Ql[2], Ql[3], qa + QLO_B);
    }

    float o[2][4];
    #pragma unroll
    for (int n = 0; n < 2; n++) { o[n][0]=0.f; o[n][1]=0.f; o[n][2]=0.f; o[n][3]=0.f; }
    float mrow[2] = { -1e30f, -1e30f };
    float lrow[2] = { 0.f, 0.f };

    int qr0 = qb + warp*16 + g;
    int qm0 = (qr0 < NN) ? qr0 : NN-1;
    int qm1 = (qr0+8 < NN) ? qr0+8 : NN-1;
    const float* mk0 = mask ? (mask + ((long)(b*MM + qm0))*NN) : (const float*)0;
    const float* mk1 = mask ? (mask + ((long)(b*MM + qm1))*NN) : (const float*)0;

    #pragma unroll 1
    for (int c = 0; c < 9; c++) {
        float s[8][4];
        #pragma unroll
        for (int t = 0; t < 8; t++) {
            uint32_t ka = sb + (uint32_t)((c*64 + t*8 + br)*48 + bk*16);
            uint32_t bh[2], bl[2];
            LDM2(bh[0], bh[1], ka);
            LDM2(bl[0], bl[1], ka + KLO_B);
            s[t][0]=0.f; s[t][1]=0.f; s[t][2]=0.f; s[t][3]=0.f;
            MMA16816(s[t], Qh, bh);
            MMA16816(s[t], Qh, bl);
            MMA16816(s[t], Ql, bh);
        }
        float mx0 = -1e30f, mx1 = -1e30f;
        #pragma unroll
        for (int t = 0; t < 8; t++) {
            if (c < 8 || t == 0) {
                s[t][0]*=0.25f; s[t][1]*=0.25f; s[t][2]*=0.25f; s[t][3]*=0.25f;
                if (mask) {
                    int j = c*64 + t*8 + (lane&3)*2;
                    float2 m0 = *(const float2*)(mk0 + j);
                    float2 m1 = *(const float2*)(mk1 + j);
                    s[t][0]+=m0.x; s[t][1]+=m0.y; s[t][2]+=m1.x; s[t][3]+=m1.y;
                }
            } else {
                s[t][0]=-1e30f; s[t][1]=-1e30f; s[t][2]=-1e30f; s[t][3]=-1e30f;
            }
            mx0 = fmaxf(mx0, fmaxf(s[t][0], s[t][1]));
            mx1 = fmaxf(mx1, fmaxf(s[t][2], s[t][3]));
        }
        mx0 = fmaxf(mx0, __shfl_xor_sync(FULL, mx0, 1));
        mx0 = fmaxf(mx0, __shfl_xor_sync(FULL, mx0, 2));
        mx1 = fmaxf(mx1, __shfl_xor_sync(FULL, mx1, 1));
        mx1 = fmaxf(mx1, __shfl_xor_sync(FULL, mx1, 2));
        float mn0 = fmaxf(mrow[0], mx0), mn1 = fmaxf(mrow[1], mx1);
        float f0 = __expf(mrow[0] - mn0), f1 = __expf(mrow[1] - mn1);
        mrow[0] = mn0; mrow[1] = mn1;
        float rs0 = 0.f, rs1 = 0.f;
        #pragma unroll
        for (int t = 0; t < 8; t++) {
            s[t][0] = __expf(s[t][0] - mn0);
            s[t][1] = __expf(s[t][1] - mn0);
            s[t][2] = __expf(s[t][2] - mn1);
            s[t][3] = __expf(s[t][3] - mn1);
            rs0 += s[t][0] + s[t][1];
            rs1 += s[t][2] + s[t][3];
        }
        rs0 += __shfl_xor_sync(FULL, rs0, 1); rs0 += __shfl_xor_sync(FULL, rs0, 2);
        rs1 += __shfl_xor_sync(FULL, rs1, 1); rs1 += __shfl_xor_sync(FULL, rs1, 2);
        lrow[0] = lrow[0]*f0 + rs0;
        lrow[1] = lrow[1]*f1 + rs1;
        #pragma unroll
        for (int n = 0; n < 2; n++) {
            o[n][0]*=f0; o[n][1]*=f0; o[n][2]*=f1; o[n][3]*=f1;
        }
        #pragma unroll
        for (int ss = 0; ss < 4; ss++) {
            uint32_t pah[4], pal[4];
            cvtpk(s[2*ss][0],   s[2*ss][1],   pah[0], pal[0]);
            cvtpk(s[2*ss][2],   s[2*ss][3],   pah[1], pal[1]);
            cvtpk(s[2*ss+1][0], s[2*ss+1][1], pah[2], pal[2]);
            cvtpk(s[2*ss+1][2], s[2*ss+1][3], pah[3], pal[3]);
            #pragma unroll
            for (int n = 0; n < 2; n++) {
                uint32_t va = sb + VHI_B +
                    (uint32_t)((n*8 + br)*1168 + (c*64 + ss*16)*2 + bk*16);
                uint32_t vh[2], vl[2];
                LDM2(vh[0], vh[1], va);
                LDM2(vl[0], vl[1], va + VLO_B);
                MMA16816(o[n], pah, vh);
                MMA16816(o[n], pah, vl);
                MMA16816(o[n], pal, vh);
            }
        }
    }

    float i0 = 1.f / lrow[0], i1 = 1.f / lrow[1];
    #pragma unroll
    for (int n = 0; n < 2; n++) {
        int d = h*DKK + n*8 + (lane&3)*2;
        if (qr0 < NN) {
            uint32_t hp, lp;
            cvtpk(o[n][0]*i0, o[n][1]*i0, hp, lp);
            long off = ((long)(b*NN + qr0))*EE + d;
            *(uint32_t*)(Oh + off) = hp;
            *(uint32_t*)(Ol + off) = lp;
        }
        if (qr0 + 8 < NN) {
            uint32_t hp, lp;
            cvtpk(o[n][2]*i1, o[n][3]*i1, hp, lp);
            long off = ((long)(b*NN + qr0 + 8))*EE + d;
            *(uint32_t*)(Oh + off) = hp;
            *(uint32_t*)(Ol + off) = lp;
        }
    }
}

// ---------------- instance norm: high-parallelism fused stats ----------------
// grid (BB, 4): block owns batch b, channel group eg (32 channels), all nodes.
__global__ __launch_bounds__(512)
void inorm_sf2(const float* __restrict__ Y)
{
    int b = blockIdx.x, eg = blockIdx.y;
    int tid = threadIdx.x;
    int el = tid & 31, nch = tid >> 5;       // 16 n-chunks
    int e = eg*32 + el;
    float s1 = 0.f, s2 = 0.f;
    for (int n = nch; n < NN; n += 16) {
        float v = Y[((long)(b*NN + n))*EE + e];
        s1 += v; s2 += v*v;
    }
    __shared__ float sh1[512], sh2[512];
    sh1[tid] = s1; sh2[tid] = s2;
    __syncthreads();
    #pragma unroll
    for (int off = 256; off >= 32; off >>= 1) {
        if (tid < off) { sh1[tid] += sh1[tid+off]; sh2[tid] += sh2[tid+off]; }
        __syncthreads();
    }
    if (tid < 32) {
        float t1 = sh1[tid], t2 = sh2[tid];
        float mean = t1 / (float)NN;
        float var  = t2 / (float)NN - mean*mean;
        int ee = eg*32 + tid;
        g_stats[(b*EE+ee)*2]   = mean;
        g_stats[(b*EE+ee)*2+1] = rsqrtf(var + 1e-5f);
    }
}

__global__ void inorm_apply(const float* __restrict__ Y, const float* __restrict__ gg,
                            const float* __restrict__ bt, float* __restrict__ Xo,
                            bf16* __restrict__ Xh, bf16* __restrict__ Xl)
{
    int idx = blockIdx.x * blockDim.x + threadIdx.x;
    if (idx >= BB*NN*EE) return;
    int e = idx % EE;
    int b = idx / (NN*EE);
    float mean = g_stats[(b*EE+e)*2];
    float istd = g_stats[(b*EE+e)*2+1];
    float v = (Y[idx] - mean) * istd * gg[e] + bt[e];
    Xo[idx] = v;
    split1(v, Xh + idx, Xl + idx);
}

// ---------------- decoder helpers ----------------
// enc_mean over nodes of the encoder output is EXACTLY n2b[last layer]
// (instance norm makes the node-mean of (Y-mu)*istd*g equal zero).
__global__ void build_cat(const float* __restrict__ loadv, const int* __restrict__ cur,
                          const int* __restrict__ subn, const int* __restrict__ subl,
                          const int* __restrict__ sel, const float* __restrict__ encmean)
{
    int r = blockIdx.x;
    int b = r / MM;
    int e = threadIdx.x;
    int c = cur[r];
    float le = g_x[((long)(b*NN + c))*EE + e];

    int len = subl[r];
    const int* nodes = subn + (long)r*LL;
    float ssum = 0.f; int cnt = 0;
    for (int l = 0; l < LL; l++) {
        int nd = nodes[l];
        if (l < len && nd >= DEPOTN) {
            ssum += g_x[((long)(b*NN + nd))*EE + e];
            cnt++;
        }
    }
    float cntf = (cnt > 0) ? (float)cnt : 1.f;
    float smean = ssum / cntf;

    long bl = (long)r*256, br = (long)r*KRT;
    split1(le,    g_catlh + bl + e,       g_catll + bl + e);
    split1(smean, g_catlh + bl + 128 + e, g_catll + bl + 128 + e);
    split1(le,    g_catrh + br + e,       g_catrl + br + e);
    split1(encmean[e], g_catrh + br + 128 + e, g_catrl + br + 128 + e);
    if (e == 0) split1(loadv[r], g_catrh + br + 256, g_catrl + br + 256);
    if (e >= 1 && e < 32) { g_catrh[br + 256 + e] = __float2bfloat16(0.f);
                            g_catrl[br + 256 + e] = __float2bfloat16(0.f); }
    if (e == 0) {
        int s2 = sel[(long)r*4 + 2];
        g_flag[r] = (s2 >= DEPOTN && c < DEPOTN) ? 1.f : 0.f;
    }
}

// ---------------- final tanh-clip + mask + softmax ----------------
__global__ void final_kernel(const float* __restrict__ mask, float* __restrict__ out)
{
    int r = blockIdx.x;
    int tid = threadIdx.x;
    __shared__ float buf[NN];
    __shared__ float red[256];
    const float* sn = g_sn + (long)r*NN;
    const float* mk = mask + (long)r*NN;
    const float invs = 0.08838834764831845f;

    float lm = -1e30f;
    for (int j = tid; j < NN; j += 256) {
        float v = 10.f * tanhf(sn[j] * invs) + mk[j];
        buf[j] = v;
        lm = fmaxf(lm, v);
    }
    red[tid] = lm; __syncthreads();
    for (int off = 128; off > 0; off >>= 1) {
        if (tid < off) red[tid] = fmaxf(red[tid], red[tid+off]);
        __syncthreads();
    }
    float mx = red[0]; __syncthreads();

    float ls = 0.f;
    for (int j = tid; j < NN; j += 256) {
        float e0 = __expf(buf[j] - mx);
        buf[j] = e0; ls += e0;
    }
    red[tid] = ls; __syncthreads();
    for (int off = 128; off > 0; off >>= 1) {
        if (tid < off) red[tid] += red[tid+off];
        __syncthreads();
    }
    float inv = 1.f / red[0];
    for (int j = tid; j < NN; j += 256)
        out[(long)r*NN + j] = buf[j] * inv;
}

// ---------------- host ----------------
#define GEMM_SMEM 81920

static void launch_tc(const bf16* Ah, const bf16* Al, const bf16* Bh, const bf16* Bl,
                      const float* bias, const float* resid,
                      float* C, bf16* Ch, bf16* Cl,
                      int R, int K, int Cout, int batch,
                      long sA, long sB, long sC, int relu)
{
    dim3 grid((R + 127) / 128, (Cout + 127) / 128, batch);
    gemm_tc2<<<grid, 256, GEMM_SMEM>>>(Ah, Al, Bh, Bl, bias, resid, C, Ch, Cl,
                                       R, K, Cout, sA, sB, sC, relu);
}

#define SYM(p, s) cudaGetSymbolAddress((void**)&p, s)

extern "C" void kernel_launch(void* const* d_in, const int* in_sizes, int n_in,
                              void* d_out, int out_size)
{
    const float* depot  = (const float*)d_in[0];
    const float* cust   = (const float*)d_in[1];
    const float* mask   = (const float*)d_in[2];
    const float* loadv  = (const float*)d_in[3];
    const int*   cur    = (const int*)d_in[4];
    const int*   subn   = (const int*)d_in[5];
    const int*   subl   = (const int*)d_in[6];
    const int*   sel    = (const int*)d_in[7];
    const float* edW    = (const float*)d_in[8];
    const float* edb    = (const float*)d_in[9];
    const float* ecW    = (const float*)d_in[10];
    const float* ecb    = (const float*)d_in[11];
    const float* Wq     = (const float*)d_in[12];
    const float* Wk     = (const float*)d_in[13];
    const float* Wv     = (const float*)d_in[14];
    const float* Wc     = (const float*)d_in[15];
    const float* Wcb    = (const float*)d_in[16];
    const float* n1g    = (const float*)d_in[17];
    const float* n1b    = (const float*)d_in[18];
    const float* fW1    = (const float*)d_in[19];
    const float* fb1    = (const float*)d_in[20];
    const float* fW2    = (const float*)d_in[21];
    const float* fb2    = (const float*)d_in[22];
    const float* n2g    = (const float*)d_in[23];
    const float* n2b    = (const float*)d_in[24];
    const float* dWqloc = (const float*)d_in[25];
    const float* dWqrt  = (const float*)d_in[26];
    const float* dWk    = (const float*)d_in[27];
    const float* dWv    = (const float*)d_in[28];
    const float* dWc    = (const float*)d_in[29];
    const float* dWcb   = (const float*)d_in[30];
    float* out = (float*)d_out;

    float *px, *pqkv, *py, *px1, *pkvd, *pqloc, *pqrout, *pflag, *psn;
    SYM(px, g_x); SYM(pqkv, g_qkv); SYM(py, g_y); SYM(px1, g_x1);
    SYM(pkvd, g_kvd); SYM(pqloc, g_qloc); SYM(pqrout, g_qrout);
    SYM(pflag, g_flag); SYM(psn, g_sn);

    bf16 *pxh,*pxl, *px1h,*px1l, *pmhh,*pmhl, *pffhh,*pffhl, *pattnh,*pattnl;
    bf16 *pscoreh,*pscorel, *pcatlh,*pcatll, *pcatrh,*pcatrl;
    bf16 *pwqkvh,*pwqkvl, *pwch,*pwcl, *pf1h,*pf1l, *pf2h,*pf2l;
    bf16 *pwkvh,*pwkvl, *pwqlh,*pwqll, *pwpah,*pwpal, *pwdch,*pwdcl;
    SYM(pxh, g_xh); SYM(pxl, g_xl); SYM(px1h, g_x1h); SYM(px1l, g_x1l);
    SYM(pmhh, g_mhh); SYM(pmhl, g_mhl); SYM(pffhh, g_ffhh); SYM(pffhl, g_ffhl);
    SYM(pattnh, g_attnh); SYM(pattnl, g_attnl);
    SYM(pscoreh, g_scoreh); SYM(pscorel, g_scorel);
    SYM(pcatlh, g_catlh); SYM(pcatll, g_catll); SYM(pcatrh, g_catrh); SYM(pcatrl, g_catrl);
    SYM(pwqkvh, g_wqkvh); SYM(pwqkvl, g_wqkvl); SYM(pwch, g_wch); SYM(pwcl, g_wcl);
    SYM(pf1h, g_f1h); SYM(pf1l, g_f1l); SYM(pf2h, g_f2h); SYM(pf2l, g_f2l);
    SYM(pwkvh, g_wkvh); SYM(pwkvl, g_wkvl); SYM(pwqlh, g_wqlh); SYM(pwqll, g_wqll);
    SYM(pwpah, g_wpah); SYM(pwpal, g_wpal); SYM(pwdch, g_wdch); SYM(pwdcl, g_wdcl);

    const int R = BB * NN;
    const int TOT = BB * NN * EE;
    const int NQT = (NN + 127) / 128;
    static int smem_set = 0;
    if (!smem_set) {
        cudaFuncSetAttribute(attn_mma, cudaFuncAttributeMaxDynamicSharedMemorySize, ATTN2_SMEM);
        cudaFuncSetAttribute(gemm_tc2, cudaFuncAttributeMaxDynamicSharedMemorySize, GEMM_SMEM);
        smem_set = 1;
    }

    // ---- launches 0-2 (hidden offset = 2, so profiled launch is my #3) ----
    embed_kernel<<<(TOT + 255)/256, 256>>>(depot, cust, edW, edb, ecW, ecb);     // 0
    pack_w<<<(NLL*384*EE + 256*EE + 255)/256, 256>>>(Wq, Wk, Wv, dWk, dWv);      // 1
    cvt_split<<<(NLL*EE*EE + 255)/256, 256>>>(Wc,  pwch, pwcl, NLL*EE*EE);       // 2

    // ---- my launch 3: layer-0 QKV GEMM — ncu -s 5 target ----
    launch_tc(pxh, pxl, pwqkvh, pwqkvl, 0, 0, pqkv, 0, 0, R, EE, 384, 1, 0, 0, 0, 0);

    // ---- remaining one-time converts ----
    padw_kernel<<<(EE*KRT + 255)/256, 256>>>(dWqrt);
    cvt_split<<<(NLL*FFHH*EE + 255)/256, 256>>>(fW1, pf1h, pf1l, NLL*FFHH*EE);
    cvt_split<<<(NLL*EE*FFHH + 255)/256, 256>>>(fW2, pf2h, pf2l, NLL*EE*FFHH);
    cvt_split<<<(EE*256 + 255)/256, 256>>>(dWqloc, pwqlh, pwqll, EE*256);
    cvt_split<<<(EE*EE + 255)/256, 256>>>(dWc, pwdch, pwdcl, EE*EE);

    // ---- encoder ----
    for (int i = 0; i < NLL; i++) {
        if (i > 0)
            launch_tc(pxh, pxl, pwqkvh + (long)i*384*EE, pwqkvl + (long)i*384*EE,
                      0, 0, pqkv, 0, 0, R, EE, 384, 1, 0, 0, 0, 0);
        attn_mma<<<dim3(NQT, HH, BB), 256, ATTN2_SMEM>>>(
            pqkv, (const float*)0, (const float*)0, 384,
            pqkv + 128, 384, pqkv + 256, 384, (const float*)0, pmhh, pmhl);
        launch_tc(pmhh, pmhl, pwch + (long)i*EE*EE, pwcl + (long)i*EE*EE,
                  Wcb + (long)i*EE, px, py, 0, 0, R, EE, EE, 1, 0, 0, 0, 0);
        inorm_sf2<<<dim3(BB, 4), 512>>>(py);
        inorm_apply<<<(TOT + 255)/256, 256>>>(py, n1g + (long)i*EE, n1b + (long)i*EE,
                                              px1, px1h, px1l);
        launch_tc(px1h, px1l, pf1h + (long)i*FFHH*EE, pf1l + (long)i*FFHH*EE,
                  fb1 + (long)i*FFHH, 0, 0, pffhh, pffhl, R, EE, FFHH, 1, 0, 0, 0, 1);
        launch_tc(pffhh, pffhl, pf2h + (long)i*EE*FFHH, pf2l + (long)i*EE*FFHH,
                  fb2 + (long)i*EE, px1, py, 0, 0, R, FFHH, EE, 1, 0, 0, 0, 0);
        inorm_sf2<<<dim3(BB, 4), 512>>>(py);
        inorm_apply<<<(TOT + 255)/256, 256>>>(py, n2g + (long)i*EE, n2b + (long)i*EE,
                                              px, pxh, pxl);
    }

    // ---- decoder ----
    launch_tc(pxh, pxl, pwkvh, pwkvl, 0, 0, pkvd, 0, 0, R, EE, 256, 1, 0, 0, 0, 0);
    // enc_mean == n2b[last layer] exactly (instance-norm identity)
    build_cat<<<BB*MM, EE>>>(loadv, cur, subn, subl, sel, n2b + (long)(NLL-1)*EE);
    launch_tc(pcatlh, pcatll, pwqlh, pwqll, 0, 0, pqloc, 0, 0, R, 256, EE, 1, 0, 0, 0, 0);
    launch_tc(pcatrh, pcatrl, pwpah, pwpal, 0, 0, pqrout, 0, 0, R, KRT, EE, 1, 0, 0, 0, 0);
    attn_mma<<<dim3(NQT, HH, BB), 256, ATTN2_SMEM>>>(
        pqloc, pqrout, pflag, 128, pkvd, 256, pkvd + 128, 256, mask, pattnh, pattnl);
    launch_tc(pattnh, pattnl, pwdch, pwdcl, dWcb, 0, 0, pscoreh, pscorel,
              R, EE, EE, 1, 0, 0, 0, 0);
    launch_tc(pscoreh, pscorel, pxh, pxl, 0, 0, psn, 0, 0, MM, EE, NN, BB,
              (long)MM*EE, (long)NN*EE, (long)MM*NN, 0);
    final_kernel<<<BB*MM, 256>>>(mask, out);
}

// round 11
// speedup vs baseline: 1.4727x; 1.0223x over previous
#include <cuda_runtime.h>
#include <cuda_bf16.h>
#include <math.h>
#include <stdint.h>

#define BB 32
#define NN 520
#define DEPOTN 20
#define CUSTN 500
#define EE 128
#define HH 8
#define DKK 16
#define FFHH 512
#define NLL 6
#define MM 520
#define LL 40
#define KRT 288

typedef __nv_bfloat16 bf16;

// ---------------- fp32 scratch ----------------
__device__ __align__(16) float g_x   [BB*NN*EE];
__device__ __align__(16) float g_qkv [BB*NN*384];
__device__ __align__(16) float g_y   [BB*NN*EE];
__device__ __align__(16) float g_x1  [BB*NN*EE];
__device__ __align__(16) float g_stats[BB*EE*2];
__device__ __align__(16) float g_kvd [BB*NN*256];
__device__ __align__(16) float g_qloc [BB*MM*EE];
__device__ __align__(16) float g_qrout[BB*MM*EE];
__device__ __align__(16) float g_flag [BB*MM];
__device__ __align__(16) float g_sn   [BB*MM*NN];

// ---------------- bf16 hi/lo scratch ----------------
__device__ __align__(16) bf16 g_xh[BB*NN*EE],      g_xl[BB*NN*EE];
__device__ __align__(16) bf16 g_x1h[BB*NN*EE],     g_x1l[BB*NN*EE];
__device__ __align__(16) bf16 g_mhh[BB*NN*EE],     g_mhl[BB*NN*EE];
__device__ __align__(16) bf16 g_ffhh[BB*NN*FFHH],  g_ffhl[BB*NN*FFHH];
__device__ __align__(16) bf16 g_attnh[BB*MM*EE],   g_attnl[BB*MM*EE];
__device__ __align__(16) bf16 g_scoreh[BB*MM*EE],  g_scorel[BB*MM*EE];
__device__ __align__(16) bf16 g_catlh[BB*MM*256],  g_catll[BB*MM*256];
__device__ __align__(16) bf16 g_catrh[BB*MM*KRT],  g_catrl[BB*MM*KRT];
__device__ __align__(16) bf16 g_wqkvh[NLL*384*EE], g_wqkvl[NLL*384*EE];
__device__ __align__(16) bf16 g_wch[NLL*EE*EE],    g_wcl[NLL*EE*EE];
__device__ __align__(16) bf16 g_f1h[NLL*FFHH*EE],  g_f1l[NLL*FFHH*EE];
__device__ __align__(16) bf16 g_f2h[NLL*EE*FFHH],  g_f2l[NLL*EE*FFHH];
__device__ __align__(16) bf16 g_wkvh[256*EE],      g_wkvl[256*EE];
__device__ __align__(16) bf16 g_wqlh[EE*256],      g_wqll[EE*256];
__device__ __align__(16) bf16 g_wpah[EE*KRT],      g_wpal[EE*KRT];
__device__ __align__(16) bf16 g_wdch[EE*EE],       g_wdcl[EE*EE];

__device__ __forceinline__ void split1(float x, bf16* h, bf16* l)
{
    bf16 hv = __float2bfloat16(x);
    *h = hv;
    *l = __float2bfloat16(x - __bfloat162float(hv));
}

__device__ __forceinline__ void cvtpk(float x0, float x1, uint32_t& h, uint32_t& l)
{
    bf16 h0 = __float2bfloat16(x0), h1 = __float2bfloat16(x1);
    float l0 = x0 - __bfloat162float(h0), l1 = x1 - __bfloat162float(h1);
    h = ((uint32_t)__bfloat16_as_ushort(h1) << 16) | __bfloat16_as_ushort(h0);
    bf16 g0 = __float2bfloat16(l0), g1 = __float2bfloat16(l1);
    l = ((uint32_t)__bfloat16_as_ushort(g1) << 16) | __bfloat16_as_ushort(g0);
}

// ---------------- generic fp32 -> hi/lo ----------------
__global__ void cvt_split(const float* __restrict__ s, bf16* __restrict__ h,
                          bf16* __restrict__ l, int n)
{
    int i = blockIdx.x * blockDim.x + threadIdx.x;
    if (i < n) split1(s[i], h + i, l + i);
}

// ---------------- embedding ----------------
__global__ void embed_kernel(const float* __restrict__ dep, const float* __restrict__ cus,
                             const float* __restrict__ Wd, const float* __restrict__ bd,
                             const float* __restrict__ Wc, const float* __restrict__ bc)
{
    int idx = blockIdx.x * blockDim.x + threadIdx.x;
    if (idx >= BB*NN*EE) return;
    int e = idx % EE;
    int n = (idx / EE) % NN;
    int b = idx / (EE*NN);
    float acc;
    if (n < DEPOTN) {
        const float* f = dep + ((long)b*DEPOTN + n) * 4;
        acc = bd[e];
        #pragma unroll
        for (int j = 0; j < 4; j++) acc += f[j] * Wd[e*4 + j];
    } else {
        const float* f = cus + ((long)b*CUSTN + (n - DEPOTN)) * 3;
        acc = bc[e];
        #pragma unroll
        for (int j = 0; j < 3; j++) acc += f[j] * Wc[e*3 + j];
    }
    g_x[idx] = acc;
    split1(acc, g_xh + idx, g_xl + idx);
}

// ---------------- weight packing ----------------
__global__ void pack_w(const float* __restrict__ Wq, const float* __restrict__ Wk,
                       const float* __restrict__ Wv, const float* __restrict__ dWk,
                       const float* __restrict__ dWv)
{
    int idx = blockIdx.x * blockDim.x + threadIdx.x;
    const int tot1 = NLL*384*EE;
    if (idx < tot1) {
        int col = idx % EE;
        int row = (idx / EE) % 384;
        int l   = idx / (EE*384);
        float v;
        if (row < 128)      v = Wq[((long)l*EE + row)*EE + col];
        else if (row < 256) v = Wk[((long)l*EE + row-128)*EE + col];
        else                v = Wv[((long)l*EE + row-256)*EE + col];
        split1(v, g_wqkvh + idx, g_wqkvl + idx);
    } else {
        int j = idx - tot1;
        if (j < 256*EE) {
            int col = j % EE;
            int row = j / EE;
            float v = (row < 128) ? dWk[row*EE + col] : dWv[(row-128)*EE + col];
            split1(v, g_wkvh + j, g_wkvl + j);
        }
    }
}

__global__ void padw_kernel(const float* __restrict__ Wr)
{
    int idx = blockIdx.x * blockDim.x + threadIdx.x;
    if (idx >= EE*KRT) return;
    int rr = idx / KRT, cc = idx % KRT;
    float v = (cc < 257) ? Wr[rr*257 + cc] : 0.f;
    split1(v, g_wpah + idx, g_wpal + idx);
}

// ---------------- MMA primitives ----------------
#define LDM4(r0,r1,r2,r3,addr) \
    asm volatile("ldmatrix.sync.aligned.m8n8.x4.shared.b16 {%0,%1,%2,%3},[%4];" \
                 : "=r"(r0),"=r"(r1),"=r"(r2),"=r"(r3) : "r"(addr))
#define LDM2(r0,r1,addr) \
    asm volatile("ldmatrix.sync.aligned.m8n8.x2.shared.b16 {%0,%1},[%2];" \
                 : "=r"(r0),"=r"(r1) : "r"(addr))
#define MMA16816(c,a,b) \
    asm volatile("mma.sync.aligned.m16n8k16.row.col.f32.bf16.bf16.f32 " \
                 "{%0,%1,%2,%3},{%4,%5,%6,%7},{%8,%9},{%0,%1,%2,%3};" \
                 : "+f"((c)[0]),"+f"((c)[1]),"+f"((c)[2]),"+f"((c)[3]) \
                 : "r"((a)[0]),"r"((a)[1]),"r"((a)[2]),"r"((a)[3]), "r"((b)[0]),"r"((b)[1]))

// ---------------- TC GEMM v3: pass-major MMA scheduling ----------------
#define MAT 10240
#define STAGE 40960

__global__ __launch_bounds__(256, 2)
void gemm_tc2(const bf16* __restrict__ Ahi, const bf16* __restrict__ Alo,
              const bf16* __restrict__ Bhi, const bf16* __restrict__ Blo,
              const float* __restrict__ bias, const float* __restrict__ resid,
              float* __restrict__ C, bf16* __restrict__ Chi, bf16* __restrict__ Clo,
              int R, int K, int Cout, long sA, long sB, long sC, int relu)
{
    int bz = blockIdx.z;
    Ahi += (long)bz*sA; Alo += (long)bz*sA;
    Bhi += (long)bz*sB; Blo += (long)bz*sB;
    if (C)     C   += (long)bz*sC;
    if (Chi) { Chi += (long)bz*sC; Clo += (long)bz*sC; }
    if (resid) resid += (long)bz*sC;

    extern __shared__ bf16 smb[];
    uint32_t sb = (uint32_t)__cvta_generic_to_shared(smb);

    int tid = threadIdx.x, lane = tid & 31, warp = tid >> 5;
    int wm = warp >> 2, wn = warp & 3;
    int rowBase = blockIdx.x * 128, colBase = blockIdx.y * 128;

    float c[4][4][4];
    #pragma unroll
    for (int i = 0; i < 4; i++)
        #pragma unroll
        for (int j = 0; j < 4; j++)
            { c[i][j][0]=0.f; c[i][j][1]=0.f; c[i][j][2]=0.f; c[i][j][3]=0.f; }

    const bf16* bases[4] = { Ahi, Alo, Bhi, Blo };
    int nk = K >> 5;

    #define FILL(st, kt) do { \
        int k0 = (kt) << 5; \
        _Pragma("unroll") \
        for (int t = 0; t < 8; t++) { \
            int o = tid + t*256; \
            int m = o >> 9, r = (o >> 2) & 127, seg = o & 3; \
            int gr = ((m < 2) ? rowBase : colBase) + r; \
            int lim = (m < 2) ? R : Cout; \
            long grc = (gr < lim) ? gr : 0; \
            const bf16* src = bases[m] + grc*K + k0 + seg*8; \
            uint32_t dst = sb + (st)*STAGE + m*MAT + r*80 + seg*16; \
            int nbytes = (gr < lim) ? 16 : 0; \
            asm volatile("cp.async.ca.shared.global [%0],[%1],16,%2;" \
                         :: "r"(dst), "l"(src), "r"(nbytes)); \
        } \
        asm volatile("cp.async.commit_group;"); \
    } while (0)

    FILL(0, 0);

    int ar = lane & 15, ak = (lane >> 4);
    int br = lane & 7,  bk = (lane >> 3) & 1;

    for (int kt = 0; kt < nk; kt++) {
        int st = kt & 1;
        if (kt + 1 < nk) {
            FILL(st ^ 1, kt + 1);
            asm volatile("cp.async.wait_group 1;");
        } else {
            asm volatile("cp.async.wait_group 0;");
        }
        __syncthreads();

        uint32_t aOff = sb + st*STAGE;
        uint32_t bOff = aOff + 2*MAT;
        #pragma unroll
        for (int ks = 0; ks < 2; ks++) {
            uint32_t Ah[4][4], Al[4][4];
            #pragma unroll
            for (int i = 0; i < 4; i++) {
                uint32_t ad = aOff + (uint32_t)((wm*64 + i*16 + ar)*80 + ak*16 + ks*32);
                LDM4(Ah[i][0], Ah[i][1], Ah[i][2], Ah[i][3], ad);
                LDM4(Al[i][0], Al[i][1], Al[i][2], Al[i][3], ad + MAT);
            }
            // j in pairs; pass-major within the pair: dependent-MMA gap = 7
            #pragma unroll
            for (int jp = 0; jp < 2; jp++) {
                uint32_t Bh[2][2], Bl[2][2];
                #pragma unroll
                for (int jj = 0; jj < 2; jj++) {
                    int j = jp*2 + jj;
                    uint32_t bd = bOff + (uint32_t)((wn*32 + j*8 + br)*80 + bk*16 + ks*32);
                    LDM2(Bh[jj][0], Bh[jj][1], bd);
                    LDM2(Bl[jj][0], Bl[jj][1], bd + MAT);
                }
                #pragma unroll
                for (int jj = 0; jj < 2; jj++)
                    #pragma unroll
                    for (int i = 0; i < 4; i++)
                        MMA16816(c[i][jp*2+jj], Ah[i], Bh[jj]);
                #pragma unroll
                for (int jj = 0; jj < 2; jj++)
                    #pragma unroll
                    for (int i = 0; i < 4; i++)
                        MMA16816(c[i][jp*2+jj], Ah[i], Bl[jj]);
                #pragma unroll
                for (int jj = 0; jj < 2; jj++)
                    #pragma unroll
                    for (int i = 0; i < 4; i++)
                        MMA16816(c[i][jp*2+jj], Al[i], Bh[jj]);
            }
        }
        __syncthreads();
    }

    int gid = lane >> 2, tig = lane & 3;
    #pragma unroll
    for (int i = 0; i < 4; i++) {
        int rbase = rowBase + wm*64 + i*16 + gid;
        #pragma unroll
        for (int j = 0; j < 4; j++) {
            int c0 = colBase + wn*32 + j*8 + tig*2;
            if (c0 >= Cout) continue;
            #pragma unroll
            for (int hh = 0; hh < 2; hh++) {
                int row = rbase + hh*8;
                if (row >= R) continue;
                float v0 = c[i][j][2*hh], v1 = c[i][j][2*hh+1];
                if (bias)  { v0 += bias[c0]; v1 += bias[c0+1]; }
                if (resid) {
                    float2 rv = *(const float2*)(resid + (long)row*Cout + c0);
                    v0 += rv.x; v1 += rv.y;
                }
                if (relu) { v0 = fmaxf(v0, 0.f); v1 = fmaxf(v1, 0.f); }
                if (C) *(float2*)(C + (long)row*Cout + c0) = make_float2(v0, v1);
                if (Chi) {
                    uint32_t hp, lp;
                    cvtpk(v0, v1, hp, lp);
                    *(uint32_t*)(Chi + (long)row*Cout + c0) = hp;
                    *(uint32_t*)(Clo + (long)row*Cout + c0) = lp;
                }
            }
        }
    }
}

// ---------------- attention via MMA (pass-major scheduling) ----------------
#define KPAD 576
#define KLO_B  27648
#define VHI_B  55296
#define VLO_B  18688
#define QHI_B  92672
#define QLO_B  6144
#define ATTN2_SMEM 104960

__global__ __launch_bounds__(256)
void attn_mma(const float* __restrict__ Q, const float* __restrict__ Q2,
              const float* __restrict__ flagv, int ldq,
              const float* __restrict__ Kt, int ldk,
              const float* __restrict__ Vt, int ldv,
              const float* __restrict__ mask,
              bf16* __restrict__ Oh, bf16* __restrict__ Ol)
{
    int qb = blockIdx.x * 128;
    int h = blockIdx.y, b = blockIdx.z;
    extern __shared__ bf16 sm2[];
    uint32_t sb = (uint32_t)__cvta_generic_to_shared(sm2);
    int tid = threadIdx.x;

    const int KHI_E = 0, KLO_E = 13824, VHI_E = 27648, VLO_E = 36992;
    const int QHI_E = 46336, QLO_E = 49408;

    const float* Kg = Kt + (long)b*NN*ldk + h*DKK;
    const float* Vg = Vt + (long)b*NN*ldv + h*DKK;
    for (int i = tid; i < KPAD*DKK; i += 256) {
        int key = i >> 4, d = i & 15;
        float kv = (key < NN) ? Kg[(long)key*ldk + d] : 0.f;
        float vv = (key < NN) ? Vg[(long)key*ldv + d] : 0.f;
        bf16 kh = __float2bfloat16(kv);
        bf16 kl = __float2bfloat16(kv - __bfloat162float(kh));
        bf16 vh = __float2bfloat16(vv);
        bf16 vl = __float2bfloat16(vv - __bfloat162float(vh));
        sm2[KHI_E + key*24 + d] = kh;
        sm2[KLO_E + key*24 + d] = kl;
        sm2[VHI_E + d*584 + key] = vh;
        sm2[VLO_E + d*584 + key] = vl;
    }
    const float* Qg = Q + (long)b*NN*ldq + h*DKK;
    const float* Qg2 = Q2 ? (Q2 + (long)b*NN*ldq + h*DKK) : (const float*)0;
    for (int i = tid; i < 128*DKK; i += 256) {
        int row = i >> 4, d = i & 15;
        int q = qb + row;
        float qv = 0.f;
        if (q < NN) {
            qv = Qg[(long)q*ldq + d];
            if (Qg2) {
                float f = flagv[(long)b*MM + q];
                qv = f*qv + (1.f - f)*Qg2[(long)q*ldq + d];
            }
        }
        bf16 qh = __float2bfloat16(qv);
        sm2[QHI_E + row*24 + d] = qh;
        sm2[QLO_E + row*24 + d] = __float2bfloat16(qv - __bfloat162float(qh));
    }
    __syncthreads();

    int warp = tid >> 5, lane = tid & 31;
    if (qb + warp*16 >= NN) return;   // tail-wave skip (no block syncs below)

    int g = lane >> 2;
    int ar = lane & 15, ak = lane >> 4;
    int br = lane & 7,  bk = (lane >> 3) & 1;
    const unsigned FULL = 0xffffffffu;

    uint32_t Qh[4], Ql[4];
    {
        uint32_t qa = sb + QHI_B + (uint32_t)((warp*16 + ar)*48 + ak*16);
        LDM4(Qh[0], Qh[1], Qh[2], Qh[3], qa);
        LDM4(Ql[0], Ql[1], Ql[2], Ql[3], qa + QLO_B);
    }

    // three accumulator sets (independent MMA chains), merged at finalize
    float oA[2][4], oB[2][4], oC[2][4];
    #pragma unroll
    for (int n = 0; n < 2; n++)
        #pragma unroll
        for (int q = 0; q < 4; q++) { oA[n][q]=0.f; oB[n][q]=0.f; oC[n][q]=0.f; }
    float mrow[2] = { -1e30f, -1e30f };
    float lrow[2] = { 0.f, 0.f };

    int qr0 = qb + warp*16 + g;
    int qm0 = (qr0 < NN) ? qr0 : NN-1;
    int qm1 = (qr0+8 < NN) ? qr0+8 : NN-1;
    const float* mk0 = mask ? (mask + ((long)(b*MM + qm0))*NN) : (const float*)0;
    const float* mk1 = mask ? (mask + ((long)(b*MM + qm1))*NN) : (const float*)0;

    #pragma unroll 1
    for (int c = 0; c < 9; c++) {
        float s[8][4];
        // ---- S = Q K^T: preload all 8 B frag pairs, then 3 indep passes ----
        uint32_t Bh[8][2], Bl[8][2];
        #pragma unroll
        for (int t = 0; t < 8; t++) {
            uint32_t ka = sb + (uint32_t)((c*64 + t*8 + br)*48 + bk*16);
            LDM2(Bh[t][0], Bh[t][1], ka);
            LDM2(Bl[t][0], Bl[t][1], ka + KLO_B);
            s[t][0]=0.f; s[t][1]=0.f; s[t][2]=0.f; s[t][3]=0.f;
        }
        #pragma unroll
        for (int t = 0; t < 8; t++) MMA16816(s[t], Qh, Bh[t]);
        #pragma unroll
        for (int t = 0; t < 8; t++) MMA16816(s[t], Qh, Bl[t]);
        #pragma unroll
        for (int t = 0; t < 8; t++) MMA16816(s[t], Ql, Bh[t]);

        float mx0 = -1e30f, mx1 = -1e30f;
        #pragma unroll
        for (int t = 0; t < 8; t++) {
            if (c < 8 || t == 0) {
                s[t][0]*=0.25f; s[t][1]*=0.25f; s[t][2]*=0.25f; s[t][3]*=0.25f;
                if (mask) {
                    int j = c*64 + t*8 + (lane&3)*2;
                    float2 m0 = *(const float2*)(mk0 + j);
                    float2 m1 = *(const float2*)(mk1 + j);
                    s[t][0]+=m0.x; s[t][1]+=m0.y; s[t][2]+=m1.x; s[t][3]+=m1.y;
                }
            } else {
                s[t][0]=-1e30f; s[t][1]=-1e30f; s[t][2]=-1e30f; s[t][3]=-1e30f;
            }
            mx0 = fmaxf(mx0, fmaxf(s[t][0], s[t][1]));
            mx1 = fmaxf(mx1, fmaxf(s[t][2], s[t][3]));
        }
        mx0 = fmaxf(mx0, __shfl_xor_sync(FULL, mx0, 1));
        mx0 = fmaxf(mx0, __shfl_xor_sync(FULL, mx0, 2));
        mx1 = fmaxf(mx1, __shfl_xor_sync(FULL, mx1, 1));
        mx1 = fmaxf(mx1, __shfl_xor_sync(FULL, mx1, 2));
        float mn0 = fmaxf(mrow[0], mx0), mn1 = fmaxf(mrow[1], mx1);
        float f0 = __expf(mrow[0] - mn0), f1 = __expf(mrow[1] - mn1);
        mrow[0] = mn0; mrow[1] = mn1;
        float rs0 = 0.f, rs1 = 0.f;
        #pragma unroll
        for (int t = 0; t < 8; t++) {
            s[t][0] = __expf(s[t][0] - mn0);
            s[t][1] = __expf(s[t][1] - mn0);
            s[t][2] = __expf(s[t][2] - mn1);
            s[t][3] = __expf(s[t][3] - mn1);
            rs0 += s[t][0] + s[t][1];
            rs1 += s[t][2] + s[t][3];
        }
        rs0 += __shfl_xor_sync(FULL, rs0, 1); rs0 += __shfl_xor_sync(FULL, rs0, 2);
        rs1 += __shfl_xor_sync(FULL, rs1, 1); rs1 += __shfl_xor_sync(FULL, rs1, 2);
        lrow[0] = lrow[0]*f0 + rs0;
        lrow[1] = lrow[1]*f1 + rs1;
        #pragma unroll
        for (int n = 0; n < 2; n++) {
            oA[n][0]*=f0; oA[n][1]*=f0; oA[n][2]*=f1; oA[n][3]*=f1;
            oB[n][0]*=f0; oB[n][1]*=f0; oB[n][2]*=f1; oB[n][3]*=f1;
            oC[n][0]*=f0; oC[n][1]*=f0; oC[n][2]*=f1; oC[n][3]*=f1;
        }
        // ---- P @ V: each pass targets its own accumulator set ----
        #pragma unroll
        for (int ss = 0; ss < 4; ss++) {
            uint32_t pah[4], pal[4];
            cvtpk(s[2*ss][0],   s[2*ss][1],   pah[0], pal[0]);
            cvtpk(s[2*ss][2],   s[2*ss][3],   pah[1], pal[1]);
            cvtpk(s[2*ss+1][0], s[2*ss+1][1], pah[2], pal[2]);
            cvtpk(s[2*ss+1][2], s[2*ss+1][3], pah[3], pal[3]);
            #pragma unroll
            for (int n = 0; n < 2; n++) {
                uint32_t va = sb + VHI_B +
                    (uint32_t)((n*8 + br)*1168 + (c*64 + ss*16)*2 + bk*16);
                uint32_t vh[2], vl[2];
                LDM2(vh[0], vh[1], va);
                LDM2(vl[0], vl[1], va + VLO_B);
                MMA16816(oA[n], pah, vh);
                MMA16816(oB[n], pah, vl);
                MMA16816(oC[n], pal, vh);
            }
        }
    }

    float i0 = 1.f / lrow[0], i1 = 1.f / lrow[1];
    #pragma unroll
    for (int n = 0; n < 2; n++) {
        int d = h*DKK + n*8 + (lane&3)*2;
        if (qr0 < NN) {
            uint32_t hp, lp;
            cvtpk((oA[n][0]+oB[n][0]+oC[n][0])*i0,
                  (oA[n][1]+oB[n][1]+oC[n][1])*i0, hp, lp);
            long off = ((long)(b*NN + qr0))*EE + d;
            *(uint32_t*)(Oh + off) = hp;
            *(uint32_t*)(Ol + off) = lp;
        }
        if (qr0 + 8 < NN) {
            uint32_t hp, lp;
            cvtpk((oA[n][2]+oB[n][2]+oC[n][2])*i1,
                  (oA[n][3]+oB[n][3]+oC[n][3])*i1, hp, lp);
            long off = ((long)(b*NN + qr0 + 8))*EE + d;
            *(uint32_t*)(Oh + off) = hp;
            *(uint32_t*)(Ol + off) = lp;
        }
    }
}

// ---------------- instance norm: high-parallelism fused stats ----------------
__global__ __launch_bounds__(512)
void inorm_sf2(const float* __restrict__ Y)
{
    int b = blockIdx.x, eg = blockIdx.y;
    int tid = threadIdx.x;
    int el = tid & 31, nch = tid >> 5;
    int e = eg*32 + el;
    float s1 = 0.f, s2 = 0.f;
    for (int n = nch; n < NN; n += 16) {
        float v = Y[((long)(b*NN + n))*EE + e];
        s1 += v; s2 += v*v;
    }
    __shared__ float sh1[512], sh2[512];
    sh1[tid] = s1; sh2[tid] = s2;
    __syncthreads();
    #pragma unroll
    for (int off = 256; off >= 32; off >>= 1) {
        if (tid < off) { sh1[tid] += sh1[tid+off]; sh2[tid] += sh2[tid+off]; }
        __syncthreads();
    }
    if (tid < 32) {
        float t1 = sh1[tid], t2 = sh2[tid];
        float mean = t1 / (float)NN;
        float var  = t2 / (float)NN - mean*mean;
        int ee = eg*32 + tid;
        g_stats[(b*EE+ee)*2]   = mean;
        g_stats[(b*EE+ee)*2+1] = rsqrtf(var + 1e-5f);
    }
}

__global__ void inorm_apply(const float* __restrict__ Y, const float* __restrict__ gg,
                            const float* __restrict__ bt, float* __restrict__ Xo,
                            bf16* __restrict__ Xh, bf16* __restrict__ Xl)
{
    int idx = blockIdx.x * blockDim.x + threadIdx.x;
    if (idx >= BB*NN*EE) return;
    int e = idx % EE;
    int b = idx / (NN*EE);
    float mean = g_stats[(b*EE+e)*2];
    float istd = g_stats[(b*EE+e)*2+1];
    float v = (Y[idx] - mean) * istd * gg[e] + bt[e];
    Xo[idx] = v;
    split1(v, Xh + idx, Xl + idx);
}

// ---------------- decoder helpers ----------------
__global__ void build_cat(const float* __restrict__ loadv, const int* __restrict__ cur,
                          const int* __restrict__ subn, const int* __restrict__ subl,
                          const int* __restrict__ sel, const float* __restrict__ encmean)
{
    int r = blockIdx.x;
    int b = r / MM;
    int e = threadIdx.x;
    int c = cur[r];
    float le = g_x[((long)(b*NN + c))*EE + e];

    int len = subl[r];
    const int* nodes = subn + (long)r*LL;
    float ssum = 0.f; int cnt = 0;
    for (int l = 0; l < LL; l++) {
        int nd = nodes[l];
        if (l < len && nd >= DEPOTN) {
            ssum += g_x[((long)(b*NN + nd))*EE + e];
            cnt++;
        }
    }
    float cntf = (cnt > 0) ? (float)cnt : 1.f;
    float smean = ssum / cntf;

    long bl = (long)r*256, br = (long)r*KRT;
    split1(le,    g_catlh + bl + e,       g_catll + bl + e);
    split1(smean, g_catlh + bl + 128 + e, g_catll + bl + 128 + e);
    split1(le,    g_catrh + br + e,       g_catrl + br + e);
    split1(encmean[e], g_catrh + br + 128 + e, g_catrl + br + 128 + e);
    if (e == 0) split1(loadv[r], g_catrh + br + 256, g_catrl + br + 256);
    if (e >= 1 && e < 32) { g_catrh[br + 256 + e] = __float2bfloat16(0.f);
                            g_catrl[br + 256 + e] = __float2bfloat16(0.f); }
    if (e == 0) {
        int s2 = sel[(long)r*4 + 2];
        g_flag[r] = (s2 >= DEPOTN && c < DEPOTN) ? 1.f : 0.f;
    }
}

// ---------------- final tanh-clip + mask + softmax ----------------
__global__ void final_kernel(const float* __restrict__ mask, float* __restrict__ out)
{
    int r = blockIdx.x;
    int tid = threadIdx.x;
    __shared__ float buf[NN];
    __shared__ float red[256];
    const float* sn = g_sn + (long)r*NN;
    const float* mk = mask + (long)r*NN;
    const float invs = 0.08838834764831845f;

    float lm = -1e30f;
    for (int j = tid; j < NN; j += 256) {
        float v = 10.f * tanhf(sn[j] * invs) + mk[j];
        buf[j] = v;
        lm = fmaxf(lm, v);
    }
    red[tid] = lm; __syncthreads();
    for (int off = 128; off > 0; off >>= 1) {
        if (tid < off) red[tid] = fmaxf(red[tid], red[tid+off]);
        __syncthreads();
    }
    float mx = red[0]; __syncthreads();

    float ls = 0.f;
    for (int j = tid; j < NN; j += 256) {
        float e0 = __expf(buf[j] - mx);
        buf[j] = e0; ls += e0;
    }
    red[tid] = ls; __syncthreads();
    for (int off = 128; off > 0; off >>= 1) {
        if (tid < off) red[tid] += red[tid+off];
        __syncthreads();
    }
    float inv = 1.f / red[0];
    for (int j = tid; j < NN; j += 256)
        out[(long)r*NN + j] = buf[j] * inv;
}

// ---------------- host ----------------
#define GEMM_SMEM 81920

static void launch_tc(const bf16* Ah, const bf16* Al, const bf16* Bh, const bf16* Bl,
                      const float* bias, const float* resid,
                      float* C, bf16* Ch, bf16* Cl,
                      int R, int K, int Cout, int batch,
                      long sA, long sB, long sC, int relu)
{
    dim3 grid((R + 127) / 128, (Cout + 127) / 128, batch);
    gemm_tc2<<<grid, 256, GEMM_SMEM>>>(Ah, Al, Bh, Bl, bias, resid, C, Ch, Cl,
                                       R, K, Cout, sA, sB, sC, relu);
}

#define SYM(p, s) cudaGetSymbolAddress((void**)&p, s)

extern "C" void kernel_launch(void* const* d_in, const int* in_sizes, int n_in,
                              void* d_out, int out_size)
{
    const float* depot  = (const float*)d_in[0];
    const float* cust   = (const float*)d_in[1];
    const float* mask   = (const float*)d_in[2];
    const float* loadv  = (const float*)d_in[3];
    const int*   cur    = (const int*)d_in[4];
    const int*   subn   = (const int*)d_in[5];
    const int*   subl   = (const int*)d_in[6];
    const int*   sel    = (const int*)d_in[7];
    const float* edW    = (const float*)d_in[8];
    const float* edb    = (const float*)d_in[9];
    const float* ecW    = (const float*)d_in[10];
    const float* ecb    = (const float*)d_in[11];
    const float* Wq     = (const float*)d_in[12];
    const float* Wk     = (const float*)d_in[13];
    const float* Wv     = (const float*)d_in[14];
    const float* Wc     = (const float*)d_in[15];
    const float* Wcb    = (const float*)d_in[16];
    const float* n1g    = (const float*)d_in[17];
    const float* n1b    = (const float*)d_in[18];
    const float* fW1    = (const float*)d_in[19];
    const float* fb1    = (const float*)d_in[20];
    const float* fW2    = (const float*)d_in[21];
    const float* fb2    = (const float*)d_in[22];
    const float* n2g    = (const float*)d_in[23];
    const float* n2b    = (const float*)d_in[24];
    const float* dWqloc = (const float*)d_in[25];
    const float* dWqrt  = (const float*)d_in[26];
    const float* dWk    = (const float*)d_in[27];
    const float* dWv    = (const float*)d_in[28];
    const float* dWc    = (const float*)d_in[29];
    const float* dWcb   = (const float*)d_in[30];
    float* out = (float*)d_out;

    float *px, *pqkv, *py, *px1, *pkvd, *pqloc, *pqrout, *pflag, *psn;
    SYM(px, g_x); SYM(pqkv, g_qkv); SYM(py, g_y); SYM(px1, g_x1);
    SYM(pkvd, g_kvd); SYM(pqloc, g_qloc); SYM(pqrout, g_qrout);
    SYM(pflag, g_flag); SYM(psn, g_sn);

    bf16 *pxh,*pxl, *px1h,*px1l, *pmhh,*pmhl, *pffhh,*pffhl, *pattnh,*pattnl;
    bf16 *pscoreh,*pscorel, *pcatlh,*pcatll, *pcatrh,*pcatrl;
    bf16 *pwqkvh,*pwqkvl, *pwch,*pwcl, *pf1h,*pf1l, *pf2h,*pf2l;
    bf16 *pwkvh,*pwkvl, *pwqlh,*pwqll, *pwpah,*pwpal, *pwdch,*pwdcl;
    SYM(pxh, g_xh); SYM(pxl, g_xl); SYM(px1h, g_x1h); SYM(px1l, g_x1l);
    SYM(pmhh, g_mhh); SYM(pmhl, g_mhl); SYM(pffhh, g_ffhh); SYM(pffhl, g_ffhl);
    SYM(pattnh, g_attnh); SYM(pattnl, g_attnl);
    SYM(pscoreh, g_scoreh); SYM(pscorel, g_scorel);
    SYM(pcatlh, g_catlh); SYM(pcatll, g_catll); SYM(pcatrh, g_catrh); SYM(pcatrl, g_catrl);
    SYM(pwqkvh, g_wqkvh); SYM(pwqkvl, g_wqkvl); SYM(pwch, g_wch); SYM(pwcl, g_wcl);
    SYM(pf1h, g_f1h); SYM(pf1l, g_f1l); SYM(pf2h, g_f2h); SYM(pf2l, g_f2l);
    SYM(pwkvh, g_wkvh); SYM(pwkvl, g_wkvl); SYM(pwqlh, g_wqlh); SYM(pwqll, g_wqll);
    SYM(pwpah, g_wpah); SYM(pwpal, g_wpal); SYM(pwdch, g_wdch); SYM(pwdcl, g_wdcl);

    const int R = BB * NN;
    const int TOT = BB * NN * EE;
    const int NQT = (NN + 127) / 128;
    static int smem_set = 0;
    if (!smem_set) {
        cudaFuncSetAttribute(attn_mma, cudaFuncAttributeMaxDynamicSharedMemorySize, ATTN2_SMEM);
        cudaFuncSetAttribute(gemm_tc2, cudaFuncAttributeMaxDynamicSharedMemorySize, GEMM_SMEM);
        smem_set = 1;
    }

    // ---- launches 0-2 ----
    embed_kernel<<<(TOT + 255)/256, 256>>>(depot, cust, edW, edb, ecW, ecb);
    pack_w<<<(NLL*384*EE + 256*EE + 255)/256, 256>>>(Wq, Wk, Wv, dWk, dWv);
    cvt_split<<<(NLL*EE*EE + 255)/256, 256>>>(Wc,  pwch, pwcl, NLL*EE*EE);

    // ---- my launch 3: layer-0 QKV GEMM — ncu -s 5 target ----
    launch_tc(pxh, pxl, pwqkvh, pwqkvl, 0, 0, pqkv, 0, 0, R, EE, 384, 1, 0, 0, 0, 0);

    padw_kernel<<<(EE*KRT + 255)/256, 256>>>(dWqrt);
    cvt_split<<<(NLL*FFHH*EE + 255)/256, 256>>>(fW1, pf1h, pf1l, NLL*FFHH*EE);
    cvt_split<<<(NLL*EE*FFHH + 255)/256, 256>>>(fW2, pf2h, pf2l, NLL*EE*FFHH);
    cvt_split<<<(EE*256 + 255)/256, 256>>>(dWqloc, pwqlh, pwqll, EE*256);
    cvt_split<<<(EE*EE + 255)/256, 256>>>(dWc, pwdch, pwdcl, EE*EE);

    // ---- encoder ----
    for (int i = 0; i < NLL; i++) {
        if (i > 0)
            launch_tc(pxh, pxl, pwqkvh + (long)i*384*EE, pwqkvl + (long)i*384*EE,
                      0, 0, pqkv, 0, 0, R, EE, 384, 1, 0, 0, 0, 0);
        attn_mma<<<dim3(NQT, HH, BB), 256, ATTN2_SMEM>>>(
            pqkv, (const float*)0, (const float*)0, 384,
            pqkv + 128, 384, pqkv + 256, 384, (const float*)0, pmhh, pmhl);
        launch_tc(pmhh, pmhl, pwch + (long)i*EE*EE, pwcl + (long)i*EE*EE,
                  Wcb + (long)i*EE, px, py, 0, 0, R, EE, EE, 1, 0, 0, 0, 0);
        inorm_sf2<<<dim3(BB, 4), 512>>>(py);
        inorm_apply<<<(TOT + 255)/256, 256>>>(py, n1g + (long)i*EE, n1b + (long)i*EE,
                                              px1, px1h, px1l);
        launch_tc(px1h, px1l, pf1h + (long)i*FFHH*EE, pf1l + (long)i*FFHH*EE,
                  fb1 + (long)i*FFHH, 0, 0, pffhh, pffhl, R, EE, FFHH, 1, 0, 0, 0, 1);
        launch_tc(pffhh, pffhl, pf2h + (long)i*EE*FFHH, pf2l + (long)i*EE*FFHH,
                  fb2 + (long)i*EE, px1, py, 0, 0, R, FFHH, EE, 1, 0, 0, 0, 0);
        inorm_sf2<<<dim3(BB, 4), 512>>>(py);
        inorm_apply<<<(TOT + 255)/256, 256>>>(py, n2g + (long)i*EE, n2b + (long)i*EE,
                                              px, pxh, pxl);
    }

    // ---- decoder ----
    launch_tc(pxh, pxl, pwkvh, pwkvl, 0, 0, pkvd, 0, 0, R, EE, 256, 1, 0, 0, 0, 0);
    build_cat<<<BB*MM, EE>>>(loadv, cur, subn, subl, sel, n2b + (long)(NLL-1)*EE);
    launch_tc(pcatlh, pcatll, pwqlh, pwqll, 0, 0, pqloc, 0, 0, R, 256, EE, 1, 0, 0, 0, 0);
    launch_tc(pcatrh, pcatrl, pwpah, pwpal, 0, 0, pqrout, 0, 0, R, KRT, EE, 1, 0, 0, 0, 0);
    attn_mma<<<dim3(NQT, HH, BB), 256, ATTN2_SMEM>>>(
        pqloc, pqrout, pflag, 128, pkvd, 256, pkvd + 128, 256, mask, pattnh, pattnl);
    launch_tc(pattnh, pattnl, pwdch, pwdcl, dWcb, 0, 0, pscoreh, pscorel,
              R, EE, EE, 1, 0, 0, 0, 0);
    launch_tc(pscoreh, pscorel, pxh, pxl, 0, 0, psn, 0, 0, MM, EE, NN, BB,
              (long)MM*EE, (long)NN*EE, (long)MM*NN, 0);
    final_kernel<<<BB*MM, 256>>>(mask, out);
}

// round 12
// speedup vs baseline: 1.5839x; 1.0754x over previous
#include <cuda_runtime.h>
#include <cuda_bf16.h>
#include <math.h>
#include <stdint.h>

#define BB 32
#define NN 520
#define DEPOTN 20
#define CUSTN 500
#define EE 128
#define HH 8
#define DKK 16
#define FFHH 512
#define NLL 6
#define MM 520
#define LL 40
#define KRT 288

typedef __nv_bfloat16 bf16;

// ---------------- fp32 scratch ----------------
__device__ __align__(16) float g_x   [BB*NN*EE];
__device__ __align__(16) float g_qkv [BB*NN*384];
__device__ __align__(16) float g_y   [BB*NN*EE];
__device__ __align__(16) float g_x1  [BB*NN*EE];
__device__ __align__(16) float g_stats[BB*EE*2];
__device__ __align__(16) float g_kvd [BB*NN*256];
__device__ __align__(16) float g_qloc [BB*MM*EE];
__device__ __align__(16) float g_qrout[BB*MM*EE];
__device__ __align__(16) float g_flag [BB*MM];
__device__ __align__(16) float g_sn   [BB*MM*NN];

// ---------------- bf16 hi/lo scratch ----------------
__device__ __align__(16) bf16 g_xh[BB*NN*EE],      g_xl[BB*NN*EE];
__device__ __align__(16) bf16 g_x1h[BB*NN*EE],     g_x1l[BB*NN*EE];
__device__ __align__(16) bf16 g_mhh[BB*NN*EE],     g_mhl[BB*NN*EE];
__device__ __align__(16) bf16 g_ffhh[BB*NN*FFHH],  g_ffhl[BB*NN*FFHH];
__device__ __align__(16) bf16 g_attnh[BB*MM*EE],   g_attnl[BB*MM*EE];
__device__ __align__(16) bf16 g_scoreh[BB*MM*EE],  g_scorel[BB*MM*EE];
__device__ __align__(16) bf16 g_catlh[BB*MM*256],  g_catll[BB*MM*256];
__device__ __align__(16) bf16 g_catrh[BB*MM*KRT],  g_catrl[BB*MM*KRT];
__device__ __align__(16) bf16 g_wqkvh[NLL*384*EE], g_wqkvl[NLL*384*EE];
__device__ __align__(16) bf16 g_wch[NLL*EE*EE],    g_wcl[NLL*EE*EE];
__device__ __align__(16) bf16 g_f1h[NLL*FFHH*EE],  g_f1l[NLL*FFHH*EE];
__device__ __align__(16) bf16 g_f2h[NLL*EE*FFHH],  g_f2l[NLL*EE*FFHH];
__device__ __align__(16) bf16 g_wkvh[256*EE],      g_wkvl[256*EE];
__device__ __align__(16) bf16 g_wqlh[EE*256],      g_wqll[EE*256];
__device__ __align__(16) bf16 g_wpah[EE*KRT],      g_wpal[EE*KRT];
__device__ __align__(16) bf16 g_wdch[EE*EE],       g_wdcl[EE*EE];

__device__ __forceinline__ void split1(float x, bf16* h, bf16* l)
{
    bf16 hv = __float2bfloat16(x);
    *h = hv;
    *l = __float2bfloat16(x - __bfloat162float(hv));
}

__device__ __forceinline__ void cvtpk(float x0, float x1, uint32_t& h, uint32_t& l)
{
    bf16 h0 = __float2bfloat16(x0), h1 = __float2bfloat16(x1);
    float l0 = x0 - __bfloat162float(h0), l1 = x1 - __bfloat162float(h1);
    h = ((uint32_t)__bfloat16_as_ushort(h1) << 16) | __bfloat16_as_ushort(h0);
    bf16 g0 = __float2bfloat16(l0), g1 = __float2bfloat16(l1);
    l = ((uint32_t)__bfloat16_as_ushort(g1) << 16) | __bfloat16_as_ushort(g0);
}

// ---------------- generic fp32 -> hi/lo ----------------
__global__ void cvt_split(const float* __restrict__ s, bf16* __restrict__ h,
                          bf16* __restrict__ l, int n)
{
    int i = blockIdx.x * blockDim.x + threadIdx.x;
    if (i < n) split1(s[i], h + i, l + i);
}

// ---------------- embedding ----------------
__global__ void embed_kernel(const float* __restrict__ dep, const float* __restrict__ cus,
                             const float* __restrict__ Wd, const float* __restrict__ bd,
                             const float* __restrict__ Wc, const float* __restrict__ bc)
{
    int idx = blockIdx.x * blockDim.x + threadIdx.x;
    if (idx >= BB*NN*EE) return;
    int e = idx % EE;
    int n = (idx / EE) % NN;
    int b = idx / (EE*NN);
    float acc;
    if (n < DEPOTN) {
        const float* f = dep + ((long)b*DEPOTN + n) * 4;
        acc = bd[e];
        #pragma unroll
        for (int j = 0; j < 4; j++) acc += f[j] * Wd[e*4 + j];
    } else {
        const float* f = cus + ((long)b*CUSTN + (n - DEPOTN)) * 3;
        acc = bc[e];
        #pragma unroll
        for (int j = 0; j < 3; j++) acc += f[j] * Wc[e*3 + j];
    }
    g_x[idx] = acc;
    split1(acc, g_xh + idx, g_xl + idx);
}

// ---------------- weight packing ----------------
__global__ void pack_w(const float* __restrict__ Wq, const float* __restrict__ Wk,
                       const float* __restrict__ Wv, const float* __restrict__ dWk,
                       const float* __restrict__ dWv)
{
    int idx = blockIdx.x * blockDim.x + threadIdx.x;
    const int tot1 = NLL*384*EE;
    if (idx < tot1) {
        int col = idx % EE;
        int row = (idx / EE) % 384;
        int l   = idx / (EE*384);
        float v;
        if (row < 128)      v = Wq[((long)l*EE + row)*EE + col];
        else if (row < 256) v = Wk[((long)l*EE + row-128)*EE + col];
        else                v = Wv[((long)l*EE + row-256)*EE + col];
        split1(v, g_wqkvh + idx, g_wqkvl + idx);
    } else {
        int j = idx - tot1;
        if (j < 256*EE) {
            int col = j % EE;
            int row = j / EE;
            float v = (row < 128) ? dWk[row*EE + col] : dWv[(row-128)*EE + col];
            split1(v, g_wkvh + j, g_wkvl + j);
        }
    }
}

__global__ void padw_kernel(const float* __restrict__ Wr)
{
    int idx = blockIdx.x * blockDim.x + threadIdx.x;
    if (idx >= EE*KRT) return;
    int rr = idx / KRT, cc = idx % KRT;
    float v = (cc < 257) ? Wr[rr*257 + cc] : 0.f;
    split1(v, g_wpah + idx, g_wpal + idx);
}

// ---------------- MMA primitives ----------------
#define LDM4(r0,r1,r2,r3,addr) \
    asm volatile("ldmatrix.sync.aligned.m8n8.x4.shared.b16 {%0,%1,%2,%3},[%4];" \
                 : "=r"(r0),"=r"(r1),"=r"(r2),"=r"(r3) : "r"(addr))
#define LDM2(r0,r1,addr) \
    asm volatile("ldmatrix.sync.aligned.m8n8.x2.shared.b16 {%0,%1},[%2];" \
                 : "=r"(r0),"=r"(r1) : "r"(addr))
#define MMA16816(c,a,b) \
    asm volatile("mma.sync.aligned.m16n8k16.row.col.f32.bf16.bf16.f32 " \
                 "{%0,%1,%2,%3},{%4,%5,%6,%7},{%8,%9},{%0,%1,%2,%3};" \
                 : "+f"((c)[0]),"+f"((c)[1]),"+f"((c)[2]),"+f"((c)[3]) \
                 : "r"((a)[0]),"r"((a)[1]),"r"((a)[2]),"r"((a)[3]), "r"((b)[0]),"r"((b)[1]))

// ---------------- TC GEMM v3: pass-major MMA scheduling ----------------
#define MAT 10240
#define STAGE 40960

__global__ __launch_bounds__(256, 2)
void gemm_tc2(const bf16* __restrict__ Ahi, const bf16* __restrict__ Alo,
              const bf16* __restrict__ Bhi, const bf16* __restrict__ Blo,
              const float* __restrict__ bias, const float* __restrict__ resid,
              float* __restrict__ C, bf16* __restrict__ Chi, bf16* __restrict__ Clo,
              int R, int K, int Cout, long sA, long sB, long sC, int relu)
{
    int bz = blockIdx.z;
    Ahi += (long)bz*sA; Alo += (long)bz*sA;
    Bhi += (long)bz*sB; Blo += (long)bz*sB;
    if (C)     C   += (long)bz*sC;
    if (Chi) { Chi += (long)bz*sC; Clo += (long)bz*sC; }
    if (resid) resid += (long)bz*sC;

    extern __shared__ bf16 smb[];
    uint32_t sb = (uint32_t)__cvta_generic_to_shared(smb);

    int tid = threadIdx.x, lane = tid & 31, warp = tid >> 5;
    int wm = warp >> 2, wn = warp & 3;
    int rowBase = blockIdx.x * 128, colBase = blockIdx.y * 128;

    float c[4][4][4];
    #pragma unroll
    for (int i = 0; i < 4; i++)
        #pragma unroll
        for (int j = 0; j < 4; j++)
            { c[i][j][0]=0.f; c[i][j][1]=0.f; c[i][j][2]=0.f; c[i][j][3]=0.f; }

    const bf16* bases[4] = { Ahi, Alo, Bhi, Blo };
    int nk = K >> 5;

    #define FILL(st, kt) do { \
        int k0 = (kt) << 5; \
        _Pragma("unroll") \
        for (int t = 0; t < 8; t++) { \
            int o = tid + t*256; \
            int m = o >> 9, r = (o >> 2) & 127, seg = o & 3; \
            int gr = ((m < 2) ? rowBase : colBase) + r; \
            int lim = (m < 2) ? R : Cout; \
            long grc = (gr < lim) ? gr : 0; \
            const bf16* src = bases[m] + grc*K + k0 + seg*8; \
            uint32_t dst = sb + (st)*STAGE + m*MAT + r*80 + seg*16; \
            int nbytes = (gr < lim) ? 16 : 0; \
            asm volatile("cp.async.ca.shared.global [%0],[%1],16,%2;" \
                         :: "r"(dst), "l"(src), "r"(nbytes)); \
        } \
        asm volatile("cp.async.commit_group;"); \
    } while (0)

    FILL(0, 0);

    int ar = lane & 15, ak = (lane >> 4);
    int br = lane & 7,  bk = (lane >> 3) & 1;

    for (int kt = 0; kt < nk; kt++) {
        int st = kt & 1;
        if (kt + 1 < nk) {
            FILL(st ^ 1, kt + 1);
            asm volatile("cp.async.wait_group 1;");
        } else {
            asm volatile("cp.async.wait_group 0;");
        }
        __syncthreads();

        uint32_t aOff = sb + st*STAGE;
        uint32_t bOff = aOff + 2*MAT;
        #pragma unroll
        for (int ks = 0; ks < 2; ks++) {
            uint32_t Ah[4][4], Al[4][4];
            #pragma unroll
            for (int i = 0; i < 4; i++) {
                uint32_t ad = aOff + (uint32_t)((wm*64 + i*16 + ar)*80 + ak*16 + ks*32);
                LDM4(Ah[i][0], Ah[i][1], Ah[i][2], Ah[i][3], ad);
                LDM4(Al[i][0], Al[i][1], Al[i][2], Al[i][3], ad + MAT);
            }
            #pragma unroll
            for (int jp = 0; jp < 2; jp++) {
                uint32_t Bh[2][2], Bl[2][2];
                #pragma unroll
                for (int jj = 0; jj < 2; jj++) {
                    int j = jp*2 + jj;
                    uint32_t bd = bOff + (uint32_t)((wn*32 + j*8 + br)*80 + bk*16 + ks*32);
                    LDM2(Bh[jj][0], Bh[jj][1], bd);
                    LDM2(Bl[jj][0], Bl[jj][1], bd + MAT);
                }
                #pragma unroll
                for (int jj = 0; jj < 2; jj++)
                    #pragma unroll
                    for (int i = 0; i < 4; i++)
                        MMA16816(c[i][jp*2+jj], Ah[i], Bh[jj]);
                #pragma unroll
                for (int jj = 0; jj < 2; jj++)
                    #pragma unroll
                    for (int i = 0; i < 4; i++)
                        MMA16816(c[i][jp*2+jj], Ah[i], Bl[jj]);
                #pragma unroll
                for (int jj = 0; jj < 2; jj++)
                    #pragma unroll
                    for (int i = 0; i < 4; i++)
                        MMA16816(c[i][jp*2+jj], Al[i], Bh[jj]);
            }
        }
        __syncthreads();
    }

    int gid = lane >> 2, tig = lane & 3;
    #pragma unroll
    for (int i = 0; i < 4; i++) {
        int rbase = rowBase + wm*64 + i*16 + gid;
        #pragma unroll
        for (int j = 0; j < 4; j++) {
            int c0 = colBase + wn*32 + j*8 + tig*2;
            if (c0 >= Cout) continue;
            #pragma unroll
            for (int hh = 0; hh < 2; hh++) {
                int row = rbase + hh*8;
                if (row >= R) continue;
                float v0 = c[i][j][2*hh], v1 = c[i][j][2*hh+1];
                if (bias)  { v0 += bias[c0]; v1 += bias[c0+1]; }
                if (resid) {
                    float2 rv = *(const float2*)(resid + (long)row*Cout + c0);
                    v0 += rv.x; v1 += rv.y;
                }
                if (relu) { v0 = fmaxf(v0, 0.f); v1 = fmaxf(v1, 0.f); }
                if (C) *(float2*)(C + (long)row*Cout + c0) = make_float2(v0, v1);
                if (Chi) {
                    uint32_t hp, lp;
                    cvtpk(v0, v1, hp, lp);
                    *(uint32_t*)(Chi + (long)row*Cout + c0) = hp;
                    *(uint32_t*)(Clo + (long)row*Cout + c0) = lp;
                }
            }
        }
    }
}

// ---------------- attention: one block per (h,b); K/V staged ONCE, q-tiles looped ----------------
#define KPAD 576
#define KLO_B  27648
#define VHI_B  55296
#define VLO_B  18688
#define QHI_B  92672
#define QLO_B  6144
#define ATTN2_SMEM 104960
#define NQT 5

__global__ __launch_bounds__(256)
void attn_mma(const float* __restrict__ Q, const float* __restrict__ Q2,
              const float* __restrict__ flagv, int ldq,
              const float* __restrict__ Kt, int ldk,
              const float* __restrict__ Vt, int ldv,
              const float* __restrict__ mask,
              bf16* __restrict__ Oh, bf16* __restrict__ Ol)
{
    int h = blockIdx.x, b = blockIdx.y;
    extern __shared__ bf16 sm2[];
    uint32_t sb = (uint32_t)__cvta_generic_to_shared(sm2);
    int tid = threadIdx.x;

    const int KHI_E = 0, KLO_E = 13824, VHI_E = 27648, VLO_E = 36992;
    const int QHI_E = 46336, QLO_E = 49408;

    // stage K/V hi/lo ONCE per (h,b)
    const float* Kg = Kt + (long)b*NN*ldk + h*DKK;
    const float* Vg = Vt + (long)b*NN*ldv + h*DKK;
    for (int i = tid; i < KPAD*DKK; i += 256) {
        int key = i >> 4, d = i & 15;
        float kv = (key < NN) ? Kg[(long)key*ldk + d] : 0.f;
        float vv = (key < NN) ? Vg[(long)key*ldv + d] : 0.f;
        bf16 kh = __float2bfloat16(kv);
        bf16 kl = __float2bfloat16(kv - __bfloat162float(kh));
        bf16 vh = __float2bfloat16(vv);
        bf16 vl = __float2bfloat16(vv - __bfloat162float(vh));
        sm2[KHI_E + key*24 + d] = kh;
        sm2[KLO_E + key*24 + d] = kl;
        sm2[VHI_E + d*584 + key] = vh;
        sm2[VLO_E + d*584 + key] = vl;
    }

    const float* Qg = Q + (long)b*NN*ldq + h*DKK;
    const float* Qg2 = Q2 ? (Q2 + (long)b*NN*ldq + h*DKK) : (const float*)0;

    int warp = tid >> 5, lane = tid & 31;
    int g = lane >> 2;
    int ar = lane & 15, ak = lane >> 4;
    int br = lane & 7,  bk = (lane >> 3) & 1;
    const unsigned FULL = 0xffffffffu;

    #pragma unroll 1
    for (int qt = 0; qt < NQT; qt++) {
        int qb = qt * 128;
        __syncthreads();   // prior tile's Q reads done (and K/V staged, for qt=0)
        for (int i = tid; i < 128*DKK; i += 256) {
            int row = i >> 4, d = i & 15;
            int q = qb + row;
            float qv = 0.f;
            if (q < NN) {
                qv = Qg[(long)q*ldq + d];
                if (Qg2) {
                    float f = flagv[(long)b*MM + q];
                    qv = f*qv + (1.f - f)*Qg2[(long)q*ldq + d];
                }
            }
            bf16 qh = __float2bfloat16(qv);
            sm2[QHI_E + row*24 + d] = qh;
            sm2[QLO_E + row*24 + d] = __float2bfloat16(qv - __bfloat162float(qh));
        }
        __syncthreads();

        bool valid = (qb + warp*16) < NN;
        if (!valid) continue;   // rejoin at next iteration's top barrier

        uint32_t Qh[4], Ql[4];
        {
            uint32_t qa = sb + QHI_B + (uint32_t)((warp*16 + ar)*48 + ak*16);
            LDM4(Qh[0], Qh[1], Qh[2], Qh[3], qa);
            LDM4(Ql[0], Ql[1], Ql[2], Ql[3], qa + QLO_B);
        }

        float oA[2][4], oB[2][4], oC[2][4];
        #pragma unroll
        for (int n = 0; n < 2; n++)
            #pragma unroll
            for (int q = 0; q < 4; q++) { oA[n][q]=0.f; oB[n][q]=0.f; oC[n][q]=0.f; }
        float mrow[2] = { -1e30f, -1e30f };
        float lrow[2] = { 0.f, 0.f };

        int qr0 = qb + warp*16 + g;
        int qm0 = (qr0 < NN) ? qr0 : NN-1;
        int qm1 = (qr0+8 < NN) ? qr0+8 : NN-1;
        const float* mk0 = mask ? (mask + ((long)(b*MM + qm0))*NN) : (const float*)0;
        const float* mk1 = mask ? (mask + ((long)(b*MM + qm1))*NN) : (const float*)0;

        #pragma unroll 1
        for (int c = 0; c < 9; c++) {
            float s[8][4];
            uint32_t Bh[8][2], Bl[8][2];
            #pragma unroll
            for (int t = 0; t < 8; t++) {
                uint32_t ka = sb + (uint32_t)((c*64 + t*8 + br)*48 + bk*16);
                LDM2(Bh[t][0], Bh[t][1], ka);
                LDM2(Bl[t][0], Bl[t][1], ka + KLO_B);
                s[t][0]=0.f; s[t][1]=0.f; s[t][2]=0.f; s[t][3]=0.f;
            }
            #pragma unroll
            for (int t = 0; t < 8; t++) MMA16816(s[t], Qh, Bh[t]);
            #pragma unroll
            for (int t = 0; t < 8; t++) MMA16816(s[t], Qh, Bl[t]);
            #pragma unroll
            for (int t = 0; t < 8; t++) MMA16816(s[t], Ql, Bh[t]);

            float mx0 = -1e30f, mx1 = -1e30f;
            #pragma unroll
            for (int t = 0; t < 8; t++) {
                if (c < 8 || t == 0) {
                    s[t][0]*=0.25f; s[t][1]*=0.25f; s[t][2]*=0.25f; s[t][3]*=0.25f;
                    if (mask) {
                        int j = c*64 + t*8 + (lane&3)*2;
                        float2 m0 = *(const float2*)(mk0 + j);
                        float2 m1 = *(const float2*)(mk1 + j);
                        s[t][0]+=m0.x; s[t][1]+=m0.y; s[t][2]+=m1.x; s[t][3]+=m1.y;
                    }
                } else {
                    s[t][0]=-1e30f; s[t][1]=-1e30f; s[t][2]=-1e30f; s[t][3]=-1e30f;
                }
                mx0 = fmaxf(mx0, fmaxf(s[t][0], s[t][1]));
                mx1 = fmaxf(mx1, fmaxf(s[t][2], s[t][3]));
            }
            mx0 = fmaxf(mx0, __shfl_xor_sync(FULL, mx0, 1));
            mx0 = fmaxf(mx0, __shfl_xor_sync(FULL, mx0, 2));
            mx1 = fmaxf(mx1, __shfl_xor_sync(FULL, mx1, 1));
            mx1 = fmaxf(mx1, __shfl_xor_sync(FULL, mx1, 2));
            float mn0 = fmaxf(mrow[0], mx0), mn1 = fmaxf(mrow[1], mx1);
            float f0 = __expf(mrow[0] - mn0), f1 = __expf(mrow[1] - mn1);
            mrow[0] = mn0; mrow[1] = mn1;
            float rs0 = 0.f, rs1 = 0.f;
            #pragma unroll
            for (int t = 0; t < 8; t++) {
                s[t][0] = __expf(s[t][0] - mn0);
                s[t][1] = __expf(s[t][1] - mn0);
                s[t][2] = __expf(s[t][2] - mn1);
                s[t][3] = __expf(s[t][3] - mn1);
                rs0 += s[t][0] + s[t][1];
                rs1 += s[t][2] + s[t][3];
            }
            rs0 += __shfl_xor_sync(FULL, rs0, 1); rs0 += __shfl_xor_sync(FULL, rs0, 2);
            rs1 += __shfl_xor_sync(FULL, rs1, 1); rs1 += __shfl_xor_sync(FULL, rs1, 2);
            lrow[0] = lrow[0]*f0 + rs0;
            lrow[1] = lrow[1]*f1 + rs1;
            #pragma unroll
            for (int n = 0; n < 2; n++) {
                oA[n][0]*=f0; oA[n][1]*=f0; oA[n][2]*=f1; oA[n][3]*=f1;
                oB[n][0]*=f0; oB[n][1]*=f0; oB[n][2]*=f1; oB[n][3]*=f1;
                oC[n][0]*=f0; oC[n][1]*=f0; oC[n][2]*=f1; oC[n][3]*=f1;
            }
            #pragma unroll
            for (int ss = 0; ss < 4; ss++) {
                uint32_t pah[4], pal[4];
                cvtpk(s[2*ss][0],   s[2*ss][1],   pah[0], pal[0]);
                cvtpk(s[2*ss][2],   s[2*ss][3],   pah[1], pal[1]);
                cvtpk(s[2*ss+1][0], s[2*ss+1][1], pah[2], pal[2]);
                cvtpk(s[2*ss+1][2], s[2*ss+1][3], pah[3], pal[3]);
                #pragma unroll
                for (int n = 0; n < 2; n++) {
                    uint32_t va = sb + VHI_B +
                        (uint32_t)((n*8 + br)*1168 + (c*64 + ss*16)*2 + bk*16);
                    uint32_t vh[2], vl[2];
                    LDM2(vh[0], vh[1], va);
                    LDM2(vl[0], vl[1], va + VLO_B);
                    MMA16816(oA[n], pah, vh);
                    MMA16816(oB[n], pah, vl);
                    MMA16816(oC[n], pal, vh);
                }
            }
        }

        float i0 = 1.f / lrow[0], i1 = 1.f / lrow[1];
        #pragma unroll
        for (int n = 0; n < 2; n++) {
            int d = h*DKK + n*8 + (lane&3)*2;
            if (qr0 < NN) {
                uint32_t hp, lp;
                cvtpk((oA[n][0]+oB[n][0]+oC[n][0])*i0,
                      (oA[n][1]+oB[n][1]+oC[n][1])*i0, hp, lp);
                long off = ((long)(b*NN + qr0))*EE + d;
                *(uint32_t*)(Oh + off) = hp;
                *(uint32_t*)(Ol + off) = lp;
            }
            if (qr0 + 8 < NN) {
                uint32_t hp, lp;
                cvtpk((oA[n][2]+oB[n][2]+oC[n][2])*i1,
                      (oA[n][3]+oB[n][3]+oC[n][3])*i1, hp, lp);
                long off = ((long)(b*NN + qr0 + 8))*EE + d;
                *(uint32_t*)(Oh + off) = hp;
                *(uint32_t*)(Ol + off) = lp;
            }
        }
    }
}

// ---------------- instance norm: high-parallelism fused stats ----------------
__global__ __launch_bounds__(512)
void inorm_sf2(const float* __restrict__ Y)
{
    int b = blockIdx.x, eg = blockIdx.y;
    int tid = threadIdx.x;
    int el = tid & 31, nch = tid >> 5;
    int e = eg*32 + el;
    float s1 = 0.f, s2 = 0.f;
    for (int n = nch; n < NN; n += 16) {
        float v = Y[((long)(b*NN + n))*EE + e];
        s1 += v; s2 += v*v;
    }
    __shared__ float sh1[512], sh2[512];
    sh1[tid] = s1; sh2[tid] = s2;
    __syncthreads();
    #pragma unroll
    for (int off = 256; off >= 32; off >>= 1) {
        if (tid < off) { sh1[tid] += sh1[tid+off]; sh2[tid] += sh2[tid+off]; }
        __syncthreads();
    }
    if (tid < 32) {
        float t1 = sh1[tid], t2 = sh2[tid];
        float mean = t1 / (float)NN;
        float var  = t2 / (float)NN - mean*mean;
        int ee = eg*32 + tid;
        g_stats[(b*EE+ee)*2]   = mean;
        g_stats[(b*EE+ee)*2+1] = rsqrtf(var + 1e-5f);
    }
}

// float4-vectorized apply
__global__ void inorm_apply(const float* __restrict__ Y, const float* __restrict__ gg,
                            const float* __restrict__ bt, float* __restrict__ Xo,
                            bf16* __restrict__ Xh, bf16* __restrict__ Xl)
{
    int i4 = blockIdx.x * blockDim.x + threadIdx.x;
    if (i4 >= BB*NN*EE/4) return;
    long idx = (long)i4 * 4;
    int e = (int)(idx % EE);
    int b = (int)(idx / ((long)NN*EE));
    float4 y = *(const float4*)(Y + idx);
    const float* st = g_stats + ((long)b*EE + e)*2;
    float v0 = (y.x - st[0]) * st[1] * gg[e]   + bt[e];
    float v1 = (y.y - st[2]) * st[3] * gg[e+1] + bt[e+1];
    float v2 = (y.z - st[4]) * st[5] * gg[e+2] + bt[e+2];
    float v3 = (y.w - st[6]) * st[7] * gg[e+3] + bt[e+3];
    *(float4*)(Xo + idx) = make_float4(v0, v1, v2, v3);
    uint32_t h0, l0, h1, l1;
    cvtpk(v0, v1, h0, l0);
    cvtpk(v2, v3, h1, l1);
    *(uint2*)(Xh + idx) = make_uint2(h0, h1);
    *(uint2*)(Xl + idx) = make_uint2(l0, l1);
}

// ---------------- decoder helpers ----------------
__global__ void build_cat(const float* __restrict__ loadv, const int* __restrict__ cur,
                          const int* __restrict__ subn, const int* __restrict__ subl,
                          const int* __restrict__ sel, const float* __restrict__ encmean)
{
    int r = blockIdx.x;
    int b = r / MM;
    int e = threadIdx.x;
    int c = cur[r];
    float le = g_x[((long)(b*NN + c))*EE + e];

    int len = subl[r];
    const int* nodes = subn + (long)r*LL;
    float ssum = 0.f; int cnt = 0;
    for (int l = 0; l < LL; l++) {
        int nd = nodes[l];
        if (l < len && nd >= DEPOTN) {
            ssum += g_x[((long)(b*NN + nd))*EE + e];
            cnt++;
        }
    }
    float cntf = (cnt > 0) ? (float)cnt : 1.f;
    float smean = ssum / cntf;

    long bl = (long)r*256, br = (long)r*KRT;
    split1(le,    g_catlh + bl + e,       g_catll + bl + e);
    split1(smean, g_catlh + bl + 128 + e, g_catll + bl + 128 + e);
    split1(le,    g_catrh + br + e,       g_catrl + br + e);
    split1(encmean[e], g_catrh + br + 128 + e, g_catrl + br + 128 + e);
    if (e == 0) split1(loadv[r], g_catrh + br + 256, g_catrl + br + 256);
    if (e >= 1 && e < 32) { g_catrh[br + 256 + e] = __float2bfloat16(0.f);
                            g_catrl[br + 256 + e] = __float2bfloat16(0.f); }
    if (e == 0) {
        int s2 = sel[(long)r*4 + 2];
        g_flag[r] = (s2 >= DEPOTN && c < DEPOTN) ? 1.f : 0.f;
    }
}

// ---------------- final tanh-clip + mask + softmax ----------------
__global__ void final_kernel(const float* __restrict__ mask, float* __restrict__ out)
{
    int r = blockIdx.x;
    int tid = threadIdx.x;
    __shared__ float buf[NN];
    __shared__ float red[256];
    const float* sn = g_sn + (long)r*NN;
    const float* mk = mask + (long)r*NN;
    const float invs = 0.08838834764831845f;

    float lm = -1e30f;
    for (int j = tid; j < NN; j += 256) {
        float v = 10.f * tanhf(sn[j] * invs) + mk[j];
        buf[j] = v;
        lm = fmaxf(lm, v);
    }
    red[tid] = lm; __syncthreads();
    for (int off = 128; off > 0; off >>= 1) {
        if (tid < off) red[tid] = fmaxf(red[tid], red[tid+off]);
        __syncthreads();
    }
    float mx = red[0]; __syncthreads();

    float ls = 0.f;
    for (int j = tid; j < NN; j += 256) {
        float e0 = __expf(buf[j] - mx);
        buf[j] = e0; ls += e0;
    }
    red[tid] = ls; __syncthreads();
    for (int off = 128; off > 0; off >>= 1) {
        if (tid < off) red[tid] += red[tid+off];
        __syncthreads();
    }
    float inv = 1.f / red[0];
    for (int j = tid; j < NN; j += 256)
        out[(long)r*NN + j] = buf[j] * inv;
}

// ---------------- host ----------------
#define GEMM_SMEM 81920

static void launch_tc(const bf16* Ah, const bf16* Al, const bf16* Bh, const bf16* Bl,
                      const float* bias, const float* resid,
                      float* C, bf16* Ch, bf16* Cl,
                      int R, int K, int Cout, int batch,
                      long sA, long sB, long sC, int relu)
{
    dim3 grid((R + 127) / 128, (Cout + 127) / 128, batch);
    gemm_tc2<<<grid, 256, GEMM_SMEM>>>(Ah, Al, Bh, Bl, bias, resid, C, Ch, Cl,
                                       R, K, Cout, sA, sB, sC, relu);
}

#define SYM(p, s) cudaGetSymbolAddress((void**)&p, s)

extern "C" void kernel_launch(void* const* d_in, const int* in_sizes, int n_in,
                              void* d_out, int out_size)
{
    const float* depot  = (const float*)d_in[0];
    const float* cust   = (const float*)d_in[1];
    const float* mask   = (const float*)d_in[2];
    const float* loadv  = (const float*)d_in[3];
    const int*   cur    = (const int*)d_in[4];
    const int*   subn   = (const int*)d_in[5];
    const int*   subl   = (const int*)d_in[6];
    const int*   sel    = (const int*)d_in[7];
    const float* edW    = (const float*)d_in[8];
    const float* edb    = (const float*)d_in[9];
    const float* ecW    = (const float*)d_in[10];
    const float* ecb    = (const float*)d_in[11];
    const float* Wq     = (const float*)d_in[12];
    const float* Wk     = (const float*)d_in[13];
    const float* Wv     = (const float*)d_in[14];
    const float* Wc     = (const float*)d_in[15];
    const float* Wcb    = (const float*)d_in[16];
    const float* n1g    = (const float*)d_in[17];
    const float* n1b    = (const float*)d_in[18];
    const float* fW1    = (const float*)d_in[19];
    const float* fb1    = (const float*)d_in[20];
    const float* fW2    = (const float*)d_in[21];
    const float* fb2    = (const float*)d_in[22];
    const float* n2g    = (const float*)d_in[23];
    const float* n2b    = (const float*)d_in[24];
    const float* dWqloc = (const float*)d_in[25];
    const float* dWqrt  = (const float*)d_in[26];
    const float* dWk    = (const float*)d_in[27];
    const float* dWv    = (const float*)d_in[28];
    const float* dWc    = (const float*)d_in[29];
    const float* dWcb   = (const float*)d_in[30];
    float* out = (float*)d_out;

    float *px, *pqkv, *py, *px1, *pkvd, *pqloc, *pqrout, *pflag, *psn;
    SYM(px, g_x); SYM(pqkv, g_qkv); SYM(py, g_y); SYM(px1, g_x1);
    SYM(pkvd, g_kvd); SYM(pqloc, g_qloc); SYM(pqrout, g_qrout);
    SYM(pflag, g_flag); SYM(psn, g_sn);

    bf16 *pxh,*pxl, *px1h,*px1l, *pmhh,*pmhl, *pffhh,*pffhl, *pattnh,*pattnl;
    bf16 *pscoreh,*pscorel, *pcatlh,*pcatll, *pcatrh,*pcatrl;
    bf16 *pwqkvh,*pwqkvl, *pwch,*pwcl, *pf1h,*pf1l, *pf2h,*pf2l;
    bf16 *pwkvh,*pwkvl, *pwqlh,*pwqll, *pwpah,*pwpal, *pwdch,*pwdcl;
    SYM(pxh, g_xh); SYM(pxl, g_xl); SYM(px1h, g_x1h); SYM(px1l, g_x1l);
    SYM(pmhh, g_mhh); SYM(pmhl, g_mhl); SYM(pffhh, g_ffhh); SYM(pffhl, g_ffhl);
    SYM(pattnh, g_attnh); SYM(pattnl, g_attnl);
    SYM(pscoreh, g_scoreh); SYM(pscorel, g_scorel);
    SYM(pcatlh, g_catlh); SYM(pcatll, g_catll); SYM(pcatrh, g_catrh); SYM(pcatrl, g_catrl);
    SYM(pwqkvh, g_wqkvh); SYM(pwqkvl, g_wqkvl); SYM(pwch, g_wch); SYM(pwcl, g_wcl);
    SYM(pf1h, g_f1h); SYM(pf1l, g_f1l); SYM(pf2h, g_f2h); SYM(pf2l, g_f2l);
    SYM(pwkvh, g_wkvh); SYM(pwkvl, g_wkvl); SYM(pwqlh, g_wqlh); SYM(pwqll, g_wqll);
    SYM(pwpah, g_wpah); SYM(pwpal, g_wpal); SYM(pwdch, g_wdch); SYM(pwdcl, g_wdcl);

    const int R = BB * NN;
    const int TOT = BB * NN * EE;
    static int smem_set = 0;
    if (!smem_set) {
        cudaFuncSetAttribute(attn_mma, cudaFuncAttributeMaxDynamicSharedMemorySize, ATTN2_SMEM);
        cudaFuncSetAttribute(gemm_tc2, cudaFuncAttributeMaxDynamicSharedMemorySize, GEMM_SMEM);
        smem_set = 1;
    }

    // ---- launches 0-2 ----
    embed_kernel<<<(TOT + 255)/256, 256>>>(depot, cust, edW, edb, ecW, ecb);
    pack_w<<<(NLL*384*EE + 256*EE + 255)/256, 256>>>(Wq, Wk, Wv, dWk, dWv);
    cvt_split<<<(NLL*EE*EE + 255)/256, 256>>>(Wc,  pwch, pwcl, NLL*EE*EE);

    // ---- my launch 3: layer-0 QKV GEMM — ncu -s 5 target ----
    launch_tc(pxh, pxl, pwqkvh, pwqkvl, 0, 0, pqkv, 0, 0, R, EE, 384, 1, 0, 0, 0, 0);

    padw_kernel<<<(EE*KRT + 255)/256, 256>>>(dWqrt);
    cvt_split<<<(NLL*FFHH*EE + 255)/256, 256>>>(fW1, pf1h, pf1l, NLL*FFHH*EE);
    cvt_split<<<(NLL*EE*FFHH + 255)/256, 256>>>(fW2, pf2h, pf2l, NLL*EE*FFHH);
    cvt_split<<<(EE*256 + 255)/256, 256>>>(dWqloc, pwqlh, pwqll, EE*256);
    cvt_split<<<(EE*EE + 255)/256, 256>>>(dWc, pwdch, pwdcl, EE*EE);

    // ---- encoder ----
    for (int i = 0; i < NLL; i++) {
        if (i > 0)
            launch_tc(pxh, pxl, pwqkvh + (long)i*384*EE, pwqkvl + (long)i*384*EE,
                      0, 0, pqkv, 0, 0, R, EE, 384, 1, 0, 0, 0, 0);
        attn_mma<<<dim3(HH, BB), 256, ATTN2_SMEM>>>(
            pqkv, (const float*)0, (const float*)0, 384,
            pqkv + 128, 384, pqkv + 256, 384, (const float*)0, pmhh, pmhl);
        launch_tc(pmhh, pmhl, pwch + (long)i*EE*EE, pwcl + (long)i*EE*EE,
                  Wcb + (long)i*EE, px, py, 0, 0, R, EE, EE, 1, 0, 0, 0, 0);
        inorm_sf2<<<dim3(BB, 4), 512>>>(py);
        inorm_apply<<<(TOT/4 + 255)/256, 256>>>(py, n1g + (long)i*EE, n1b + (long)i*EE,
                                                px1, px1h, px1l);
        launch_tc(px1h, px1l, pf1h + (long)i*FFHH*EE, pf1l + (long)i*FFHH*EE,
                  fb1 + (long)i*FFHH, 0, 0, pffhh, pffhl, R, EE, FFHH, 1, 0, 0, 0, 1);
        launch_tc(pffhh, pffhl, pf2h + (long)i*EE*FFHH, pf2l + (long)i*EE*FFHH,
                  fb2 + (long)i*EE, px1, py, 0, 0, R, FFHH, EE, 1, 0, 0, 0, 0);
        inorm_sf2<<<dim3(BB, 4), 512>>>(py);
        inorm_apply<<<(TOT/4 + 255)/256, 256>>>(py, n2g + (long)i*EE, n2b + (long)i*EE,
                                                px, pxh, pxl);
    }

    // ---- decoder ----
    launch_tc(pxh, pxl, pwkvh, pwkvl, 0, 0, pkvd, 0, 0, R, EE, 256, 1, 0, 0, 0, 0);
    build_cat<<<BB*MM, EE>>>(loadv, cur, subn, subl, sel, n2b + (long)(NLL-1)*EE);
    launch_tc(pcatlh, pcatll, pwqlh, pwqll, 0, 0, pqloc, 0, 0, R, 256, EE, 1, 0, 0, 0, 0);
    launch_tc(pcatrh, pcatrl, pwpah, pwpal, 0, 0, pqrout, 0, 0, R, KRT, EE, 1, 0, 0, 0, 0);
    attn_mma<<<dim3(HH, BB), 256, ATTN2_SMEM>>>(
        pqloc, pqrout, pflag, 128, pkvd, 256, pkvd + 128, 256, mask, pattnh, pattnl);
    launch_tc(pattnh, pattnl, pwdch, pwdcl, dWcb, 0, 0, pscoreh, pscorel,
              R, EE, EE, 1, 0, 0, 0, 0);
    launch_tc(pscoreh, pscorel, pxh, pxl, 0, 0, psn, 0, 0, MM, EE, NN, BB,
              (long)MM*EE, (long)NN*EE, (long)MM*NN, 0);
    final_kernel<<<BB*MM, 256>>>(mask, out);
}